// round 2
// baseline (speedup 1.0000x reference)
#include <cuda_runtime.h>
#include <cstdint>
#include <cstdio>

// Problem constants
#define E   160
#define BB  8
#define NN  4096
#define BN  (BB*NN)          // 32768 tokens
#define DINN 15
#define BSTR 162             // smem B row stride (floats): 8B-aligned, low bank conflict

constexpr size_t HALF_ELEMS = (size_t)BN * 16 * E;   // 83,886,080 floats per half

// ---------------- static device scratch (allocation-free rule) ----------------
__device__ float g_cproj[6 * E * E];       // fused inner projection matrices [k][j]
__device__ float g_mfin [6 * E * E];       // fused final projection matrices [t][j]
__device__ float g_bfin [6 * E];           // fused final biases
__device__ float g_px   [6ull * BN * E];               // projected X (q/k/v for in & out layers)
__device__ float g_obuf [2ull * BN * 16 * E];          // inner attn out (half-major), reused token-major later
__device__ float g_fq   [2ull * BN * 16 * E];
__device__ float g_fk   [2ull * BN * 16 * E];
__device__ float g_fv   [2ull * BN * 16 * E];
__device__ float g_pooled[(size_t)BN * E];

// ---------------- f32x2 helpers (Blackwell packed fp32) ----------------
__device__ __forceinline__ unsigned long long fma2(unsigned long long a,
                                                   unsigned long long b,
                                                   unsigned long long c) {
    unsigned long long d;
    asm("fma.rn.f32x2 %0, %1, %2, %3;" : "=l"(d) : "l"(a), "l"(b), "l"(c));
    return d;
}
__device__ __forceinline__ unsigned long long pack2(float x, float y) {
    unsigned long long r;
    asm("mov.b64 %0, {%1,%2};" : "=l"(r) : "f"(x), "f"(y));
    return r;
}
__device__ __forceinline__ float2 unpack2(unsigned long long v) {
    float2 f;
    asm("mov.b64 {%0,%1}, %2;" : "=f"(f.x), "=f"(f.y) : "l"(v));
    return f;
}

// ---------------- K1: fuse weight matrices ----------------
// m in [0,6):  g_cproj[m] = W_m @ in_w_slice.T      (layout [k][j], y = x @ C)
// m in [6,12): g_mfin[m-6][t][j] = sum_c f_in_w[f*E+j][c] * out_w[c][t]
__global__ void fuse_weights(
    const float* __restrict__ iWq, const float* __restrict__ iWk, const float* __restrict__ iWv,
    const float* __restrict__ oWq, const float* __restrict__ oWk, const float* __restrict__ oWv,
    const float* __restrict__ i_in_w, const float* __restrict__ o_in_w,
    const float* __restrict__ f_in_w, const float* __restrict__ i_out_w,
    const float* __restrict__ o_out_w)
{
    __shared__ float col[E];
    int m = blockIdx.y, r = blockIdx.x, j = threadIdx.x;
    if (m < 6) {
        const float* W = (m == 0) ? iWq : (m == 1) ? iWk : (m == 2) ? iWv
                       : (m == 3) ? oWq : (m == 4) ? oWk : oWv;
        const float* inw = ((m < 3) ? i_in_w : o_in_w) + (size_t)(m % 3) * E * E;
        col[j] = W[r * E + j];
        __syncthreads();
        float s = 0.f;
        #pragma unroll 8
        for (int tt = 0; tt < E; tt++) s += col[tt] * inw[j * E + tt];
        g_cproj[(size_t)m * E * E + r * E + j] = s;
    } else {
        int mf = m - 6;
        int f = mf >> 1;
        const float* ow = (mf & 1) ? o_out_w : i_out_w;
        col[j] = ow[j * E + r];          // col[c] = out_w[c][r], thread j plays role of c
        __syncthreads();
        float s = 0.f;
        #pragma unroll 8
        for (int c = 0; c < E; c++) s += col[c] * f_in_w[(f * E + j) * E + c];
        g_mfin[(size_t)mf * E * E + r * E + j] = s;
    }
}

// K1b: fused final biases: bfin[mf][j] = out_b @ f_in_w[f*E+j] + f_in_b[f*E+j]
__global__ void fuse_bias(const float* __restrict__ f_in_w, const float* __restrict__ f_in_b,
                          const float* __restrict__ i_out_b, const float* __restrict__ o_out_b)
{
    int mf = blockIdx.x, j = threadIdx.x;
    int f = mf >> 1;
    const float* ob = (mf & 1) ? o_out_b : i_out_b;
    float s = f_in_b[f * E + j];
    #pragma unroll 8
    for (int c = 0; c < E; c++) s += ob[c] * f_in_w[(f * E + j) * E + c];
    g_bfin[mf * E + j] = s;
}

// ---------------- generic 128-row x 160-col GEMM, K=160, f32x2 micro-kernel ----------
// Out[row][j] = sum_k A[row][k] * B[k][j] + bias[j]
// TRANSB=0: Bm is [k][j] (fused matrices); TRANSB=1: Bm is [j][k] (raw weights, W.T applied)
// MODE=0: plain store; MODE=1: elu store; MODE=2: per-token (32-row) max-pool store
template<int TRANSB, int MODE>
__global__ __launch_bounds__(256, 1) void gemm128(
    const float* __restrict__ A, const float* __restrict__ Bm,
    const float* __restrict__ bias, float* __restrict__ Out)
{
    extern __shared__ float sm[];
    float* As = sm;                 // 128*160 floats
    float* Bs = sm + 128 * E;       // 160*BSTR floats
    const int t = threadIdx.x;
    const size_t rowBase = (size_t)blockIdx.x * 128;

    // load A tile (coalesced float4)
    const float4* Ag = reinterpret_cast<const float4*>(A + rowBase * E);
    float4* As4 = reinterpret_cast<float4*>(As);
    #pragma unroll
    for (int i = 0; i < 20; i++) As4[t + 256 * i] = Ag[t + 256 * i];

    // load B matrix into smem (row stride BSTR)
    if (TRANSB == 0) {
        #pragma unroll 4
        for (int i = 0; i < 100; i++) {
            int idx = t + 256 * i;
            int k = idx / E, j = idx - k * E;
            Bs[k * BSTR + j] = Bm[idx];
        }
    } else {
        #pragma unroll 4
        for (int i = 0; i < 100; i++) {
            int idx = t + 256 * i;
            int j = idx / E, k = idx - j * E;
            Bs[k * BSTR + j] = Bm[idx];
        }
    }
    __syncthreads();

    const int tx = t & 15, ty = t >> 4;     // tx: 10-col group, ty: 8-row group
    unsigned long long acc[8][5];
    const unsigned long long z = pack2(0.f, 0.f);
    #pragma unroll
    for (int i = 0; i < 8; i++)
        #pragma unroll
        for (int u = 0; u < 5; u++) acc[i][u] = z;

    const float* Ath = As + ty * (8 * E);
    #pragma unroll 2
    for (int k = 0; k < E; k++) {
        unsigned long long b2[5];
        const unsigned long long* bp =
            reinterpret_cast<const unsigned long long*>(Bs + k * BSTR + tx * 10);
        #pragma unroll
        for (int u = 0; u < 5; u++) b2[u] = bp[u];
        #pragma unroll
        for (int i = 0; i < 8; i++) {
            float a = Ath[i * E + k];
            unsigned long long a2 = pack2(a, a);
            #pragma unroll
            for (int u = 0; u < 5; u++) acc[i][u] = fma2(a2, b2[u], acc[i][u]);
        }
    }

    float bcol[10];
    #pragma unroll
    for (int u = 0; u < 10; u++) bcol[u] = bias[tx * 10 + u];

    if (MODE == 2) {
        // write g into As (reuse), then max-pool per token (32 rows each)
        __syncthreads();
        #pragma unroll
        for (int i = 0; i < 8; i++) {
            int lr = ty * 8 + i;
            #pragma unroll
            for (int u = 0; u < 5; u++) {
                float2 v = unpack2(acc[i][u]);
                As[lr * E + tx * 10 + 2 * u]     = v.x + bcol[2 * u];
                As[lr * E + tx * 10 + 2 * u + 1] = v.y + bcol[2 * u + 1];
            }
        }
        __syncthreads();
        for (int p = t; p < 4 * E; p += 256) {
            int tok = p / E, j = p - tok * E;
            float mx = -3.4e38f;
            #pragma unroll
            for (int r = 0; r < 32; r++) mx = fmaxf(mx, As[(tok * 32 + r) * E + j]);
            Out[(rowBase / 32 + tok) * E + j] = mx;
        }
    } else {
        #pragma unroll
        for (int i = 0; i < 8; i++) {
            size_t ro = (rowBase + ty * 8 + i) * E + tx * 10;
            #pragma unroll
            for (int u = 0; u < 5; u++) {
                float2 v = unpack2(acc[i][u]);
                v.x += bcol[2 * u];
                v.y += bcol[2 * u + 1];
                if (MODE == 1) {
                    v.x = v.x > 0.f ? v.x : expm1f(v.x);
                    v.y = v.y > 0.f ? v.y : expm1f(v.y);
                }
                *reinterpret_cast<float2*>(Out + ro + 2 * u) = v;
            }
        }
    }
}

// ---------------- K3: inner attention (both halves), gather of projected rows ----------
__global__ __launch_bounds__(160) void inner_attn(const int* __restrict__ in_idx,
                                                  const int* __restrict__ out_idx)
{
    __shared__ float qs[16 * E], ks[16 * E], vs[16 * E];
    __shared__ float sc[5 * 16 * 16];
    __shared__ int idx[16];
    const int n = blockIdx.x, b = blockIdx.y;
    const int t = threadIdx.x;
    const size_t tok = (size_t)b * NN + n;

    for (int half = 0; half < 2; half++) {
        const int* ia = half ? out_idx : in_idx;
        if (t == 0) idx[0] = n;
        if (t >= 1 && t < 16) idx[t] = ia[tok * DINN + (t - 1)];
        __syncthreads();

        const float* pq = g_px + (size_t)(half * 3 + 0) * BN * E;
        const float* pk = g_px + (size_t)(half * 3 + 1) * BN * E;
        const float* pv = g_px + (size_t)(half * 3 + 2) * BN * E;
        const size_t base = (size_t)b * NN;
        #pragma unroll
        for (int i = 0; i < 16; i++) {
            size_t rr = (base + idx[i]) * E;
            qs[i * E + t] = pq[rr + t];
            ks[i * E + t] = pk[rr + t];
            vs[i * E + t] = pv[rr + t];
        }
        __syncthreads();

        const float scale = 0.17677669529663687f;  // 1/sqrt(32)
        for (int si = t; si < 1280; si += 160) {
            int h = si >> 8, rem = si & 255, l = rem >> 4, m = rem & 15;
            const float* qr = qs + l * E + h * 32;
            const float* kr = ks + m * E + h * 32;
            float s = 0.f;
            #pragma unroll
            for (int d = 0; d < 32; d++) s += qr[d] * kr[d];
            sc[si] = s * scale;
        }
        __syncthreads();

        if (t < 80) {
            float* row = sc + t * 16;
            float mx = row[0];
            #pragma unroll
            for (int m = 1; m < 16; m++) mx = fmaxf(mx, row[m]);
            float sum = 0.f;
            #pragma unroll
            for (int m = 0; m < 16; m++) { float e = __expf(row[m] - mx); row[m] = e; sum += e; }
            float inv = 1.f / sum;
            #pragma unroll
            for (int m = 0; m < 16; m++) row[m] *= inv;
        }
        __syncthreads();

        float* outp = g_obuf + ((size_t)half * BN + tok) * 16 * E;
        for (int oi = t; oi < 16 * E; oi += 160) {
            int l = oi / E, e = oi - l * E, h = e >> 5;
            const float* srow = sc + (h << 8) + (l << 4);
            float s = 0.f;
            #pragma unroll
            for (int m = 0; m < 16; m++) s += srow[m] * vs[m * E + e];
            outp[oi] = s;
        }
        __syncthreads();
    }
}

// ---------------- K5a: final attention (h=1, L=32, d=160) ----------------
__global__ __launch_bounds__(256) void final_attn()
{
    extern __shared__ float sm[];
    float* qs = sm;              // 32*160
    float* ks = sm + 5120;
    float* vs = sm + 10240;
    float* sc = sm + 15360;      // 32*32
    const size_t tok = blockIdx.x;
    const int t = threadIdx.x;

    // load the two halves of qf/kf/vf (half-major global layout)
    for (int i = t; i < 640; i += 256) {
        ((float4*)qs)[i]       = ((const float4*)(g_fq + tok * 2560))[i];
        ((float4*)qs)[640 + i] = ((const float4*)(g_fq + HALF_ELEMS + tok * 2560))[i];
        ((float4*)ks)[i]       = ((const float4*)(g_fk + tok * 2560))[i];
        ((float4*)ks)[640 + i] = ((const float4*)(g_fk + HALF_ELEMS + tok * 2560))[i];
        ((float4*)vs)[i]       = ((const float4*)(g_fv + tok * 2560))[i];
        ((float4*)vs)[640 + i] = ((const float4*)(g_fv + HALF_ELEMS + tok * 2560))[i];
    }
    __syncthreads();

    // scores: 2x2 register blocks over the 32x32 score matrix
    {
        const int i2 = t >> 4, j2 = t & 15;
        const float* q0 = qs + (2 * i2) * E;
        const float* q1 = q0 + E;
        const float* k0 = ks + (2 * j2) * E;
        const float* k1 = k0 + E;
        float s00 = 0.f, s01 = 0.f, s10 = 0.f, s11 = 0.f;
        #pragma unroll 4
        for (int d = 0; d < E; d++) {
            float a0 = q0[d], a1 = q1[d], b0 = k0[d], b1 = k1[d];
            s00 += a0 * b0; s01 += a0 * b1; s10 += a1 * b0; s11 += a1 * b1;
        }
        const float scale = 0.07905694150420949f;  // 1/sqrt(160)
        sc[(2 * i2) * 32 + 2 * j2]         = s00 * scale;
        sc[(2 * i2) * 32 + 2 * j2 + 1]     = s01 * scale;
        sc[(2 * i2 + 1) * 32 + 2 * j2]     = s10 * scale;
        sc[(2 * i2 + 1) * 32 + 2 * j2 + 1] = s11 * scale;
    }
    __syncthreads();

    if (t < 32) {
        float* row = sc + t * 32;
        float mx = row[0];
        #pragma unroll
        for (int m = 1; m < 32; m++) mx = fmaxf(mx, row[m]);
        float sum = 0.f;
        #pragma unroll
        for (int m = 0; m < 32; m++) { float e = __expf(row[m] - mx); row[m] = e; sum += e; }
        float inv = 1.f / sum;
        #pragma unroll
        for (int m = 0; m < 32; m++) row[m] *= inv;
    }
    __syncthreads();

    // o = softmax @ vf : thread handles row l = t/8, 20 cols starting at (t&7)*20
    {
        const int l = t >> 3, eb = (t & 7) * 20;
        unsigned long long acc[10];
        const unsigned long long z = pack2(0.f, 0.f);
        #pragma unroll
        for (int u = 0; u < 10; u++) acc[u] = z;
        const float* srow = sc + l * 32;
        #pragma unroll 4
        for (int m = 0; m < 32; m++) {
            float s = srow[m];
            unsigned long long s2 = pack2(s, s);
            const unsigned long long* vp =
                reinterpret_cast<const unsigned long long*>(vs + m * E + eb);
            #pragma unroll
            for (int u = 0; u < 10; u++) acc[u] = fma2(s2, vp[u], acc[u]);
        }
        float* outp = g_obuf + (tok * 32 + l) * E + eb;   // token-major reuse of g_obuf
        #pragma unroll
        for (int u = 0; u < 10; u++)
            reinterpret_cast<float2*>(outp)[u] = unpack2(acc[u]);
    }
}

// ---------------- host orchestration ----------------
extern "C" void kernel_launch(void* const* d_in, const int* in_sizes, int n_in,
                              void* d_out, int out_size)
{
    const float* X       = (const float*)d_in[0];
    const int*   in_idx  = (const int*)  d_in[1];
    const int*   out_idx = (const int*)  d_in[2];
    const float* iWq     = (const float*)d_in[3];
    const float* iWk     = (const float*)d_in[4];
    const float* iWv     = (const float*)d_in[5];
    const float* i_in_w  = (const float*)d_in[6];
    const float* i_in_b  = (const float*)d_in[7];
    const float* i_out_w = (const float*)d_in[8];
    const float* i_out_b = (const float*)d_in[9];
    const float* oWq     = (const float*)d_in[10];
    const float* oWk     = (const float*)d_in[11];
    const float* oWv     = (const float*)d_in[12];
    const float* o_in_w  = (const float*)d_in[13];
    const float* o_in_b  = (const float*)d_in[14];
    const float* o_out_w = (const float*)d_in[15];
    const float* o_out_b = (const float*)d_in[16];
    const float* f_in_w  = (const float*)d_in[17];
    const float* f_in_b  = (const float*)d_in[18];
    const float* f_out_w = (const float*)d_in[19];
    const float* f_out_b = (const float*)d_in[20];
    const float* lin_w   = (const float*)d_in[21];
    const float* lin_b   = (const float*)d_in[22];
    float* out = (float*)d_out;

    float *cproj, *mfin, *bfin, *px, *obuf, *fq, *fk, *fv, *pooled;
    cudaGetSymbolAddress((void**)&cproj,  g_cproj);
    cudaGetSymbolAddress((void**)&mfin,   g_mfin);
    cudaGetSymbolAddress((void**)&bfin,   g_bfin);
    cudaGetSymbolAddress((void**)&px,     g_px);
    cudaGetSymbolAddress((void**)&obuf,   g_obuf);
    cudaGetSymbolAddress((void**)&fq,     g_fq);
    cudaGetSymbolAddress((void**)&fk,     g_fk);
    cudaGetSymbolAddress((void**)&fv,     g_fv);
    cudaGetSymbolAddress((void**)&pooled, g_pooled);

    const size_t smem_g = (size_t)(128 * E + E * BSTR) * sizeof(float);   // 185,600 B
    cudaFuncSetAttribute(gemm128<0, 0>, cudaFuncAttributeMaxDynamicSharedMemorySize, (int)smem_g);
    cudaFuncSetAttribute(gemm128<1, 1>, cudaFuncAttributeMaxDynamicSharedMemorySize, (int)smem_g);
    cudaFuncSetAttribute(gemm128<1, 2>, cudaFuncAttributeMaxDynamicSharedMemorySize, (int)smem_g);
    cudaFuncSetAttribute(final_attn,    cudaFuncAttributeMaxDynamicSharedMemorySize, 65536);

    // K1: fused weights + biases
    fuse_weights<<<dim3(E, 12), E>>>(iWq, iWk, iWv, oWq, oWk, oWv,
                                     i_in_w, o_in_w, f_in_w, i_out_w, o_out_w);
    fuse_bias<<<6, E>>>(f_in_w, f_in_b, i_out_b, o_out_b);

    // K2: project X by the 6 fused inner matrices (q/k/v for in & out layers)
    for (int m = 0; m < 6; m++) {
        const float* bias = (m < 3) ? (i_in_b + m * E) : (o_in_b + (m - 3) * E);
        gemm128<0, 0><<<BN / 128, 256, smem_g>>>(X, cproj + (size_t)m * E * E, bias,
                                                 px + (size_t)m * BN * E);
    }

    // K3: inner attentions via gather of projected rows (writes g_obuf half-major)
    inner_attn<<<dim3(NN, BB), 160>>>(in_idx, out_idx);

    // K4: fused final projections (o @ (out_w^T f_in_w^T)) -> qf/kf/vf
    float* F[3] = {fq, fk, fv};
    for (int p = 0; p < 3; p++) {
        for (int h = 0; h < 2; h++) {
            int mf = p * 2 + h;
            gemm128<0, 0><<<(unsigned)(HALF_ELEMS / E / 128), 256, smem_g>>>(
                obuf + (size_t)h * HALF_ELEMS,
                mfin + (size_t)mf * E * E,
                bfin + mf * E,
                F[p] + (size_t)h * HALF_ELEMS);
        }
    }

    // K5a: final attention -> writes g_obuf token-major
    final_attn<<<BN, 256, 65536>>>();

    // K5b: final out-projection + per-token max pool
    gemm128<1, 2><<<BN * 32 / 128, 256, smem_g>>>(obuf, f_out_w, f_out_b, pooled);

    // K6: pooled @ lin_w.T + lin_b, ELU -> output
    gemm128<1, 1><<<BN / 128, 256, smem_g>>>(pooled, lin_w, lin_b, out);

    (void)in_sizes; (void)n_in; (void)out_size;
}

// round 5
// speedup vs baseline: 1.4212x; 1.4212x over previous
#include <cuda_runtime.h>
#include <cuda_fp16.h>
#include <cstdint>
#include <cstdio>

// Problem constants
#define E   160
#define BB  8
#define NN  4096
#define BN  (BB*NN)          // 32768 tokens
#define DINN 15
#define BSTR 162             // smem B row stride for gemm128 (floats)
#define BSTR3 164            // smem B panel stride for gemm3 (floats, 16B-aligned rows)

constexpr size_t HALF_ELEMS = (size_t)BN * 16 * E;   // 83,886,080 elements per half

// ---------------- static device scratch (allocation-free rule) ----------------
__device__ float g_cproj[6 * E * E];       // fused inner projection matrices [k][j]
__device__ float g_mfin [6 * E * E];       // fused final projection matrices [k][j] (q h0,q h1,k h0,k h1,v h0,v h1)
__device__ float g_bfin [6 * E];           // fused final biases
__device__ float g_mv   [2 * E * E];       // v-matrices with f_out_w folded in: [half][k][t]
__device__ float g_bv   [2 * E];           // v-bias with f_out_w folded in
__device__ float g_px   [6ull * BN * E];               // projected X (q/k/v for in & out layers)
__device__ float g_obuf [2ull * BN * 16 * E];          // inner attn out (half-major)
__device__ __half g_fq  [2ull * BN * 16 * E];
__device__ __half g_fk  [2ull * BN * 16 * E];
__device__ __half g_fv  [2ull * BN * 16 * E];          // v' = v-projected + out-projected (f_out_w folded)
__device__ float g_pooled[(size_t)BN * E];

// ---------------- f32x2 helpers (Blackwell packed fp32) ----------------
__device__ __forceinline__ unsigned long long fma2(unsigned long long a,
                                                   unsigned long long b,
                                                   unsigned long long c) {
    unsigned long long d;
    asm("fma.rn.f32x2 %0, %1, %2, %3;" : "=l"(d) : "l"(a), "l"(b), "l"(c));
    return d;
}
__device__ __forceinline__ unsigned long long pack2(float x, float y) {
    unsigned long long r;
    asm("mov.b64 %0, {%1,%2};" : "=l"(r) : "f"(x), "f"(y));
    return r;
}
__device__ __forceinline__ float2 unpack2(unsigned long long v) {
    float2 f;
    asm("mov.b64 {%0,%1}, %2;" : "=f"(f.x), "=f"(f.y) : "l"(v));
    return f;
}

// ---------------- K1: fuse weight matrices ----------------
__global__ void fuse_weights(
    const float* __restrict__ iWq, const float* __restrict__ iWk, const float* __restrict__ iWv,
    const float* __restrict__ oWq, const float* __restrict__ oWk, const float* __restrict__ oWv,
    const float* __restrict__ i_in_w, const float* __restrict__ o_in_w,
    const float* __restrict__ f_in_w, const float* __restrict__ i_out_w,
    const float* __restrict__ o_out_w)
{
    __shared__ float col[E];
    int m = blockIdx.y, r = blockIdx.x, j = threadIdx.x;
    if (m < 6) {
        const float* W = (m == 0) ? iWq : (m == 1) ? iWk : (m == 2) ? iWv
                       : (m == 3) ? oWq : (m == 4) ? oWk : oWv;
        const float* inw = ((m < 3) ? i_in_w : o_in_w) + (size_t)(m % 3) * E * E;
        col[j] = W[r * E + j];
        __syncthreads();
        float s = 0.f;
        #pragma unroll 8
        for (int tt = 0; tt < E; tt++) s += col[tt] * inw[j * E + tt];
        g_cproj[(size_t)m * E * E + r * E + j] = s;
    } else {
        int mf = m - 6;
        int f = mf >> 1;
        const float* ow = (mf & 1) ? o_out_w : i_out_w;
        col[j] = ow[j * E + r];
        __syncthreads();
        float s = 0.f;
        #pragma unroll 8
        for (int c = 0; c < E; c++) s += col[c] * f_in_w[(f * E + j) * E + c];
        g_mfin[(size_t)mf * E * E + r * E + j] = s;
    }
}

// K1b: fused final biases: bfin[mf][j] = out_b @ f_in_w[f*E+j] + f_in_b[f*E+j]
__global__ void fuse_bias(const float* __restrict__ f_in_w, const float* __restrict__ f_in_b,
                          const float* __restrict__ i_out_b, const float* __restrict__ o_out_b)
{
    int mf = blockIdx.x, j = threadIdx.x;
    int f = mf >> 1;
    const float* ob = (mf & 1) ? o_out_b : i_out_b;
    float s = f_in_b[f * E + j];
    #pragma unroll 8
    for (int c = 0; c < E; c++) s += ob[c] * f_in_w[(f * E + j) * E + c];
    g_bfin[mf * E + j] = s;
}

// K1c: fold f_out_w into the fused v matrices: mv[half][k][t] = sum_j mfin_v[half][k][j] * f_out_w[t][j]
__global__ void fuse_v_mat(const float* __restrict__ f_out_w)
{
    __shared__ float rowv[E];
    int k = blockIdx.x, half = blockIdx.y, t = threadIdx.x;
    rowv[t] = g_mfin[(size_t)(4 + half) * E * E + k * E + t];
    __syncthreads();
    float s = 0.f;
    #pragma unroll 8
    for (int j = 0; j < E; j++) s += rowv[j] * f_out_w[t * E + j];
    g_mv[(size_t)half * E * E + k * E + t] = s;
}

// K1d: bv[half][t] = sum_j bfin_v[half][j] * f_out_w[t][j] + f_out_b[t]
__global__ void fuse_v_bias(const float* __restrict__ f_out_w, const float* __restrict__ f_out_b)
{
    __shared__ float rowb[E];
    int half = blockIdx.x, t = threadIdx.x;
    rowb[t] = g_bfin[(4 + half) * E + t];
    __syncthreads();
    float s = f_out_b[t];
    #pragma unroll 8
    for (int j = 0; j < E; j++) s += rowb[j] * f_out_w[t * E + j];
    g_bv[half * E + t] = s;
}

// ---------------- generic 128-row x 160-col GEMM, K=160 (used for K2, K6) -------------
// MODE=0: plain store; MODE=1: elu store
template<int TRANSB, int MODE>
__global__ __launch_bounds__(256, 1) void gemm128(
    const float* __restrict__ A, const float* __restrict__ Bm,
    const float* __restrict__ bias, float* __restrict__ Out)
{
    extern __shared__ float sm[];
    float* As = sm;                 // 128*160 floats
    float* Bs = sm + 128 * E;       // 160*BSTR floats
    const int t = threadIdx.x;
    const size_t rowBase = (size_t)blockIdx.x * 128;

    const float4* Ag = reinterpret_cast<const float4*>(A + rowBase * E);
    float4* As4 = reinterpret_cast<float4*>(As);
    #pragma unroll
    for (int i = 0; i < 20; i++) As4[t + 256 * i] = Ag[t + 256 * i];

    if (TRANSB == 0) {
        #pragma unroll 4
        for (int i = 0; i < 100; i++) {
            int idx = t + 256 * i;
            int k = idx / E, j = idx - k * E;
            Bs[k * BSTR + j] = Bm[idx];
        }
    } else {
        #pragma unroll 4
        for (int i = 0; i < 100; i++) {
            int idx = t + 256 * i;
            int j = idx / E, k = idx - j * E;
            Bs[k * BSTR + j] = Bm[idx];
        }
    }
    __syncthreads();

    const int tx = t & 15, ty = t >> 4;
    unsigned long long acc[8][5];
    const unsigned long long z = pack2(0.f, 0.f);
    #pragma unroll
    for (int i = 0; i < 8; i++)
        #pragma unroll
        for (int u = 0; u < 5; u++) acc[i][u] = z;

    const float* Ath = As + ty * (8 * E);
    #pragma unroll 2
    for (int k = 0; k < E; k++) {
        unsigned long long b2[5];
        const unsigned long long* bp =
            reinterpret_cast<const unsigned long long*>(Bs + k * BSTR + tx * 10);
        #pragma unroll
        for (int u = 0; u < 5; u++) b2[u] = bp[u];
        #pragma unroll
        for (int i = 0; i < 8; i++) {
            float a = Ath[i * E + k];
            unsigned long long a2 = pack2(a, a);
            #pragma unroll
            for (int u = 0; u < 5; u++) acc[i][u] = fma2(a2, b2[u], acc[i][u]);
        }
    }

    float bcol[10];
    #pragma unroll
    for (int u = 0; u < 10; u++) bcol[u] = bias[tx * 10 + u];

    #pragma unroll
    for (int i = 0; i < 8; i++) {
        size_t ro = (rowBase + ty * 8 + i) * E + tx * 10;
        #pragma unroll
        for (int u = 0; u < 5; u++) {
            float2 v = unpack2(acc[i][u]);
            v.x += bcol[2 * u];
            v.y += bcol[2 * u + 1];
            if (MODE == 1) {
                v.x = v.x > 0.f ? v.x : expm1f(v.x);
                v.y = v.y > 0.f ? v.y : expm1f(v.y);
            }
            *reinterpret_cast<float2*>(Out + ro + 2 * u) = v;
        }
    }
}

// ---------------- K4 merged: A-tile resident, 3 output matrices, B k-panel streamed ----
// Rows: 2*BN*16 total (half-major). 4096 tiles per half.
__global__ __launch_bounds__(256, 2) void gemm3()
{
    extern __shared__ float sm[];
    float* As = sm;                        // 128*160 floats = 80KB
    float* Bs = sm + 128 * E;              // 2 buffers * 16 * BSTR3 floats = 20.5KB
    const int t = threadIdx.x;
    const int half = blockIdx.x >> 12;     // 4096 tiles per half
    const size_t rowBase = (size_t)blockIdx.x * 128;

    // load A tile once
    const float4* Ag = reinterpret_cast<const float4*>(g_obuf + rowBase * E);
    float4* As4 = reinterpret_cast<float4*>(As);
    #pragma unroll
    for (int i = 0; i < 20; i++) As4[t + 256 * i] = Ag[t + 256 * i];
    __syncthreads();

    const int tx = t & 15, ty = t >> 4;
    const float* Ath = As + ty * (8 * E);
    const unsigned long long z = pack2(0.f, 0.f);

    for (int p = 0; p < 3; p++) {
        const float* Bm   = (p < 2) ? (g_mfin + (size_t)(2 * p + half) * E * E)
                                    : (g_mv + (size_t)half * E * E);
        const float* bias = (p < 2) ? (g_bfin + (2 * p + half) * E)
                                    : (g_bv + half * E);
        __half* Outp = ((p == 0) ? g_fq : (p == 1) ? g_fk : g_fv) + rowBase * E;
        const float4* Bg = reinterpret_cast<const float4*>(Bm);   // 40 float4 per k-row

        unsigned long long acc[8][5];
        #pragma unroll
        for (int i = 0; i < 8; i++)
            #pragma unroll
            for (int u = 0; u < 5; u++) acc[i][u] = z;

        // prefetch panel 0 (16 k-rows = 640 float4)
        float4 pf[3];
        #pragma unroll
        for (int s = 0; s < 3; s++) {
            int idx = t + 256 * s;
            pf[s] = (idx < 640) ? Bg[idx] : make_float4(0.f, 0.f, 0.f, 0.f);
        }
        // store panel 0 into buffer 0 (safe: previous pass last used buffer 1)
        #pragma unroll
        for (int s = 0; s < 3; s++) {
            int idx = t + 256 * s;
            if (idx < 640) {
                int kk = idx / 40, j4 = idx - kk * 40;
                *reinterpret_cast<float4*>(Bs + kk * BSTR3 + j4 * 4) = pf[s];
            }
        }
        __syncthreads();

        for (int kp = 0; kp < 10; kp++) {
            const int buf = kp & 1;
            if (kp < 9) {
                #pragma unroll
                for (int s = 0; s < 3; s++) {
                    int idx = t + 256 * s;
                    pf[s] = (idx < 640) ? Bg[(kp + 1) * 640 + idx]
                                        : make_float4(0.f, 0.f, 0.f, 0.f);
                }
            }
            // compute on panel kp
            const float* Bp = Bs + buf * (16 * BSTR3) + tx * 10;
            #pragma unroll
            for (int kk = 0; kk < 16; kk++) {
                unsigned long long b2[5];
                const unsigned long long* bp =
                    reinterpret_cast<const unsigned long long*>(Bp + kk * BSTR3);
                #pragma unroll
                for (int u = 0; u < 5; u++) b2[u] = bp[u];
                const int k = kp * 16 + kk;
                #pragma unroll
                for (int i = 0; i < 8; i++) {
                    float a = Ath[i * E + k];
                    unsigned long long a2 = pack2(a, a);
                    #pragma unroll
                    for (int u = 0; u < 5; u++) acc[i][u] = fma2(a2, b2[u], acc[i][u]);
                }
            }
            if (kp < 9) {
                __syncthreads();
                float* Bd = Bs + (buf ^ 1) * (16 * BSTR3);
                #pragma unroll
                for (int s = 0; s < 3; s++) {
                    int idx = t + 256 * s;
                    if (idx < 640) {
                        int kk = idx / 40, j4 = idx - kk * 40;
                        *reinterpret_cast<float4*>(Bd + kk * BSTR3 + j4 * 4) = pf[s];
                    }
                }
                __syncthreads();
            }
        }

        // epilogue: bias + fp16 store
        float bcol[10];
        #pragma unroll
        for (int u = 0; u < 10; u++) bcol[u] = bias[tx * 10 + u];
        #pragma unroll
        for (int i = 0; i < 8; i++) {
            __half* op = Outp + (size_t)(ty * 8 + i) * E + tx * 10;
            #pragma unroll
            for (int u = 0; u < 5; u++) {
                float2 v = unpack2(acc[i][u]);
                v.x += bcol[2 * u];
                v.y += bcol[2 * u + 1];
                *reinterpret_cast<__half2*>(op + 2 * u) = __floats2half2_rn(v.x, v.y);
            }
        }
    }
}

// ---------------- K3: inner attention (both halves), gather of projected rows ----------
__global__ __launch_bounds__(160) void inner_attn(const int* __restrict__ in_idx,
                                                  const int* __restrict__ out_idx)
{
    __shared__ float qs[16 * E], ks[16 * E], vs[16 * E];
    __shared__ float sc[5 * 16 * 16];
    __shared__ int idx[16];
    const int n = blockIdx.x, b = blockIdx.y;
    const int t = threadIdx.x;
    const size_t tok = (size_t)b * NN + n;

    for (int half = 0; half < 2; half++) {
        const int* ia = half ? out_idx : in_idx;
        if (t == 0) idx[0] = n;
        if (t >= 1 && t < 16) idx[t] = ia[tok * DINN + (t - 1)];
        __syncthreads();

        const float* pq = g_px + (size_t)(half * 3 + 0) * BN * E;
        const float* pk = g_px + (size_t)(half * 3 + 1) * BN * E;
        const float* pv = g_px + (size_t)(half * 3 + 2) * BN * E;
        const size_t base = (size_t)b * NN;
        #pragma unroll
        for (int i = 0; i < 16; i++) {
            size_t rr = (base + idx[i]) * E;
            qs[i * E + t] = pq[rr + t];
            ks[i * E + t] = pk[rr + t];
            vs[i * E + t] = pv[rr + t];
        }
        __syncthreads();

        const float scale = 0.17677669529663687f;  // 1/sqrt(32)
        for (int si = t; si < 1280; si += 160) {
            int h = si >> 8, rem = si & 255, l = rem >> 4, m = rem & 15;
            const float* qr = qs + l * E + h * 32;
            const float* kr = ks + m * E + h * 32;
            float s = 0.f;
            #pragma unroll
            for (int d = 0; d < 32; d++) s += qr[d] * kr[d];
            sc[si] = s * scale;
        }
        __syncthreads();

        if (t < 80) {
            float* row = sc + t * 16;
            float mx = row[0];
            #pragma unroll
            for (int m = 1; m < 16; m++) mx = fmaxf(mx, row[m]);
            float sum = 0.f;
            #pragma unroll
            for (int m = 0; m < 16; m++) { float e = __expf(row[m] - mx); row[m] = e; sum += e; }
            float inv = 1.f / sum;
            #pragma unroll
            for (int m = 0; m < 16; m++) row[m] *= inv;
        }
        __syncthreads();

        float* outp = g_obuf + ((size_t)half * BN + tok) * 16 * E;
        for (int oi = t; oi < 16 * E; oi += 160) {
            int l = oi / E, e = oi - l * E, h = e >> 5;
            const float* srow = sc + (h << 8) + (l << 4);
            float s = 0.f;
            #pragma unroll
            for (int m = 0; m < 16; m++) s += srow[m] * vs[m * E + e];
            outp[oi] = s;
        }
        __syncthreads();
    }
}

// ---------------- K5: final attention (h=1, L=32, d=160) + out-proj fold + max pool ----
__global__ __launch_bounds__(256) void final_attn2()
{
    extern __shared__ char smc[];
    __half* qs = reinterpret_cast<__half*>(smc);       // q(5120) k(5120) v(5120) halves
    float* sc  = reinterpret_cast<float*>(smc + 30720); // 32*32
    float* osm = sc + 1024;                             // 32*160
    const size_t tok = blockIdx.x;
    const int t = threadIdx.x;

    // load qf/kf/vf' (fp16, half-major global layout): 3 mats * 2 halves * 320 int4
    {
        for (int i = t; i < 1920; i += 256) {
            int mat = i / 640, r = i - mat * 640;
            int hh = r / 320, x = r - hh * 320;
            const __half* srcp = ((mat == 0) ? g_fq : (mat == 1) ? g_fk : g_fv)
                                 + (size_t)hh * HALF_ELEMS + tok * 2560;
            reinterpret_cast<int4*>(qs + mat * 5120 + hh * 2560)[x] =
                reinterpret_cast<const int4*>(srcp)[x];
        }
    }
    __syncthreads();

    // scores: 2x2 register blocks over the 32x32 score matrix (fp32 accum)
    {
        const int i2 = t >> 4, j2 = t & 15;
        const __half2* q0 = reinterpret_cast<const __half2*>(qs + (2 * i2) * E);
        const __half2* q1 = q0 + 80;
        const __half2* k0 = reinterpret_cast<const __half2*>(qs + 5120 + (2 * j2) * E);
        const __half2* k1 = k0 + 80;
        float s00 = 0.f, s01 = 0.f, s10 = 0.f, s11 = 0.f;
        #pragma unroll 4
        for (int d = 0; d < 80; d++) {
            float2 a0 = __half22float2(q0[d]), a1 = __half22float2(q1[d]);
            float2 b0 = __half22float2(k0[d]), b1 = __half22float2(k1[d]);
            s00 += a0.x * b0.x + a0.y * b0.y;
            s01 += a0.x * b1.x + a0.y * b1.y;
            s10 += a1.x * b0.x + a1.y * b0.y;
            s11 += a1.x * b1.x + a1.y * b1.y;
        }
        const float scale = 0.07905694150420949f;  // 1/sqrt(160)
        sc[(2 * i2) * 32 + 2 * j2]         = s00 * scale;
        sc[(2 * i2) * 32 + 2 * j2 + 1]     = s01 * scale;
        sc[(2 * i2 + 1) * 32 + 2 * j2]     = s10 * scale;
        sc[(2 * i2 + 1) * 32 + 2 * j2 + 1] = s11 * scale;
    }
    __syncthreads();

    if (t < 32) {
        float* row = sc + t * 32;
        float mx = row[0];
        #pragma unroll
        for (int m = 1; m < 32; m++) mx = fmaxf(mx, row[m]);
        float sum = 0.f;
        #pragma unroll
        for (int m = 0; m < 32; m++) { float e = __expf(row[m] - mx); row[m] = e; sum += e; }
        float inv = 1.f / sum;
        #pragma unroll
        for (int m = 0; m < 32; m++) row[m] *= inv;
    }
    __syncthreads();

    // o' = softmax @ vf' (already out-projected; bias folded, rows of S sum to 1)
    {
        const int l = t >> 3, eb = (t & 7) * 20;
        float acc[20];
        #pragma unroll
        for (int u = 0; u < 20; u++) acc[u] = 0.f;
        const float* srow = sc + l * 32;
        const __half* vbase = qs + 10240;
        #pragma unroll 4
        for (int m = 0; m < 32; m++) {
            float s = srow[m];
            const __half2* vp = reinterpret_cast<const __half2*>(vbase + m * E + eb);
            #pragma unroll
            for (int u = 0; u < 10; u++) {
                float2 f = __half22float2(vp[u]);
                acc[2 * u]     += s * f.x;
                acc[2 * u + 1] += s * f.y;
            }
        }
        float* op = osm + l * E + eb;
        #pragma unroll
        for (int u = 0; u < 20; u++) op[u] = acc[u];
    }
    __syncthreads();

    // max pool over the 32 rows -> pooled
    for (int j = t; j < E; j += 256) {
        float mx = -3.4e38f;
        #pragma unroll
        for (int r = 0; r < 32; r++) mx = fmaxf(mx, osm[r * E + j]);
        g_pooled[tok * E + j] = mx;
    }
}

// ---------------- host orchestration ----------------
extern "C" void kernel_launch(void* const* d_in, const int* in_sizes, int n_in,
                              void* d_out, int out_size)
{
    const float* X       = (const float*)d_in[0];
    const int*   in_idx  = (const int*)  d_in[1];
    const int*   out_idx = (const int*)  d_in[2];
    const float* iWq     = (const float*)d_in[3];
    const float* iWk     = (const float*)d_in[4];
    const float* iWv     = (const float*)d_in[5];
    const float* i_in_w  = (const float*)d_in[6];
    const float* i_in_b  = (const float*)d_in[7];
    const float* i_out_w = (const float*)d_in[8];
    const float* i_out_b = (const float*)d_in[9];
    const float* oWq     = (const float*)d_in[10];
    const float* oWk     = (const float*)d_in[11];
    const float* oWv     = (const float*)d_in[12];
    const float* o_in_w  = (const float*)d_in[13];
    const float* o_in_b  = (const float*)d_in[14];
    const float* o_out_w = (const float*)d_in[15];
    const float* o_out_b = (const float*)d_in[16];
    const float* f_in_w  = (const float*)d_in[17];
    const float* f_in_b  = (const float*)d_in[18];
    const float* f_out_w = (const float*)d_in[19];
    const float* f_out_b = (const float*)d_in[20];
    const float* lin_w   = (const float*)d_in[21];
    const float* lin_b   = (const float*)d_in[22];
    float* out = (float*)d_out;

    float *cproj, *px, *pooled;
    cudaGetSymbolAddress((void**)&cproj,  g_cproj);
    cudaGetSymbolAddress((void**)&px,     g_px);
    cudaGetSymbolAddress((void**)&pooled, g_pooled);

    const size_t smem_g  = (size_t)(128 * E + E * BSTR) * sizeof(float);          // 185,600 B
    const size_t smem_g3 = (size_t)(128 * E + 2 * 16 * BSTR3) * sizeof(float);    // 102,912 B
    const size_t smem_fa = 30720 + 4096 + 20480;                                  //  55,296 B
    cudaFuncSetAttribute(gemm128<0, 0>, cudaFuncAttributeMaxDynamicSharedMemorySize, (int)smem_g);
    cudaFuncSetAttribute(gemm128<1, 1>, cudaFuncAttributeMaxDynamicSharedMemorySize, (int)smem_g);
    cudaFuncSetAttribute(gemm3,         cudaFuncAttributeMaxDynamicSharedMemorySize, (int)smem_g3);
    cudaFuncSetAttribute(final_attn2,   cudaFuncAttributeMaxDynamicSharedMemorySize, (int)smem_fa);

    // K1: fused weights + biases (+ f_out_w fold into v path)
    fuse_weights<<<dim3(E, 12), E>>>(iWq, iWk, iWv, oWq, oWk, oWv,
                                     i_in_w, o_in_w, f_in_w, i_out_w, o_out_w);
    fuse_bias<<<6, E>>>(f_in_w, f_in_b, i_out_b, o_out_b);
    fuse_v_mat<<<dim3(E, 2), E>>>(f_out_w);
    fuse_v_bias<<<2, E>>>(f_out_w, f_out_b);

    // K2: project X by the 6 fused inner matrices (q/k/v for in & out layers)
    for (int m = 0; m < 6; m++) {
        const float* bias = (m < 3) ? (i_in_b + m * E) : (o_in_b + (m - 3) * E);
        gemm128<0, 0><<<BN / 128, 256, smem_g>>>(X, cproj + (size_t)m * E * E, bias,
                                                 px + (size_t)m * BN * E);
    }

    // K3: inner attentions via gather of projected rows (writes g_obuf half-major)
    inner_attn<<<dim3(NN, BB), 160>>>(in_idx, out_idx);

    // K4: merged fused final projections -> qf/kf/vf' (fp16), one launch
    gemm3<<<8192, 256, smem_g3>>>();

    // K5: final attention + folded out-projection + max pool -> pooled
    final_attn2<<<BN, 256, smem_fa>>>();

    // K6: pooled @ lin_w.T + lin_b, ELU -> output
    gemm128<1, 1><<<BN / 128, 256, smem_g>>>(pooled, lin_w, lin_b, out);

    (void)in_sizes; (void)n_in; (void)out_size;
}

// round 6
// speedup vs baseline: 2.1518x; 1.5141x over previous
#include <cuda_runtime.h>
#include <cuda_fp16.h>
#include <cstdint>
#include <cstdio>

// Problem constants
#define E   160
#define BB  8
#define NN  4096
#define BN  (BB*NN)          // 32768 tokens
#define DINN 15
#define BSTR 162             // smem B row stride for gemm128 (floats)

constexpr size_t HALF_ELEMS = (size_t)BN * 16 * E;   // 83,886,080 elements per half

// ---------------- static device scratch (allocation-free rule) ----------------
__device__ float g_cproj[6 * E * E];       // fused inner projection matrices [k][j]
__device__ float g_mfin [6 * E * E];       // fused final projection matrices [k][j] (q h0,q h1,k h0,k h1,v h0,v h1)
__device__ float g_bfin [6 * E];           // fused final biases
__device__ float g_mv   [2 * E * E];       // v-matrices with f_out_w folded in: [half][k][t]
__device__ float g_bv   [2 * E];           // v-bias with f_out_w folded in
__device__ __half g_wh  [6 * E * E];       // fp16 weights, transposed [n][k] with k-permuted layout for mma frags
__device__ float g_px   [6ull * BN * E];               // projected X (q/k/v for in & out layers)
__device__ __half g_obuf[2ull * BN * 16 * E];          // inner attn out (half-major), fp16
__device__ __half g_fq  [2ull * BN * 16 * E];
__device__ __half g_fk  [2ull * BN * 16 * E];
__device__ __half g_fv  [2ull * BN * 16 * E];          // v' = v-projected + out-projected (f_out_w folded)
__device__ float g_pooled[(size_t)BN * E];

// ---------------- f32x2 helpers (Blackwell packed fp32) ----------------
__device__ __forceinline__ unsigned long long fma2(unsigned long long a,
                                                   unsigned long long b,
                                                   unsigned long long c) {
    unsigned long long d;
    asm("fma.rn.f32x2 %0, %1, %2, %3;" : "=l"(d) : "l"(a), "l"(b), "l"(c));
    return d;
}
__device__ __forceinline__ unsigned long long pack2(float x, float y) {
    unsigned long long r;
    asm("mov.b64 %0, {%1,%2};" : "=l"(r) : "f"(x), "f"(y));
    return r;
}
__device__ __forceinline__ float2 unpack2(unsigned long long v) {
    float2 f;
    asm("mov.b64 {%0,%1}, %2;" : "=f"(f.x), "=f"(f.y) : "l"(v));
    return f;
}

// ---------------- mma.sync m16n8k16 fp16->fp32 ----------------
__device__ __forceinline__ void mma16816(float* c, uint32_t a0, uint32_t a1,
                                         uint32_t a2, uint32_t a3,
                                         uint32_t b0, uint32_t b1) {
    asm volatile(
        "mma.sync.aligned.m16n8k16.row.col.f32.f16.f16.f32 "
        "{%0,%1,%2,%3}, {%4,%5,%6,%7}, {%8,%9}, {%0,%1,%2,%3};\n"
        : "+f"(c[0]), "+f"(c[1]), "+f"(c[2]), "+f"(c[3])
        : "r"(a0), "r"(a1), "r"(a2), "r"(a3), "r"(b0), "r"(b1));
}

// ---------------- K1: fuse weight matrices ----------------
__global__ void fuse_weights(
    const float* __restrict__ iWq, const float* __restrict__ iWk, const float* __restrict__ iWv,
    const float* __restrict__ oWq, const float* __restrict__ oWk, const float* __restrict__ oWv,
    const float* __restrict__ i_in_w, const float* __restrict__ o_in_w,
    const float* __restrict__ f_in_w, const float* __restrict__ i_out_w,
    const float* __restrict__ o_out_w)
{
    __shared__ float col[E];
    int m = blockIdx.y, r = blockIdx.x, j = threadIdx.x;
    if (m < 6) {
        const float* W = (m == 0) ? iWq : (m == 1) ? iWk : (m == 2) ? iWv
                       : (m == 3) ? oWq : (m == 4) ? oWk : oWv;
        const float* inw = ((m < 3) ? i_in_w : o_in_w) + (size_t)(m % 3) * E * E;
        col[j] = W[r * E + j];
        __syncthreads();
        float s = 0.f;
        #pragma unroll 8
        for (int tt = 0; tt < E; tt++) s += col[tt] * inw[j * E + tt];
        g_cproj[(size_t)m * E * E + r * E + j] = s;
    } else {
        int mf = m - 6;
        int f = mf >> 1;
        const float* ow = (mf & 1) ? o_out_w : i_out_w;
        col[j] = ow[j * E + r];
        __syncthreads();
        float s = 0.f;
        #pragma unroll 8
        for (int c = 0; c < E; c++) s += col[c] * f_in_w[(f * E + j) * E + c];
        g_mfin[(size_t)mf * E * E + r * E + j] = s;
    }
}

// K1b: fused final biases
__global__ void fuse_bias(const float* __restrict__ f_in_w, const float* __restrict__ f_in_b,
                          const float* __restrict__ i_out_b, const float* __restrict__ o_out_b)
{
    int mf = blockIdx.x, j = threadIdx.x;
    int f = mf >> 1;
    const float* ob = (mf & 1) ? o_out_b : i_out_b;
    float s = f_in_b[f * E + j];
    #pragma unroll 8
    for (int c = 0; c < E; c++) s += ob[c] * f_in_w[(f * E + j) * E + c];
    g_bfin[mf * E + j] = s;
}

// K1c: fold f_out_w into the fused v matrices
__global__ void fuse_v_mat(const float* __restrict__ f_out_w)
{
    __shared__ float rowv[E];
    int k = blockIdx.x, half = blockIdx.y, t = threadIdx.x;
    rowv[t] = g_mfin[(size_t)(4 + half) * E * E + k * E + t];
    __syncthreads();
    float s = 0.f;
    #pragma unroll 8
    for (int j = 0; j < E; j++) s += rowv[j] * f_out_w[t * E + j];
    g_mv[(size_t)half * E * E + k * E + t] = s;
}

// K1d: bv[half][t] = bfin_v[half] @ f_out_w[t] + f_out_b[t]
__global__ void fuse_v_bias(const float* __restrict__ f_out_w, const float* __restrict__ f_out_b)
{
    __shared__ float rowb[E];
    int half = blockIdx.x, t = threadIdx.x;
    rowb[t] = g_bfin[(4 + half) * E + t];
    __syncthreads();
    float s = f_out_b[t];
    #pragma unroll 8
    for (int j = 0; j < E; j++) s += rowb[j] * f_out_w[t * E + j];
    g_bv[half * E + t] = s;
}

// K1e: convert fused matrices to fp16, transposed [n][k] with k-permutation so that
// mma fragment k-pairs (2q,2q+1)&(2q+8,2q+9) are contiguous 8-byte chunks.
// mats 0..3 = g_mfin[0..3] (q h0, q h1, k h0, k h1); mats 4,5 = g_mv[0,1] (v' h0, v' h1)
__global__ void convert_wh()
{
    int mat = blockIdx.y, n = blockIdx.x, k = threadIdx.x;
    const float* src = (mat < 4) ? (g_mfin + (size_t)mat * E * E)
                                 : (g_mv + (size_t)(mat - 4) * E * E);
    int ksp = k >> 4, l = k & 15;
    int pos = (l < 8) ? (((l >> 1) << 2) + (l & 1))
                      : ((((l - 8) >> 1) << 2) + 2 + (l & 1));
    g_wh[(size_t)mat * E * E + n * E + ksp * 16 + pos] = __float2half(src[k * E + n]);
}

// ---------------- generic 128-row x 160-col GEMM, K=160 (K2, K6), fp32 f32x2 ----------
template<int TRANSB, int MODE>
__global__ __launch_bounds__(256, 1) void gemm128(
    const float* __restrict__ A, const float* __restrict__ Bm,
    const float* __restrict__ bias, float* __restrict__ Out)
{
    extern __shared__ float sm[];
    float* As = sm;                 // 128*160 floats
    float* Bs = sm + 128 * E;       // 160*BSTR floats
    const int t = threadIdx.x;
    const size_t rowBase = (size_t)blockIdx.x * 128;

    const float4* Ag = reinterpret_cast<const float4*>(A + rowBase * E);
    float4* As4 = reinterpret_cast<float4*>(As);
    #pragma unroll
    for (int i = 0; i < 20; i++) As4[t + 256 * i] = Ag[t + 256 * i];

    if (TRANSB == 0) {
        #pragma unroll 4
        for (int i = 0; i < 100; i++) {
            int idx = t + 256 * i;
            int k = idx / E, j = idx - k * E;
            Bs[k * BSTR + j] = Bm[idx];
        }
    } else {
        #pragma unroll 4
        for (int i = 0; i < 100; i++) {
            int idx = t + 256 * i;
            int j = idx / E, k = idx - j * E;
            Bs[k * BSTR + j] = Bm[idx];
        }
    }
    __syncthreads();

    const int tx = t & 15, ty = t >> 4;
    unsigned long long acc[8][5];
    const unsigned long long z = pack2(0.f, 0.f);
    #pragma unroll
    for (int i = 0; i < 8; i++)
        #pragma unroll
        for (int u = 0; u < 5; u++) acc[i][u] = z;

    const float* Ath = As + ty * (8 * E);
    #pragma unroll 2
    for (int k = 0; k < E; k++) {
        unsigned long long b2[5];
        const unsigned long long* bp =
            reinterpret_cast<const unsigned long long*>(Bs + k * BSTR + tx * 10);
        #pragma unroll
        for (int u = 0; u < 5; u++) b2[u] = bp[u];
        #pragma unroll
        for (int i = 0; i < 8; i++) {
            float a = Ath[i * E + k];
            unsigned long long a2 = pack2(a, a);
            #pragma unroll
            for (int u = 0; u < 5; u++) acc[i][u] = fma2(a2, b2[u], acc[i][u]);
        }
    }

    float bcol[10];
    #pragma unroll
    for (int u = 0; u < 10; u++) bcol[u] = bias[tx * 10 + u];

    #pragma unroll
    for (int i = 0; i < 8; i++) {
        size_t ro = (rowBase + ty * 8 + i) * E + tx * 10;
        #pragma unroll
        for (int u = 0; u < 5; u++) {
            float2 v = unpack2(acc[i][u]);
            v.x += bcol[2 * u];
            v.y += bcol[2 * u + 1];
            if (MODE == 1) {
                v.x = v.x > 0.f ? v.x : expm1f(v.x);
                v.y = v.y > 0.f ? v.y : expm1f(v.y);
            }
            *reinterpret_cast<float2*>(Out + ro + 2 * u) = v;
        }
    }
}

// ---------------- K4: tensor-core fused final projections -------------------
// A tile (128 rows of g_obuf, fp16) resident in smem; 3 passes over q/k/v' weights.
// 8 warps: warp w -> rows [32*(w/2), +32), cols [80*(w&1), +80).
// Smem word layout: row stride 84 words (168 halves) -> conflict-free LDS.64 frags.
__global__ __launch_bounds__(256, 2) void gemm3_mma()
{
    extern __shared__ uint32_t smw[];
    uint32_t* Aw = smw;                 // 128*84 words = 43,008 B
    uint32_t* Bw = smw + 128 * 84;      // 160*84 words = 53,760 B
    const int t = threadIdx.x;
    const int half = blockIdx.x >> 12;  // 4096 tiles per half
    const size_t rowBase = (size_t)blockIdx.x * 128;

    // load A tile with k-permutation (chunks of 8 halves = uint4)
    {
        const uint4* Ag = reinterpret_cast<const uint4*>(g_obuf + rowBase * E);
        #pragma unroll
        for (int s = 0; s < 10; s++) {
            int idx = t + 256 * s;
            int row = idx / 20, c = idx - row * 20;
            uint4 v = Ag[idx];
            uint32_t* d = Aw + row * 84 + (c >> 1) * 8 + (c & 1);
            d[0] = v.x; d[2] = v.y; d[4] = v.z; d[6] = v.w;
        }
    }

    const int lane = t & 31, w = t >> 5;
    const int rb = (w >> 1) * 32;       // tile row base for this warp
    const int cb = (w & 1) * 80;        // tile col base
    const int g = lane >> 2, q = lane & 3;

    const uint32_t* A0 = Aw + (rb + g) * 84 + q * 2;
    const uint32_t* B0 = Bw + (cb + g) * 84 + q * 2;

    for (int p = 0; p < 3; p++) {
        const int mat = 2 * p + half;
        __syncthreads();   // previous pass smem reads (B + stage) complete
        // load B matrix (already transposed+permuted in global)
        {
            const uint4* Bg = reinterpret_cast<const uint4*>(g_wh + (size_t)mat * E * E);
            #pragma unroll
            for (int s = 0; s < 13; s++) {
                int idx = t + 256 * s;
                if (idx < 3200) {
                    int n = idx / 20, c = idx - n * 20;
                    *reinterpret_cast<uint4*>(Bw + n * 84 + c * 4) = Bg[idx];
                }
            }
        }
        __syncthreads();

        float acc[2][10][4];
        #pragma unroll
        for (int h2 = 0; h2 < 2; h2++)
            #pragma unroll
            for (int j = 0; j < 10; j++)
                #pragma unroll
                for (int u = 0; u < 4; u++) acc[h2][j][u] = 0.f;

        #pragma unroll
        for (int ks = 0; ks < 10; ks++) {
            uint2 aA0 = *reinterpret_cast<const uint2*>(A0 + ks * 8);             // rows rb+g
            uint2 aB0 = *reinterpret_cast<const uint2*>(A0 + 8 * 84 + ks * 8);    // rows rb+g+8
            uint2 aA1 = *reinterpret_cast<const uint2*>(A0 + 16 * 84 + ks * 8);   // rows rb+16+g
            uint2 aB1 = *reinterpret_cast<const uint2*>(A0 + 24 * 84 + ks * 8);   // rows rb+24+g
            #pragma unroll
            for (int j = 0; j < 10; j++) {
                uint2 bb = *reinterpret_cast<const uint2*>(B0 + (j * 8) * 84 + ks * 8);
                mma16816(acc[0][j], aA0.x, aB0.x, aA0.y, aB0.y, bb.x, bb.y);
                mma16816(acc[1][j], aA1.x, aB1.x, aA1.y, aB1.y, bb.x, bb.y);
            }
        }

        // epilogue: bias + fp16, staged through smem for coalesced stores
        const float* bias = (p < 2) ? (g_bfin + (2 * p + half) * E)
                                    : (g_bv + half * E);
        __half* Outg = ((p == 0) ? g_fq : (p == 1) ? g_fk : g_fv) + rowBase * E;
        __syncthreads();   // all warps done reading Bw
        __half* stage = reinterpret_cast<__half*>(Bw);
        #pragma unroll
        for (int j = 0; j < 10; j++) {
            int col = cb + j * 8 + q * 2;
            float b0f = bias[col], b1f = bias[col + 1];
            #pragma unroll
            for (int h2 = 0; h2 < 2; h2++) {
                int row = rb + h2 * 16 + g;
                *reinterpret_cast<__half2*>(stage + row * 160 + col) =
                    __floats2half2_rn(acc[h2][j][0] + b0f, acc[h2][j][1] + b1f);
                *reinterpret_cast<__half2*>(stage + (row + 8) * 160 + col) =
                    __floats2half2_rn(acc[h2][j][2] + b0f, acc[h2][j][3] + b1f);
            }
        }
        __syncthreads();
        #pragma unroll
        for (int s = 0; s < 10; s++) {
            int idx = t + 256 * s;
            reinterpret_cast<uint4*>(Outg)[idx] =
                reinterpret_cast<const uint4*>(stage)[idx];
        }
    }
}

// ---------------- K3: inner attention (both halves), gather of projected rows ----------
__global__ __launch_bounds__(160) void inner_attn(const int* __restrict__ in_idx,
                                                  const int* __restrict__ out_idx)
{
    __shared__ float qs[16 * E], ks[16 * E], vs[16 * E];
    __shared__ float sc[5 * 16 * 16];
    __shared__ int idx[16];
    const int n = blockIdx.x, b = blockIdx.y;
    const int t = threadIdx.x;
    const size_t tok = (size_t)b * NN + n;

    for (int half = 0; half < 2; half++) {
        const int* ia = half ? out_idx : in_idx;
        if (t == 0) idx[0] = n;
        if (t >= 1 && t < 16) idx[t] = ia[tok * DINN + (t - 1)];
        __syncthreads();

        const float* pq = g_px + (size_t)(half * 3 + 0) * BN * E;
        const float* pk = g_px + (size_t)(half * 3 + 1) * BN * E;
        const float* pv = g_px + (size_t)(half * 3 + 2) * BN * E;
        const size_t base = (size_t)b * NN;
        #pragma unroll
        for (int i = 0; i < 16; i++) {
            size_t rr = (base + idx[i]) * E;
            qs[i * E + t] = pq[rr + t];
            ks[i * E + t] = pk[rr + t];
            vs[i * E + t] = pv[rr + t];
        }
        __syncthreads();

        const float scale = 0.17677669529663687f;  // 1/sqrt(32)
        for (int si = t; si < 1280; si += 160) {
            int h = si >> 8, rem = si & 255, l = rem >> 4, m = rem & 15;
            const float* qr = qs + l * E + h * 32;
            const float* kr = ks + m * E + h * 32;
            float s = 0.f;
            #pragma unroll
            for (int d = 0; d < 32; d++) s += qr[d] * kr[d];
            sc[si] = s * scale;
        }
        __syncthreads();

        if (t < 80) {
            float* row = sc + t * 16;
            float mx = row[0];
            #pragma unroll
            for (int m = 1; m < 16; m++) mx = fmaxf(mx, row[m]);
            float sum = 0.f;
            #pragma unroll
            for (int m = 0; m < 16; m++) { float e = __expf(row[m] - mx); row[m] = e; sum += e; }
            float inv = 1.f / sum;
            #pragma unroll
            for (int m = 0; m < 16; m++) row[m] *= inv;
        }
        __syncthreads();

        __half* outp = g_obuf + ((size_t)half * BN + tok) * 16 * E;
        for (int oi = t; oi < 16 * E; oi += 160) {
            int l = oi / E, e = oi - l * E, h = e >> 5;
            const float* srow = sc + (h << 8) + (l << 4);
            float s = 0.f;
            #pragma unroll
            for (int m = 0; m < 16; m++) s += srow[m] * vs[m * E + e];
            outp[oi] = __float2half(s);
        }
        __syncthreads();
    }
}

// ---------------- K5: final attention (h=1, L=32, d=160) + folded out-proj + max pool --
__global__ __launch_bounds__(256) void final_attn2()
{
    extern __shared__ char smc[];
    __half* qs = reinterpret_cast<__half*>(smc);        // q(5120) k(5120) v(5120) halves
    float* sc  = reinterpret_cast<float*>(smc + 30720); // 32*32
    float* osm = sc + 1024;                             // 32*160
    const size_t tok = blockIdx.x;
    const int t = threadIdx.x;

    {
        for (int i = t; i < 1920; i += 256) {
            int mat = i / 640, r = i - mat * 640;
            int hh = r / 320, x = r - hh * 320;
            const __half* srcp = ((mat == 0) ? g_fq : (mat == 1) ? g_fk : g_fv)
                                 + (size_t)hh * HALF_ELEMS + tok * 2560;
            reinterpret_cast<int4*>(qs + mat * 5120 + hh * 2560)[x] =
                reinterpret_cast<const int4*>(srcp)[x];
        }
    }
    __syncthreads();

    {
        const int i2 = t >> 4, j2 = t & 15;
        const __half2* q0 = reinterpret_cast<const __half2*>(qs + (2 * i2) * E);
        const __half2* q1 = q0 + 80;
        const __half2* k0 = reinterpret_cast<const __half2*>(qs + 5120 + (2 * j2) * E);
        const __half2* k1 = k0 + 80;
        float s00 = 0.f, s01 = 0.f, s10 = 0.f, s11 = 0.f;
        #pragma unroll 4
        for (int d = 0; d < 80; d++) {
            float2 a0 = __half22float2(q0[d]), a1 = __half22float2(q1[d]);
            float2 b0 = __half22float2(k0[d]), b1 = __half22float2(k1[d]);
            s00 += a0.x * b0.x + a0.y * b0.y;
            s01 += a0.x * b1.x + a0.y * b1.y;
            s10 += a1.x * b0.x + a1.y * b0.y;
            s11 += a1.x * b1.x + a1.y * b1.y;
        }
        const float scale = 0.07905694150420949f;  // 1/sqrt(160)
        sc[(2 * i2) * 32 + 2 * j2]         = s00 * scale;
        sc[(2 * i2) * 32 + 2 * j2 + 1]     = s01 * scale;
        sc[(2 * i2 + 1) * 32 + 2 * j2]     = s10 * scale;
        sc[(2 * i2 + 1) * 32 + 2 * j2 + 1] = s11 * scale;
    }
    __syncthreads();

    if (t < 32) {
        float* row = sc + t * 32;
        float mx = row[0];
        #pragma unroll
        for (int m = 1; m < 32; m++) mx = fmaxf(mx, row[m]);
        float sum = 0.f;
        #pragma unroll
        for (int m = 0; m < 32; m++) { float e = __expf(row[m] - mx); row[m] = e; sum += e; }
        float inv = 1.f / sum;
        #pragma unroll
        for (int m = 0; m < 32; m++) row[m] *= inv;
    }
    __syncthreads();

    {
        const int l = t >> 3, eb = (t & 7) * 20;
        float acc[20];
        #pragma unroll
        for (int u = 0; u < 20; u++) acc[u] = 0.f;
        const float* srow = sc + l * 32;
        const __half* vbase = qs + 10240;
        #pragma unroll 4
        for (int m = 0; m < 32; m++) {
            float s = srow[m];
            const __half2* vp = reinterpret_cast<const __half2*>(vbase + m * E + eb);
            #pragma unroll
            for (int u = 0; u < 10; u++) {
                float2 f = __half22float2(vp[u]);
                acc[2 * u]     += s * f.x;
                acc[2 * u + 1] += s * f.y;
            }
        }
        float* op = osm + l * E + eb;
        #pragma unroll
        for (int u = 0; u < 20; u++) op[u] = acc[u];
    }
    __syncthreads();

    for (int j = t; j < E; j += 256) {
        float mx = -3.4e38f;
        #pragma unroll
        for (int r = 0; r < 32; r++) mx = fmaxf(mx, osm[r * E + j]);
        g_pooled[tok * E + j] = mx;
    }
}

// ---------------- host orchestration ----------------
extern "C" void kernel_launch(void* const* d_in, const int* in_sizes, int n_in,
                              void* d_out, int out_size)
{
    const float* X       = (const float*)d_in[0];
    const int*   in_idx  = (const int*)  d_in[1];
    const int*   out_idx = (const int*)  d_in[2];
    const float* iWq     = (const float*)d_in[3];
    const float* iWk     = (const float*)d_in[4];
    const float* iWv     = (const float*)d_in[5];
    const float* i_in_w  = (const float*)d_in[6];
    const float* i_in_b  = (const float*)d_in[7];
    const float* i_out_w = (const float*)d_in[8];
    const float* i_out_b = (const float*)d_in[9];
    const float* oWq     = (const float*)d_in[10];
    const float* oWk     = (const float*)d_in[11];
    const float* oWv     = (const float*)d_in[12];
    const float* o_in_w  = (const float*)d_in[13];
    const float* o_in_b  = (const float*)d_in[14];
    const float* o_out_w = (const float*)d_in[15];
    const float* o_out_b = (const float*)d_in[16];
    const float* f_in_w  = (const float*)d_in[17];
    const float* f_in_b  = (const float*)d_in[18];
    const float* f_out_w = (const float*)d_in[19];
    const float* f_out_b = (const float*)d_in[20];
    const float* lin_w   = (const float*)d_in[21];
    const float* lin_b   = (const float*)d_in[22];
    float* out = (float*)d_out;

    float *cproj, *px, *pooled;
    cudaGetSymbolAddress((void**)&cproj,  g_cproj);
    cudaGetSymbolAddress((void**)&px,     g_px);
    cudaGetSymbolAddress((void**)&pooled, g_pooled);

    const size_t smem_g   = (size_t)(128 * E + E * BSTR) * sizeof(float);   // 185,600 B
    const size_t smem_mma = (size_t)(128 * 84 + 160 * 84) * 4;              //  96,768 B
    const size_t smem_fa  = 30720 + 4096 + 20480;                           //  55,296 B
    cudaFuncSetAttribute(gemm128<0, 0>, cudaFuncAttributeMaxDynamicSharedMemorySize, (int)smem_g);
    cudaFuncSetAttribute(gemm128<1, 1>, cudaFuncAttributeMaxDynamicSharedMemorySize, (int)smem_g);
    cudaFuncSetAttribute(gemm3_mma,     cudaFuncAttributeMaxDynamicSharedMemorySize, (int)smem_mma);
    cudaFuncSetAttribute(final_attn2,   cudaFuncAttributeMaxDynamicSharedMemorySize, (int)smem_fa);

    // K1: fused weights + biases (+ f_out_w fold into v path, fp16 conversion)
    fuse_weights<<<dim3(E, 12), E>>>(iWq, iWk, iWv, oWq, oWk, oWv,
                                     i_in_w, o_in_w, f_in_w, i_out_w, o_out_w);
    fuse_bias<<<6, E>>>(f_in_w, f_in_b, i_out_b, o_out_b);
    fuse_v_mat<<<dim3(E, 2), E>>>(f_out_w);
    fuse_v_bias<<<2, E>>>(f_out_w, f_out_b);
    convert_wh<<<dim3(E, 6), E>>>();

    // K2: project X by the 6 fused inner matrices (q/k/v for in & out layers)
    for (int m = 0; m < 6; m++) {
        const float* bias = (m < 3) ? (i_in_b + m * E) : (o_in_b + (m - 3) * E);
        gemm128<0, 0><<<BN / 128, 256, smem_g>>>(X, cproj + (size_t)m * E * E, bias,
                                                 px + (size_t)m * BN * E);
    }

    // K3: inner attentions via gather of projected rows (writes g_obuf fp16, half-major)
    inner_attn<<<dim3(NN, BB), 160>>>(in_idx, out_idx);

    // K4: tensor-core fused final projections -> qf/kf/vf' (fp16), one launch
    gemm3_mma<<<8192, 256, smem_mma>>>();

    // K5: final attention + folded out-projection + max pool -> pooled
    final_attn2<<<BN, 256, smem_fa>>>();

    // K6: pooled @ lin_w.T + lin_b, ELU -> output
    gemm128<1, 1><<<BN / 128, 256, smem_g>>>(pooled, lin_w, lin_b, out);

    (void)in_sizes; (void)n_in; (void)out_size;
}

// round 7
// speedup vs baseline: 6.4984x; 3.0200x over previous
#include <cuda_runtime.h>
#include <cuda_fp16.h>
#include <cstdint>
#include <cstdio>

// Problem constants
#define E   160
#define BB  8
#define NN  4096
#define BN  (BB*NN)          // 32768 tokens
#define DINN 15
#define BSTR 162             // smem B row stride for gemm128 (floats)

constexpr size_t HALF_ELEMS = (size_t)BN * 16 * E;   // 83,886,080 elements per half

// ---------------- static device scratch (allocation-free rule) ----------------
__device__ float g_cproj[6 * E * E];       // fused inner projection matrices [k][j]
__device__ float g_mfin [6 * E * E];       // fused final projection matrices [k][j]
__device__ float g_bfin [6 * E];           // fused final biases
__device__ float g_mv   [2 * E * E];       // v-matrices with f_out_w folded in
__device__ float g_bv   [2 * E];
__device__ __half g_wh  [6 * E * E];       // fp16 weights, [n][k] k-permuted for mma frags
__device__ __half g_px  [6ull * BN * E];               // projected X, fp16
__device__ __half g_obuf[2ull * BN * 16 * E];          // inner attn out (half-major), fp16
__device__ __half g_fq  [2ull * BN * 16 * E];
__device__ __half g_fk  [2ull * BN * 16 * E];
__device__ __half g_fv  [2ull * BN * 16 * E];          // v' (f_out_w folded)
__device__ float g_pooled[(size_t)BN * E];

// ---------------- f32x2 helpers ----------------
__device__ __forceinline__ unsigned long long fma2(unsigned long long a,
                                                   unsigned long long b,
                                                   unsigned long long c) {
    unsigned long long d;
    asm("fma.rn.f32x2 %0, %1, %2, %3;" : "=l"(d) : "l"(a), "l"(b), "l"(c));
    return d;
}
__device__ __forceinline__ unsigned long long pack2(float x, float y) {
    unsigned long long r;
    asm("mov.b64 %0, {%1,%2};" : "=l"(r) : "f"(x), "f"(y));
    return r;
}
__device__ __forceinline__ float2 unpack2(unsigned long long v) {
    float2 f;
    asm("mov.b64 {%0,%1}, %2;" : "=f"(f.x), "=f"(f.y) : "l"(v));
    return f;
}

// ---------------- mma.sync m16n8k16 fp16->fp32 ----------------
// validated ordering (R6): a0=(g,klo) a1=(g+8,klo) a2=(g,khi) a3=(g+8,khi);
// b0=(n=g, klo-pair) b1=(n=g, khi-pair)
__device__ __forceinline__ void mma16816(float* c, uint32_t a0, uint32_t a1,
                                         uint32_t a2, uint32_t a3,
                                         uint32_t b0, uint32_t b1) {
    asm volatile(
        "mma.sync.aligned.m16n8k16.row.col.f32.f16.f16.f32 "
        "{%0,%1,%2,%3}, {%4,%5,%6,%7}, {%8,%9}, {%0,%1,%2,%3};\n"
        : "+f"(c[0]), "+f"(c[1]), "+f"(c[2]), "+f"(c[3])
        : "r"(a0), "r"(a1), "r"(a2), "r"(a3), "r"(b0), "r"(b1));
}

__device__ __forceinline__ uint32_t U32(const __half* p) {
    return *reinterpret_cast<const uint32_t*>(p);
}
__device__ __forceinline__ uint32_t H2(__half a, __half b) {
    __half2 h = __halves2half2(a, b);
    return *reinterpret_cast<uint32_t*>(&h);
}
__device__ __forceinline__ uint32_t H2F(float a, float b) {
    __half2 h = __floats2half2_rn(a, b);
    return *reinterpret_cast<uint32_t*>(&h);
}

// ---------------- K1: fuse weight matrices ----------------
__global__ void fuse_weights(
    const float* __restrict__ iWq, const float* __restrict__ iWk, const float* __restrict__ iWv,
    const float* __restrict__ oWq, const float* __restrict__ oWk, const float* __restrict__ oWv,
    const float* __restrict__ i_in_w, const float* __restrict__ o_in_w,
    const float* __restrict__ f_in_w, const float* __restrict__ i_out_w,
    const float* __restrict__ o_out_w)
{
    __shared__ float col[E];
    int m = blockIdx.y, r = blockIdx.x, j = threadIdx.x;
    if (m < 6) {
        const float* W = (m == 0) ? iWq : (m == 1) ? iWk : (m == 2) ? iWv
                       : (m == 3) ? oWq : (m == 4) ? oWk : oWv;
        const float* inw = ((m < 3) ? i_in_w : o_in_w) + (size_t)(m % 3) * E * E;
        col[j] = W[r * E + j];
        __syncthreads();
        float s = 0.f;
        #pragma unroll 8
        for (int tt = 0; tt < E; tt++) s += col[tt] * inw[j * E + tt];
        g_cproj[(size_t)m * E * E + r * E + j] = s;
    } else {
        int mf = m - 6;
        int f = mf >> 1;
        const float* ow = (mf & 1) ? o_out_w : i_out_w;
        col[j] = ow[j * E + r];
        __syncthreads();
        float s = 0.f;
        #pragma unroll 8
        for (int c = 0; c < E; c++) s += col[c] * f_in_w[(f * E + j) * E + c];
        g_mfin[(size_t)mf * E * E + r * E + j] = s;
    }
}

__global__ void fuse_bias(const float* __restrict__ f_in_w, const float* __restrict__ f_in_b,
                          const float* __restrict__ i_out_b, const float* __restrict__ o_out_b)
{
    int mf = blockIdx.x, j = threadIdx.x;
    int f = mf >> 1;
    const float* ob = (mf & 1) ? o_out_b : i_out_b;
    float s = f_in_b[f * E + j];
    #pragma unroll 8
    for (int c = 0; c < E; c++) s += ob[c] * f_in_w[(f * E + j) * E + c];
    g_bfin[mf * E + j] = s;
}

__global__ void fuse_v_mat(const float* __restrict__ f_out_w)
{
    __shared__ float rowv[E];
    int k = blockIdx.x, half = blockIdx.y, t = threadIdx.x;
    rowv[t] = g_mfin[(size_t)(4 + half) * E * E + k * E + t];
    __syncthreads();
    float s = 0.f;
    #pragma unroll 8
    for (int j = 0; j < E; j++) s += rowv[j] * f_out_w[t * E + j];
    g_mv[(size_t)half * E * E + k * E + t] = s;
}

__global__ void fuse_v_bias(const float* __restrict__ f_out_w, const float* __restrict__ f_out_b)
{
    __shared__ float rowb[E];
    int half = blockIdx.x, t = threadIdx.x;
    rowb[t] = g_bfin[(4 + half) * E + t];
    __syncthreads();
    float s = f_out_b[t];
    #pragma unroll 8
    for (int j = 0; j < E; j++) s += rowb[j] * f_out_w[t * E + j];
    g_bv[half * E + t] = s;
}

// K1e: fp16 weights, transposed [n][k], k-permuted for mma frag loads
__global__ void convert_wh()
{
    int mat = blockIdx.y, n = blockIdx.x, k = threadIdx.x;
    const float* src = (mat < 4) ? (g_mfin + (size_t)mat * E * E)
                                 : (g_mv + (size_t)(mat - 4) * E * E);
    int ksp = k >> 4, l = k & 15;
    int pos = (l < 8) ? (((l >> 1) << 2) + (l & 1))
                      : ((((l - 8) >> 1) << 2) + 2 + (l & 1));
    g_wh[(size_t)mat * E * E + n * E + ksp * 16 + pos] = __float2half(src[k * E + n]);
}

// ---------------- 128x160 GEMM K=160, fp32 compute, fp32 out (K6) -------------
template<int TRANSB, int MODE>
__global__ __launch_bounds__(256, 1) void gemm128(
    const float* __restrict__ A, const float* __restrict__ Bm,
    const float* __restrict__ bias, float* __restrict__ Out)
{
    extern __shared__ float sm[];
    float* As = sm;
    float* Bs = sm + 128 * E;
    const int t = threadIdx.x;
    const size_t rowBase = (size_t)blockIdx.x * 128;

    const float4* Ag = reinterpret_cast<const float4*>(A + rowBase * E);
    float4* As4 = reinterpret_cast<float4*>(As);
    #pragma unroll
    for (int i = 0; i < 20; i++) As4[t + 256 * i] = Ag[t + 256 * i];

    if (TRANSB == 0) {
        #pragma unroll 4
        for (int i = 0; i < 100; i++) {
            int idx = t + 256 * i;
            int k = idx / E, j = idx - k * E;
            Bs[k * BSTR + j] = Bm[idx];
        }
    } else {
        #pragma unroll 4
        for (int i = 0; i < 100; i++) {
            int idx = t + 256 * i;
            int j = idx / E, k = idx - j * E;
            Bs[k * BSTR + j] = Bm[idx];
        }
    }
    __syncthreads();

    const int tx = t & 15, ty = t >> 4;
    unsigned long long acc[8][5];
    const unsigned long long z = pack2(0.f, 0.f);
    #pragma unroll
    for (int i = 0; i < 8; i++)
        #pragma unroll
        for (int u = 0; u < 5; u++) acc[i][u] = z;

    const float* Ath = As + ty * (8 * E);
    #pragma unroll 2
    for (int k = 0; k < E; k++) {
        unsigned long long b2[5];
        const unsigned long long* bp =
            reinterpret_cast<const unsigned long long*>(Bs + k * BSTR + tx * 10);
        #pragma unroll
        for (int u = 0; u < 5; u++) b2[u] = bp[u];
        #pragma unroll
        for (int i = 0; i < 8; i++) {
            float a = Ath[i * E + k];
            unsigned long long a2 = pack2(a, a);
            #pragma unroll
            for (int u = 0; u < 5; u++) acc[i][u] = fma2(a2, b2[u], acc[i][u]);
        }
    }

    float bcol[10];
    #pragma unroll
    for (int u = 0; u < 10; u++) bcol[u] = bias[tx * 10 + u];

    #pragma unroll
    for (int i = 0; i < 8; i++) {
        size_t ro = (rowBase + ty * 8 + i) * E + tx * 10;
        #pragma unroll
        for (int u = 0; u < 5; u++) {
            float2 v = unpack2(acc[i][u]);
            v.x += bcol[2 * u];
            v.y += bcol[2 * u + 1];
            if (MODE == 1) {
                v.x = v.x > 0.f ? v.x : expm1f(v.x);
                v.y = v.y > 0.f ? v.y : expm1f(v.y);
            }
            *reinterpret_cast<float2*>(Out + ro + 2 * u) = v;
        }
    }
}

// ---------------- same GEMM, fp16 output (K2 -> px) -------------
__global__ __launch_bounds__(256, 1) void gemm128h(
    const float* __restrict__ A, const float* __restrict__ Bm,
    const float* __restrict__ bias, __half* __restrict__ Out)
{
    extern __shared__ float sm[];
    float* As = sm;
    float* Bs = sm + 128 * E;
    const int t = threadIdx.x;
    const size_t rowBase = (size_t)blockIdx.x * 128;

    const float4* Ag = reinterpret_cast<const float4*>(A + rowBase * E);
    float4* As4 = reinterpret_cast<float4*>(As);
    #pragma unroll
    for (int i = 0; i < 20; i++) As4[t + 256 * i] = Ag[t + 256 * i];

    #pragma unroll 4
    for (int i = 0; i < 100; i++) {
        int idx = t + 256 * i;
        int k = idx / E, j = idx - k * E;
        Bs[k * BSTR + j] = Bm[idx];
    }
    __syncthreads();

    const int tx = t & 15, ty = t >> 4;
    unsigned long long acc[8][5];
    const unsigned long long z = pack2(0.f, 0.f);
    #pragma unroll
    for (int i = 0; i < 8; i++)
        #pragma unroll
        for (int u = 0; u < 5; u++) acc[i][u] = z;

    const float* Ath = As + ty * (8 * E);
    #pragma unroll 2
    for (int k = 0; k < E; k++) {
        unsigned long long b2[5];
        const unsigned long long* bp =
            reinterpret_cast<const unsigned long long*>(Bs + k * BSTR + tx * 10);
        #pragma unroll
        for (int u = 0; u < 5; u++) b2[u] = bp[u];
        #pragma unroll
        for (int i = 0; i < 8; i++) {
            float a = Ath[i * E + k];
            unsigned long long a2 = pack2(a, a);
            #pragma unroll
            for (int u = 0; u < 5; u++) acc[i][u] = fma2(a2, b2[u], acc[i][u]);
        }
    }

    float bcol[10];
    #pragma unroll
    for (int u = 0; u < 10; u++) bcol[u] = bias[tx * 10 + u];

    #pragma unroll
    for (int i = 0; i < 8; i++) {
        size_t ro = (rowBase + ty * 8 + i) * E + tx * 10;
        #pragma unroll
        for (int u = 0; u < 5; u++) {
            float2 v = unpack2(acc[i][u]);
            *reinterpret_cast<__half2*>(Out + ro + 2 * u) =
                __floats2half2_rn(v.x + bcol[2 * u], v.y + bcol[2 * u + 1]);
        }
    }
}

// ---------------- K4: tensor-core fused final projections (unchanged) ---------
__global__ __launch_bounds__(256, 2) void gemm3_mma()
{
    extern __shared__ uint32_t smw[];
    uint32_t* Aw = smw;                 // 128*84 words
    uint32_t* Bw = smw + 128 * 84;      // 160*84 words
    const int t = threadIdx.x;
    const int half = blockIdx.x >> 12;
    const size_t rowBase = (size_t)blockIdx.x * 128;

    {
        const uint4* Ag = reinterpret_cast<const uint4*>(g_obuf + rowBase * E);
        #pragma unroll
        for (int s = 0; s < 10; s++) {
            int idx = t + 256 * s;
            int row = idx / 20, c = idx - row * 20;
            uint4 v = Ag[idx];
            uint32_t* d = Aw + row * 84 + (c >> 1) * 8 + (c & 1);
            d[0] = v.x; d[2] = v.y; d[4] = v.z; d[6] = v.w;
        }
    }

    const int lane = t & 31, w = t >> 5;
    const int rb = (w >> 1) * 32;
    const int cb = (w & 1) * 80;
    const int g = lane >> 2, q = lane & 3;

    const uint32_t* A0 = Aw + (rb + g) * 84 + q * 2;
    const uint32_t* B0 = Bw + (cb + g) * 84 + q * 2;

    for (int p = 0; p < 3; p++) {
        const int mat = 2 * p + half;
        __syncthreads();
        {
            const uint4* Bg = reinterpret_cast<const uint4*>(g_wh + (size_t)mat * E * E);
            #pragma unroll
            for (int s = 0; s < 13; s++) {
                int idx = t + 256 * s;
                if (idx < 3200) {
                    int n = idx / 20, c = idx - n * 20;
                    *reinterpret_cast<uint4*>(Bw + n * 84 + c * 4) = Bg[idx];
                }
            }
        }
        __syncthreads();

        float acc[2][10][4];
        #pragma unroll
        for (int h2 = 0; h2 < 2; h2++)
            #pragma unroll
            for (int j = 0; j < 10; j++)
                #pragma unroll
                for (int u = 0; u < 4; u++) acc[h2][j][u] = 0.f;

        #pragma unroll
        for (int ks = 0; ks < 10; ks++) {
            uint2 aA0 = *reinterpret_cast<const uint2*>(A0 + ks * 8);
            uint2 aB0 = *reinterpret_cast<const uint2*>(A0 + 8 * 84 + ks * 8);
            uint2 aA1 = *reinterpret_cast<const uint2*>(A0 + 16 * 84 + ks * 8);
            uint2 aB1 = *reinterpret_cast<const uint2*>(A0 + 24 * 84 + ks * 8);
            #pragma unroll
            for (int j = 0; j < 10; j++) {
                uint2 bb = *reinterpret_cast<const uint2*>(B0 + (j * 8) * 84 + ks * 8);
                mma16816(acc[0][j], aA0.x, aB0.x, aA0.y, aB0.y, bb.x, bb.y);
                mma16816(acc[1][j], aA1.x, aB1.x, aA1.y, aB1.y, bb.x, bb.y);
            }
        }

        const float* bias = (p < 2) ? (g_bfin + (2 * p + half) * E)
                                    : (g_bv + half * E);
        __half* Outg = ((p == 0) ? g_fq : (p == 1) ? g_fk : g_fv) + rowBase * E;
        __syncthreads();
        __half* stage = reinterpret_cast<__half*>(Bw);
        #pragma unroll
        for (int j = 0; j < 10; j++) {
            int col = cb + j * 8 + q * 2;
            float b0f = bias[col], b1f = bias[col + 1];
            #pragma unroll
            for (int h2 = 0; h2 < 2; h2++) {
                int row = rb + h2 * 16 + g;
                *reinterpret_cast<__half2*>(stage + row * 160 + col) =
                    __floats2half2_rn(acc[h2][j][0] + b0f, acc[h2][j][1] + b1f);
                *reinterpret_cast<__half2*>(stage + (row + 8) * 160 + col) =
                    __floats2half2_rn(acc[h2][j][2] + b0f, acc[h2][j][3] + b1f);
            }
        }
        __syncthreads();
        #pragma unroll
        for (int s = 0; s < 10; s++) {
            int idx = t + 256 * s;
            reinterpret_cast<uint4*>(Outg)[idx] =
                reinterpret_cast<const uint4*>(stage)[idx];
        }
    }
}

// ---------------- K3: inner attention via mma, warp per (half, head) ----------
__global__ __launch_bounds__(320) void inner_attn_mma(const int* __restrict__ in_idx,
                                                      const int* __restrict__ out_idx)
{
    __shared__ __half tile[96][164];   // rows: hh*48 + mat*16 + l  (mat: q,k,v)
    __shared__ int idxs[2][16];
    const int n = blockIdx.x, b = blockIdx.y;
    const int t = threadIdx.x;
    const size_t tok = (size_t)b * NN + n;
    const size_t base = (size_t)b * NN;

    if (t < 32) {
        int hh = t >> 4, i = t & 15;
        const int* ia = hh ? out_idx : in_idx;
        idxs[hh][i] = (i == 0) ? n : ia[tok * DINN + i - 1];
    }
    __syncthreads();

    // gather 96 rows x 320B (fp16), 1920 uint4 tasks / 320 threads = 6
    #pragma unroll
    for (int it = 0; it < 6; it++) {
        int task = t + 320 * it;
        int r = task / 20, seg = task - r * 20;
        int hh = r / 48, sub = r - hh * 48;
        int mat = sub >> 4, l = sub & 15;
        const __half* src = g_px +
            ((size_t)(hh * 3 + mat) * BN + base + idxs[hh][l]) * E + seg * 8;
        uint4 v = *reinterpret_cast<const uint4*>(src);
        uint2* d = reinterpret_cast<uint2*>(&tile[r][seg * 8]);
        d[0] = make_uint2(v.x, v.y);
        d[1] = make_uint2(v.z, v.w);
    }
    __syncthreads();

    const int w = t >> 5, lane = t & 31;
    const int g = lane >> 2, q = lane & 3;
    const int hh = w / 5, h = w - hh * 5;
    const int qr = hh * 48, kr = qr + 16, vr = qr + 32;
    const int koff = h * 32;

    // scores S[16][16] = Q Kt over d=32 (2 k-chunks, 2 n-tiles)
    float s0[4] = {0.f, 0.f, 0.f, 0.f}, s1[4] = {0.f, 0.f, 0.f, 0.f};
    #pragma unroll
    for (int kc = 0; kc < 2; kc++) {
        int ko = koff + kc * 16 + 2 * q;
        uint32_t a0 = U32(&tile[qr + g][ko]);
        uint32_t a1 = U32(&tile[qr + g + 8][ko]);
        uint32_t a2 = U32(&tile[qr + g][ko + 8]);
        uint32_t a3 = U32(&tile[qr + g + 8][ko + 8]);
        uint32_t b0 = U32(&tile[kr + g][ko]);
        uint32_t b1 = U32(&tile[kr + g][ko + 8]);
        mma16816(s0, a0, a1, a2, a3, b0, b1);
        uint32_t b2 = U32(&tile[kr + 8 + g][ko]);
        uint32_t b3 = U32(&tile[kr + 8 + g][ko + 8]);
        mma16816(s1, a0, a1, a2, a3, b2, b3);
    }
    const float scale = 0.17677669529663687f;  // 1/sqrt(32)
    #pragma unroll
    for (int u = 0; u < 4; u++) { s0[u] *= scale; s1[u] *= scale; }

    // in-register softmax over cols (rows g and g+8), reduce across 4 q-lanes
    float mx0 = fmaxf(fmaxf(s0[0], s0[1]), fmaxf(s1[0], s1[1]));
    float mx1 = fmaxf(fmaxf(s0[2], s0[3]), fmaxf(s1[2], s1[3]));
    mx0 = fmaxf(mx0, __shfl_xor_sync(0xffffffffu, mx0, 1));
    mx0 = fmaxf(mx0, __shfl_xor_sync(0xffffffffu, mx0, 2));
    mx1 = fmaxf(mx1, __shfl_xor_sync(0xffffffffu, mx1, 1));
    mx1 = fmaxf(mx1, __shfl_xor_sync(0xffffffffu, mx1, 2));
    float e00 = __expf(s0[0] - mx0), e01 = __expf(s0[1] - mx0);
    float e02 = __expf(s1[0] - mx0), e03 = __expf(s1[1] - mx0);
    float e10 = __expf(s0[2] - mx1), e11 = __expf(s0[3] - mx1);
    float e12 = __expf(s1[2] - mx1), e13 = __expf(s1[3] - mx1);
    float sum0 = e00 + e01 + e02 + e03;
    float sum1 = e10 + e11 + e12 + e13;
    sum0 += __shfl_xor_sync(0xffffffffu, sum0, 1);
    sum0 += __shfl_xor_sync(0xffffffffu, sum0, 2);
    sum1 += __shfl_xor_sync(0xffffffffu, sum1, 1);
    sum1 += __shfl_xor_sync(0xffffffffu, sum1, 2);
    float inv0 = 1.f / sum0, inv1 = 1.f / sum1;

    // probs -> a-frags (c->a mapping)
    uint32_t pa0 = H2F(e00 * inv0, e01 * inv0);   // (row g,   k 2q,2q+1)
    uint32_t pa1 = H2F(e10 * inv1, e11 * inv1);   // (row g+8, k 2q,2q+1)
    uint32_t pa2 = H2F(e02 * inv0, e03 * inv0);   // (row g,   k 2q+8,2q+9)
    uint32_t pa3 = H2F(e12 * inv1, e13 * inv1);   // (row g+8, k 2q+8,2q+9)

    // AV: O[16][32] = P @ V, 4 n-tiles, k=16
    __half* ob = g_obuf + ((size_t)hh * BN + tok) * (16 * E) + koff;
    #pragma unroll
    for (int nt = 0; nt < 4; nt++) {
        int vc = koff + nt * 8 + g;
        uint32_t b0 = H2(tile[vr + 2 * q][vc], tile[vr + 2 * q + 1][vc]);
        uint32_t b1 = H2(tile[vr + 2 * q + 8][vc], tile[vr + 2 * q + 9][vc]);
        float o[4] = {0.f, 0.f, 0.f, 0.f};
        mma16816(o, pa0, pa1, pa2, pa3, b0, b1);
        *reinterpret_cast<__half2*>(ob + (size_t)g * E + nt * 8 + 2 * q) =
            __floats2half2_rn(o[0], o[1]);
        *reinterpret_cast<__half2*>(ob + (size_t)(g + 8) * E + nt * 8 + 2 * q) =
            __floats2half2_rn(o[2], o[3]);
    }
}

// ---------------- K5: final attention via mma + folded out-proj + max pool ----
__global__ __launch_bounds__(256) void final_attn_mma()
{
    __shared__ __half tile[96][164];   // rows 0-31 q, 32-63 k, 64-95 v
    __shared__ float sc[32][34];
    __shared__ __half ps[32][34];
    __shared__ float pb[2][160];
    const size_t tok = blockIdx.x;
    const int t = threadIdx.x;

    // load q/k/v' (fp16, half-major global layout): 1920 uint4 tasks
    #pragma unroll
    for (int it = 0; it < 8; it++) {
        int task = t + 256 * it;
        if (task < 1920) {
            int r = task / 20, seg = task - r * 20;
            int mat = r >> 5, rr = r & 31, hh = rr >> 4, l = rr & 15;
            const __half* src = ((mat == 0) ? g_fq : (mat == 1) ? g_fk : g_fv)
                + (size_t)hh * HALF_ELEMS + tok * 2560 + l * 160 + seg * 8;
            uint4 v = *reinterpret_cast<const uint4*>(src);
            uint2* d = reinterpret_cast<uint2*>(&tile[r][seg * 8]);
            d[0] = make_uint2(v.x, v.y);
            d[1] = make_uint2(v.z, v.w);
        }
    }
    __syncthreads();

    const int w = t >> 5, lane = t & 31, g = lane >> 2, q = lane & 3;

    // scores: warp -> (m-tile w>>2, n-tile w&3), k=160 in 10 chunks
    {
        const int mt = w >> 2, nt = w & 3;
        const int qr = mt * 16, kr = 32 + nt * 8;
        float c[4] = {0.f, 0.f, 0.f, 0.f};
        #pragma unroll
        for (int kc = 0; kc < 10; kc++) {
            int ko = kc * 16 + 2 * q;
            uint32_t a0 = U32(&tile[qr + g][ko]);
            uint32_t a1 = U32(&tile[qr + g + 8][ko]);
            uint32_t a2 = U32(&tile[qr + g][ko + 8]);
            uint32_t a3 = U32(&tile[qr + g + 8][ko + 8]);
            uint32_t b0 = U32(&tile[kr + g][ko]);
            uint32_t b1 = U32(&tile[kr + g][ko + 8]);
            mma16816(c, a0, a1, a2, a3, b0, b1);
        }
        *reinterpret_cast<float2*>(&sc[qr + g][nt * 8 + 2 * q]) = make_float2(c[0], c[1]);
        *reinterpret_cast<float2*>(&sc[qr + g + 8][nt * 8 + 2 * q]) = make_float2(c[2], c[3]);
    }
    __syncthreads();

    // softmax rows (32 threads), probs -> fp16
    if (t < 32) {
        const float scale = 0.07905694150420949f;  // 1/sqrt(160)
        float v[32];
        float mx = -3.4e38f;
        #pragma unroll
        for (int m = 0; m < 32; m++) { v[m] = sc[t][m] * scale; mx = fmaxf(mx, v[m]); }
        float sum = 0.f;
        #pragma unroll
        for (int m = 0; m < 32; m++) { v[m] = __expf(v[m] - mx); sum += v[m]; }
        float inv = 1.f / sum;
        #pragma unroll
        for (int m = 0; m < 16; m++)
            *reinterpret_cast<__half2*>(&ps[t][2 * m]) =
                __floats2half2_rn(v[2 * m] * inv, v[2 * m + 1] * inv);
    }
    __syncthreads();

    // AV: O = P(32x32) @ V(32x160); warp -> m-tile w>>2, n-tiles (w&3)+4j
    {
        const int mt = w >> 2, nb = w & 3;
        const int mr = mt * 16;
        uint32_t a[2][4];
        #pragma unroll
        for (int kc = 0; kc < 2; kc++) {
            int ko = kc * 16 + 2 * q;
            a[kc][0] = U32(&ps[mr + g][ko]);
            a[kc][1] = U32(&ps[mr + g + 8][ko]);
            a[kc][2] = U32(&ps[mr + g][ko + 8]);
            a[kc][3] = U32(&ps[mr + g + 8][ko + 8]);
        }
        #pragma unroll
        for (int j = 0; j < 5; j++) {
            int nt = nb + 4 * j;
            int vc = nt * 8 + g;
            float o[4] = {0.f, 0.f, 0.f, 0.f};
            #pragma unroll
            for (int kc = 0; kc < 2; kc++) {
                int vrow = 64 + kc * 16;
                uint32_t b0 = H2(tile[vrow + 2 * q][vc], tile[vrow + 2 * q + 1][vc]);
                uint32_t b1 = H2(tile[vrow + 2 * q + 8][vc], tile[vrow + 2 * q + 9][vc]);
                mma16816(o, a[kc][0], a[kc][1], a[kc][2], a[kc][3], b0, b1);
            }
            // column maxes over this warp's 16 rows (rows spread over g; 2 per lane)
            float m0 = fmaxf(o[0], o[2]);   // col nt*8+2q
            float m1 = fmaxf(o[1], o[3]);   // col nt*8+2q+1
            #pragma unroll
            for (int s = 4; s < 32; s <<= 1) {
                m0 = fmaxf(m0, __shfl_xor_sync(0xffffffffu, m0, s));
                m1 = fmaxf(m1, __shfl_xor_sync(0xffffffffu, m1, s));
            }
            if (g == 0)
                *reinterpret_cast<float2*>(&pb[mt][nt * 8 + 2 * q]) = make_float2(m0, m1);
        }
    }
    __syncthreads();

    if (t < 160)
        g_pooled[tok * E + t] = fmaxf(pb[0][t], pb[1][t]);
}

// ---------------- host orchestration ----------------
extern "C" void kernel_launch(void* const* d_in, const int* in_sizes, int n_in,
                              void* d_out, int out_size)
{
    const float* X       = (const float*)d_in[0];
    const int*   in_idx  = (const int*)  d_in[1];
    const int*   out_idx = (const int*)  d_in[2];
    const float* iWq     = (const float*)d_in[3];
    const float* iWk     = (const float*)d_in[4];
    const float* iWv     = (const float*)d_in[5];
    const float* i_in_w  = (const float*)d_in[6];
    const float* i_in_b  = (const float*)d_in[7];
    const float* i_out_w = (const float*)d_in[8];
    const float* i_out_b = (const float*)d_in[9];
    const float* oWq     = (const float*)d_in[10];
    const float* oWk     = (const float*)d_in[11];
    const float* oWv     = (const float*)d_in[12];
    const float* o_in_w  = (const float*)d_in[13];
    const float* o_in_b  = (const float*)d_in[14];
    const float* o_out_w = (const float*)d_in[15];
    const float* o_out_b = (const float*)d_in[16];
    const float* f_in_w  = (const float*)d_in[17];
    const float* f_in_b  = (const float*)d_in[18];
    const float* f_out_w = (const float*)d_in[19];
    const float* f_out_b = (const float*)d_in[20];
    const float* lin_w   = (const float*)d_in[21];
    const float* lin_b   = (const float*)d_in[22];
    float* out = (float*)d_out;

    float *cproj, *pooled;
    __half* px;
    cudaGetSymbolAddress((void**)&cproj,  g_cproj);
    cudaGetSymbolAddress((void**)&px,     g_px);
    cudaGetSymbolAddress((void**)&pooled, g_pooled);

    const size_t smem_g   = (size_t)(128 * E + E * BSTR) * sizeof(float);   // 185,600 B
    const size_t smem_mma = (size_t)(128 * 84 + 160 * 84) * 4;              //  96,768 B
    cudaFuncSetAttribute(gemm128h,      cudaFuncAttributeMaxDynamicSharedMemorySize, (int)smem_g);
    cudaFuncSetAttribute(gemm128<1, 1>, cudaFuncAttributeMaxDynamicSharedMemorySize, (int)smem_g);
    cudaFuncSetAttribute(gemm3_mma,     cudaFuncAttributeMaxDynamicSharedMemorySize, (int)smem_mma);

    // K1: fused weights + biases + fp16 conversion
    fuse_weights<<<dim3(E, 12), E>>>(iWq, iWk, iWv, oWq, oWk, oWv,
                                     i_in_w, o_in_w, f_in_w, i_out_w, o_out_w);
    fuse_bias<<<6, E>>>(f_in_w, f_in_b, i_out_b, o_out_b);
    fuse_v_mat<<<dim3(E, 2), E>>>(f_out_w);
    fuse_v_bias<<<2, E>>>(f_out_w, f_out_b);
    convert_wh<<<dim3(E, 6), E>>>();

    // K2: project X by the 6 fused inner matrices -> px (fp16)
    for (int m = 0; m < 6; m++) {
        const float* bias = (m < 3) ? (i_in_b + m * E) : (o_in_b + (m - 3) * E);
        gemm128h<<<BN / 128, 256, smem_g>>>(X, cproj + (size_t)m * E * E, bias,
                                            px + (size_t)m * BN * E);
    }

    // K3: inner attentions via tensor cores (writes g_obuf fp16, half-major)
    inner_attn_mma<<<dim3(NN, BB), 320>>>(in_idx, out_idx);

    // K4: tensor-core fused final projections -> qf/kf/vf' (fp16)
    gemm3_mma<<<8192, 256, smem_mma>>>();

    // K5: final attention (mma) + folded out-projection + max pool -> pooled
    final_attn_mma<<<BN, 256>>>();

    // K6: pooled @ lin_w.T + lin_b, ELU -> output
    gemm128<1, 1><<<BN / 128, 256, smem_g>>>(pooled, lin_w, lin_b, out);

    (void)in_sizes; (void)n_in; (void)out_size;
}

// round 9
// speedup vs baseline: 7.5923x; 1.1683x over previous
#include <cuda_runtime.h>
#include <cuda_fp16.h>
#include <cstdint>
#include <cstdio>

// Problem constants
#define E   160
#define BB  8
#define NN  4096
#define BN  (BB*NN)          // 32768 tokens
#define DINN 15
#define BSTR 162             // smem B row stride for gemm128 (floats)

constexpr size_t HALF_ELEMS = (size_t)BN * 16 * E;   // elements per half

// ---------------- static device scratch (allocation-free rule) ----------------
__device__ float g_cproj[6 * E * E];       // fused inner projection matrices [k][j]
__device__ float g_mfin [6 * E * E];       // fused final projection matrices [k][j]
__device__ float g_bfin [6 * E];           // fused final biases
__device__ float g_bv   [2 * E];           // v-bias with f_out_w folded in
__device__ __half g_wh  [12 * E * E];      // fp16 weights [n][k] k-permuted: 0-3 qf/kf, 4-5 vf', 6-11 cproj
__device__ __half g_px  [6ull * BN * E];               // projected X, fp16
__device__ __half g_obuf[2ull * BN * 16 * E];          // inner attn out (half-major), fp16
__device__ __half g_fq  [2ull * BN * 16 * E];
__device__ __half g_fk  [2ull * BN * 16 * E];
__device__ __half g_fv  [2ull * BN * 16 * E];          // v' (f_out_w folded)
__device__ float g_pooled[(size_t)BN * E];

// ---------------- f32x2 helpers ----------------
__device__ __forceinline__ unsigned long long fma2(unsigned long long a,
                                                   unsigned long long b,
                                                   unsigned long long c) {
    unsigned long long d;
    asm("fma.rn.f32x2 %0, %1, %2, %3;" : "=l"(d) : "l"(a), "l"(b), "l"(c));
    return d;
}
__device__ __forceinline__ unsigned long long pack2(float x, float y) {
    unsigned long long r;
    asm("mov.b64 %0, {%1,%2};" : "=l"(r) : "f"(x), "f"(y));
    return r;
}
__device__ __forceinline__ float2 unpack2(unsigned long long v) {
    float2 f;
    asm("mov.b64 {%0,%1}, %2;" : "=f"(f.x), "=f"(f.y) : "l"(v));
    return f;
}

// ---------------- mma.sync m16n8k16 fp16->fp32 (validated frag ordering) -------
__device__ __forceinline__ void mma16816(float* c, uint32_t a0, uint32_t a1,
                                         uint32_t a2, uint32_t a3,
                                         uint32_t b0, uint32_t b1) {
    asm volatile(
        "mma.sync.aligned.m16n8k16.row.col.f32.f16.f16.f32 "
        "{%0,%1,%2,%3}, {%4,%5,%6,%7}, {%8,%9}, {%0,%1,%2,%3};\n"
        : "+f"(c[0]), "+f"(c[1]), "+f"(c[2]), "+f"(c[3])
        : "r"(a0), "r"(a1), "r"(a2), "r"(a3), "r"(b0), "r"(b1));
}

__device__ __forceinline__ uint32_t U32(const __half* p) {
    return *reinterpret_cast<const uint32_t*>(p);
}
__device__ __forceinline__ uint32_t H2(__half a, __half b) {
    __half2 h = __halves2half2(a, b);
    return *reinterpret_cast<uint32_t*>(&h);
}
__device__ __forceinline__ uint32_t H2F(float a, float b) {
    __half2 h = __floats2half2_rn(a, b);
    return *reinterpret_cast<uint32_t*>(&h);
}

// k-permutation within a 16-k group so mma k-pairs are contiguous words
__device__ __forceinline__ int kperm(int l) {
    return (l < 8) ? (((l >> 1) << 2) + (l & 1))
                   : ((((l - 8) >> 1) << 2) + 2 + (l & 1));
}

// ---------------- setup1: all fused fp32 matrices + fused biases ----------------
// m 0..5: g_cproj[m] = W_m @ in_w_slice.T  ([k][j])
// m 6..11: g_mfin[m-6][k][j] = sum_c f_in_w[f*E+j][c] * out_w[c][k]
// m == 12, r < 6: g_bfin[r][j]
__global__ void setup1(
    const float* __restrict__ iWq, const float* __restrict__ iWk, const float* __restrict__ iWv,
    const float* __restrict__ oWq, const float* __restrict__ oWk, const float* __restrict__ oWv,
    const float* __restrict__ i_in_w, const float* __restrict__ o_in_w,
    const float* __restrict__ f_in_w, const float* __restrict__ i_out_w,
    const float* __restrict__ o_out_w,
    const float* __restrict__ f_in_b,
    const float* __restrict__ i_out_b, const float* __restrict__ o_out_b)
{
    __shared__ float col[E];
    int m = blockIdx.y, r = blockIdx.x, j = threadIdx.x;
    if (m < 6) {
        const float* W = (m == 0) ? iWq : (m == 1) ? iWk : (m == 2) ? iWv
                       : (m == 3) ? oWq : (m == 4) ? oWk : oWv;
        const float* inw = ((m < 3) ? i_in_w : o_in_w) + (size_t)(m % 3) * E * E;
        col[j] = W[r * E + j];
        __syncthreads();
        float s = 0.f;
        #pragma unroll 8
        for (int tt = 0; tt < E; tt++) s += col[tt] * inw[j * E + tt];
        g_cproj[(size_t)m * E * E + r * E + j] = s;
    } else if (m < 12) {
        int mf = m - 6;
        int f = mf >> 1;
        const float* ow = (mf & 1) ? o_out_w : i_out_w;
        col[j] = ow[j * E + r];
        __syncthreads();
        float s = 0.f;
        #pragma unroll 8
        for (int c = 0; c < E; c++) s += col[c] * f_in_w[(f * E + j) * E + c];
        g_mfin[(size_t)mf * E * E + r * E + j] = s;
    } else {
        if (r < 6) {
            int f = r >> 1;
            const float* ob = (r & 1) ? o_out_b : i_out_b;
            float s = f_in_b[f * E + j];
            #pragma unroll 8
            for (int c = 0; c < E; c++) s += ob[c] * f_in_w[(f * E + j) * E + c];
            g_bfin[r * E + j] = s;
        }
    }
}

// ---------------- setup2: fp16 k-permuted conversion of all 12 matrices + bv ----
// y 0..3:   wh[y][n][perm k]   = mfin[y][k][n]
// y 4..5:   wh[y][n][perm k]   = sum_j mfin[y][k][j] * f_out_w[n][j]   (f_out_w fold)
// y 6..11:  wh[y][n][perm k]   = cproj[y-6][k][n]
// y == 12 (x<2): bv[x][t] = bfin[4+x] @ f_out_w[t] + f_out_b[t]
__global__ void setup2(const float* __restrict__ f_out_w, const float* __restrict__ f_out_b)
{
    __shared__ float s_fw[E];
    int y = blockIdx.y, n = blockIdx.x, k = threadIdx.x;
    if (y < 4) {
        g_wh[(size_t)y * E * E + n * E + (k >> 4) * 16 + kperm(k & 15)] =
            __float2half(g_mfin[(size_t)y * E * E + k * E + n]);
    } else if (y < 6) {
        s_fw[k] = f_out_w[n * E + k];
        __syncthreads();
        const float* mrow = g_mfin + (size_t)y * E * E + k * E;
        float s = 0.f;
        #pragma unroll 8
        for (int j = 0; j < E; j++) s += mrow[j] * s_fw[j];
        g_wh[(size_t)y * E * E + n * E + (k >> 4) * 16 + kperm(k & 15)] = __float2half(s);
    } else if (y < 12) {
        g_wh[(size_t)y * E * E + n * E + (k >> 4) * 16 + kperm(k & 15)] =
            __float2half(g_cproj[(size_t)(y - 6) * E * E + k * E + n]);
    } else {
        if (n < 2) {
            float s = f_out_b[k];
            const float* bf = g_bfin + (4 + n) * E;
            #pragma unroll 8
            for (int j = 0; j < E; j++) s += bf[j] * f_out_w[k * E + j];
            g_bv[n * E + k] = s;
        }
    }
}

// ---------------- 128x160 GEMM K=160, fp32, ELU out (K6) -------------
template<int TRANSB, int MODE>
__global__ __launch_bounds__(256, 1) void gemm128(
    const float* __restrict__ A, const float* __restrict__ Bm,
    const float* __restrict__ bias, float* __restrict__ Out)
{
    extern __shared__ float sm[];
    float* As = sm;
    float* Bs = sm + 128 * E;
    const int t = threadIdx.x;
    const size_t rowBase = (size_t)blockIdx.x * 128;

    const float4* Ag = reinterpret_cast<const float4*>(A + rowBase * E);
    float4* As4 = reinterpret_cast<float4*>(As);
    #pragma unroll
    for (int i = 0; i < 20; i++) As4[t + 256 * i] = Ag[t + 256 * i];

    if (TRANSB == 0) {
        #pragma unroll 4
        for (int i = 0; i < 100; i++) {
            int idx = t + 256 * i;
            int k = idx / E, j = idx - k * E;
            Bs[k * BSTR + j] = Bm[idx];
        }
    } else {
        #pragma unroll 4
        for (int i = 0; i < 100; i++) {
            int idx = t + 256 * i;
            int j = idx / E, k = idx - j * E;
            Bs[k * BSTR + j] = Bm[idx];
        }
    }
    __syncthreads();

    const int tx = t & 15, ty = t >> 4;
    unsigned long long acc[8][5];
    const unsigned long long z = pack2(0.f, 0.f);
    #pragma unroll
    for (int i = 0; i < 8; i++)
        #pragma unroll
        for (int u = 0; u < 5; u++) acc[i][u] = z;

    const float* Ath = As + ty * (8 * E);
    #pragma unroll 2
    for (int k = 0; k < E; k++) {
        unsigned long long b2[5];
        const unsigned long long* bp =
            reinterpret_cast<const unsigned long long*>(Bs + k * BSTR + tx * 10);
        #pragma unroll
        for (int u = 0; u < 5; u++) b2[u] = bp[u];
        #pragma unroll
        for (int i = 0; i < 8; i++) {
            float a = Ath[i * E + k];
            unsigned long long a2 = pack2(a, a);
            #pragma unroll
            for (int u = 0; u < 5; u++) acc[i][u] = fma2(a2, b2[u], acc[i][u]);
        }
    }

    float bcol[10];
    #pragma unroll
    for (int u = 0; u < 10; u++) bcol[u] = bias[tx * 10 + u];

    #pragma unroll
    for (int i = 0; i < 8; i++) {
        size_t ro = (rowBase + ty * 8 + i) * E + tx * 10;
        #pragma unroll
        for (int u = 0; u < 5; u++) {
            float2 v = unpack2(acc[i][u]);
            v.x += bcol[2 * u];
            v.y += bcol[2 * u + 1];
            if (MODE == 1) {
                v.x = v.x > 0.f ? v.x : expm1f(v.x);
                v.y = v.y > 0.f ? v.y : expm1f(v.y);
            }
            *reinterpret_cast<float2*>(Out + ro + 2 * u) = v;
        }
    }
}

// ---------------- K2: tensor-core merged projection of X (6 matrices) ----------
// A tile = 128 rows of X (fp32 -> fp16 on load); 6 passes over cproj-wh mats 6..11.
__global__ __launch_bounds__(256, 2) void gemm6_mma(
    const float* __restrict__ X,
    const float* __restrict__ i_in_b, const float* __restrict__ o_in_b)
{
    extern __shared__ uint32_t smw[];
    uint32_t* Aw = smw;                 // 128*84 words
    uint32_t* Bw = smw + 128 * 84;      // 160*84 words
    const int t = threadIdx.x;
    const size_t rowBase = (size_t)blockIdx.x * 128;

    // load A tile: fp32 -> fp16, k-permuted chunks of 8
    {
        const float4* Xg = reinterpret_cast<const float4*>(X + rowBase * E);
        #pragma unroll
        for (int s = 0; s < 10; s++) {
            int idx = t + 256 * s;
            int row = idx / 20, c = idx - row * 20;
            float4 x0 = Xg[idx * 2], x1 = Xg[idx * 2 + 1];
            uint32_t* d = Aw + row * 84 + (c >> 1) * 8 + (c & 1);
            d[0] = H2F(x0.x, x0.y);
            d[2] = H2F(x0.z, x0.w);
            d[4] = H2F(x1.x, x1.y);
            d[6] = H2F(x1.z, x1.w);
        }
    }

    const int lane = t & 31, w = t >> 5;
    const int rb = (w >> 1) * 32;
    const int cb = (w & 1) * 80;
    const int g = lane >> 2, q = lane & 3;

    const uint32_t* A0 = Aw + (rb + g) * 84 + q * 2;
    const uint32_t* B0 = Bw + (cb + g) * 84 + q * 2;

    for (int p = 0; p < 6; p++) {
        __syncthreads();
        {
            const uint4* Bg = reinterpret_cast<const uint4*>(g_wh + (size_t)(6 + p) * E * E);
            #pragma unroll
            for (int s = 0; s < 13; s++) {
                int idx = t + 256 * s;
                if (idx < 3200) {
                    int n = idx / 20, c = idx - n * 20;
                    *reinterpret_cast<uint4*>(Bw + n * 84 + c * 4) = Bg[idx];
                }
            }
        }
        __syncthreads();

        float acc[2][10][4];
        #pragma unroll
        for (int h2 = 0; h2 < 2; h2++)
            #pragma unroll
            for (int j = 0; j < 10; j++)
                #pragma unroll
                for (int u = 0; u < 4; u++) acc[h2][j][u] = 0.f;

        #pragma unroll
        for (int ks = 0; ks < 10; ks++) {
            uint2 aA0 = *reinterpret_cast<const uint2*>(A0 + ks * 8);
            uint2 aB0 = *reinterpret_cast<const uint2*>(A0 + 8 * 84 + ks * 8);
            uint2 aA1 = *reinterpret_cast<const uint2*>(A0 + 16 * 84 + ks * 8);
            uint2 aB1 = *reinterpret_cast<const uint2*>(A0 + 24 * 84 + ks * 8);
            #pragma unroll
            for (int j = 0; j < 10; j++) {
                uint2 bb = *reinterpret_cast<const uint2*>(B0 + (j * 8) * 84 + ks * 8);
                mma16816(acc[0][j], aA0.x, aB0.x, aA0.y, aB0.y, bb.x, bb.y);
                mma16816(acc[1][j], aA1.x, aB1.x, aA1.y, aB1.y, bb.x, bb.y);
            }
        }

        const float* bias = (p < 3) ? (i_in_b + p * E) : (o_in_b + (p - 3) * E);
        __half* Outg = g_px + (size_t)p * BN * E + rowBase * E;
        __syncthreads();
        __half* stage = reinterpret_cast<__half*>(Bw);
        #pragma unroll
        for (int j = 0; j < 10; j++) {
            int col = cb + j * 8 + q * 2;
            float b0f = bias[col], b1f = bias[col + 1];
            #pragma unroll
            for (int h2 = 0; h2 < 2; h2++) {
                int row = rb + h2 * 16 + g;
                *reinterpret_cast<__half2*>(stage + row * 160 + col) =
                    __floats2half2_rn(acc[h2][j][0] + b0f, acc[h2][j][1] + b1f);
                *reinterpret_cast<__half2*>(stage + (row + 8) * 160 + col) =
                    __floats2half2_rn(acc[h2][j][2] + b0f, acc[h2][j][3] + b1f);
            }
        }
        __syncthreads();
        #pragma unroll
        for (int s = 0; s < 10; s++) {
            int idx = t + 256 * s;
            reinterpret_cast<uint4*>(Outg)[idx] =
                reinterpret_cast<const uint4*>(stage)[idx];
        }
    }
}

// ---------------- K4: tensor-core fused final projections ---------
__global__ __launch_bounds__(256, 2) void gemm3_mma()
{
    extern __shared__ uint32_t smw[];
    uint32_t* Aw = smw;                 // 128*84 words
    uint32_t* Bw = smw + 128 * 84;      // 160*84 words
    const int t = threadIdx.x;
    const int half = blockIdx.x >> 12;
    const size_t rowBase = (size_t)blockIdx.x * 128;

    {
        const uint4* Ag = reinterpret_cast<const uint4*>(g_obuf + rowBase * E);
        #pragma unroll
        for (int s = 0; s < 10; s++) {
            int idx = t + 256 * s;
            int row = idx / 20, c = idx - row * 20;
            uint4 v = Ag[idx];
            uint32_t* d = Aw + row * 84 + (c >> 1) * 8 + (c & 1);
            d[0] = v.x; d[2] = v.y; d[4] = v.z; d[6] = v.w;
        }
    }

    const int lane = t & 31, w = t >> 5;
    const int rb = (w >> 1) * 32;
    const int cb = (w & 1) * 80;
    const int g = lane >> 2, q = lane & 3;

    const uint32_t* A0 = Aw + (rb + g) * 84 + q * 2;
    const uint32_t* B0 = Bw + (cb + g) * 84 + q * 2;

    for (int p = 0; p < 3; p++) {
        const int mat = 2 * p + half;
        __syncthreads();
        {
            const uint4* Bg = reinterpret_cast<const uint4*>(g_wh + (size_t)mat * E * E);
            #pragma unroll
            for (int s = 0; s < 13; s++) {
                int idx = t + 256 * s;
                if (idx < 3200) {
                    int n = idx / 20, c = idx - n * 20;
                    *reinterpret_cast<uint4*>(Bw + n * 84 + c * 4) = Bg[idx];
                }
            }
        }
        __syncthreads();

        float acc[2][10][4];
        #pragma unroll
        for (int h2 = 0; h2 < 2; h2++)
            #pragma unroll
            for (int j = 0; j < 10; j++)
                #pragma unroll
                for (int u = 0; u < 4; u++) acc[h2][j][u] = 0.f;

        #pragma unroll
        for (int ks = 0; ks < 10; ks++) {
            uint2 aA0 = *reinterpret_cast<const uint2*>(A0 + ks * 8);
            uint2 aB0 = *reinterpret_cast<const uint2*>(A0 + 8 * 84 + ks * 8);
            uint2 aA1 = *reinterpret_cast<const uint2*>(A0 + 16 * 84 + ks * 8);
            uint2 aB1 = *reinterpret_cast<const uint2*>(A0 + 24 * 84 + ks * 8);
            #pragma unroll
            for (int j = 0; j < 10; j++) {
                uint2 bb = *reinterpret_cast<const uint2*>(B0 + (j * 8) * 84 + ks * 8);
                mma16816(acc[0][j], aA0.x, aB0.x, aA0.y, aB0.y, bb.x, bb.y);
                mma16816(acc[1][j], aA1.x, aB1.x, aA1.y, aB1.y, bb.x, bb.y);
            }
        }

        const float* bias = (p < 2) ? (g_bfin + (2 * p + half) * E)
                                    : (g_bv + half * E);
        __half* Outg = ((p == 0) ? g_fq : (p == 1) ? g_fk : g_fv) + rowBase * E;
        __syncthreads();
        __half* stage = reinterpret_cast<__half*>(Bw);
        #pragma unroll
        for (int j = 0; j < 10; j++) {
            int col = cb + j * 8 + q * 2;
            float b0f = bias[col], b1f = bias[col + 1];
            #pragma unroll
            for (int h2 = 0; h2 < 2; h2++) {
                int row = rb + h2 * 16 + g;
                *reinterpret_cast<__half2*>(stage + row * 160 + col) =
                    __floats2half2_rn(acc[h2][j][0] + b0f, acc[h2][j][1] + b1f);
                *reinterpret_cast<__half2*>(stage + (row + 8) * 160 + col) =
                    __floats2half2_rn(acc[h2][j][2] + b0f, acc[h2][j][3] + b1f);
            }
        }
        __syncthreads();
        #pragma unroll
        for (int s = 0; s < 10; s++) {
            int idx = t + 256 * s;
            reinterpret_cast<uint4*>(Outg)[idx] =
                reinterpret_cast<const uint4*>(stage)[idx];
        }
    }
}

// ---------------- K3: inner attention via mma, warp per (half, head) ----------
__global__ __launch_bounds__(320) void inner_attn_mma(const int* __restrict__ in_idx,
                                                      const int* __restrict__ out_idx)
{
    __shared__ __half tile[96][164];   // rows: hh*48 + mat*16 + l  (mat: q,k,v)
    __shared__ int idxs[2][16];
    const int n = blockIdx.x, b = blockIdx.y;
    const int t = threadIdx.x;
    const size_t tok = (size_t)b * NN + n;
    const size_t base = (size_t)b * NN;

    if (t < 32) {
        int hh = t >> 4, i = t & 15;
        const int* ia = hh ? out_idx : in_idx;
        idxs[hh][i] = (i == 0) ? n : ia[tok * DINN + i - 1];
    }
    __syncthreads();

    #pragma unroll
    for (int it = 0; it < 6; it++) {
        int task = t + 320 * it;
        int r = task / 20, seg = task - r * 20;
        int hh = r / 48, sub = r - hh * 48;
        int mat = sub >> 4, l = sub & 15;
        const __half* src = g_px +
            ((size_t)(hh * 3 + mat) * BN + base + idxs[hh][l]) * E + seg * 8;
        uint4 v = *reinterpret_cast<const uint4*>(src);
        uint2* d = reinterpret_cast<uint2*>(&tile[r][seg * 8]);
        d[0] = make_uint2(v.x, v.y);
        d[1] = make_uint2(v.z, v.w);
    }
    __syncthreads();

    const int w = t >> 5, lane = t & 31;
    const int g = lane >> 2, q = lane & 3;
    const int hh = w / 5, h = w - hh * 5;
    const int qr = hh * 48, kr = qr + 16, vr = qr + 32;
    const int koff = h * 32;

    float s0[4] = {0.f, 0.f, 0.f, 0.f}, s1[4] = {0.f, 0.f, 0.f, 0.f};
    #pragma unroll
    for (int kc = 0; kc < 2; kc++) {
        int ko = koff + kc * 16 + 2 * q;
        uint32_t a0 = U32(&tile[qr + g][ko]);
        uint32_t a1 = U32(&tile[qr + g + 8][ko]);
        uint32_t a2 = U32(&tile[qr + g][ko + 8]);
        uint32_t a3 = U32(&tile[qr + g + 8][ko + 8]);
        uint32_t b0 = U32(&tile[kr + g][ko]);
        uint32_t b1 = U32(&tile[kr + g][ko + 8]);
        mma16816(s0, a0, a1, a2, a3, b0, b1);
        uint32_t b2 = U32(&tile[kr + 8 + g][ko]);
        uint32_t b3 = U32(&tile[kr + 8 + g][ko + 8]);
        mma16816(s1, a0, a1, a2, a3, b2, b3);
    }
    const float scale = 0.17677669529663687f;  // 1/sqrt(32)
    #pragma unroll
    for (int u = 0; u < 4; u++) { s0[u] *= scale; s1[u] *= scale; }

    float mx0 = fmaxf(fmaxf(s0[0], s0[1]), fmaxf(s1[0], s1[1]));
    float mx1 = fmaxf(fmaxf(s0[2], s0[3]), fmaxf(s1[2], s1[3]));
    mx0 = fmaxf(mx0, __shfl_xor_sync(0xffffffffu, mx0, 1));
    mx0 = fmaxf(mx0, __shfl_xor_sync(0xffffffffu, mx0, 2));
    mx1 = fmaxf(mx1, __shfl_xor_sync(0xffffffffu, mx1, 1));
    mx1 = fmaxf(mx1, __shfl_xor_sync(0xffffffffu, mx1, 2));
    float e00 = __expf(s0[0] - mx0), e01 = __expf(s0[1] - mx0);
    float e02 = __expf(s1[0] - mx0), e03 = __expf(s1[1] - mx0);
    float e10 = __expf(s0[2] - mx1), e11 = __expf(s0[3] - mx1);
    float e12 = __expf(s1[2] - mx1), e13 = __expf(s1[3] - mx1);
    float sum0 = e00 + e01 + e02 + e03;
    float sum1 = e10 + e11 + e12 + e13;
    sum0 += __shfl_xor_sync(0xffffffffu, sum0, 1);
    sum0 += __shfl_xor_sync(0xffffffffu, sum0, 2);
    sum1 += __shfl_xor_sync(0xffffffffu, sum1, 1);
    sum1 += __shfl_xor_sync(0xffffffffu, sum1, 2);
    float inv0 = 1.f / sum0, inv1 = 1.f / sum1;

    uint32_t pa0 = H2F(e00 * inv0, e01 * inv0);
    uint32_t pa1 = H2F(e10 * inv1, e11 * inv1);
    uint32_t pa2 = H2F(e02 * inv0, e03 * inv0);
    uint32_t pa3 = H2F(e12 * inv1, e13 * inv1);

    __half* ob = g_obuf + ((size_t)hh * BN + tok) * (16 * E) + koff;
    #pragma unroll
    for (int nt = 0; nt < 4; nt++) {
        int vc = koff + nt * 8 + g;
        uint32_t b0 = H2(tile[vr + 2 * q][vc], tile[vr + 2 * q + 1][vc]);
        uint32_t b1 = H2(tile[vr + 2 * q + 8][vc], tile[vr + 2 * q + 9][vc]);
        float o[4] = {0.f, 0.f, 0.f, 0.f};
        mma16816(o, pa0, pa1, pa2, pa3, b0, b1);
        *reinterpret_cast<__half2*>(ob + (size_t)g * E + nt * 8 + 2 * q) =
            __floats2half2_rn(o[0], o[1]);
        *reinterpret_cast<__half2*>(ob + (size_t)(g + 8) * E + nt * 8 + 2 * q) =
            __floats2half2_rn(o[2], o[3]);
    }
}

// ---------------- K5: final attention via mma + folded out-proj + max pool ----
__global__ __launch_bounds__(256) void final_attn_mma()
{
    __shared__ __half tile[96][164];   // rows 0-31 q, 32-63 k, 64-95 v
    __shared__ float sc[32][34];
    __shared__ __half ps[32][34];
    __shared__ float pb[2][160];
    const size_t tok = blockIdx.x;
    const int t = threadIdx.x;

    #pragma unroll
    for (int it = 0; it < 8; it++) {
        int task = t + 256 * it;
        if (task < 1920) {
            int r = task / 20, seg = task - r * 20;
            int mat = r >> 5, rr = r & 31, hh = rr >> 4, l = rr & 15;
            const __half* src = ((mat == 0) ? g_fq : (mat == 1) ? g_fk : g_fv)
                + (size_t)hh * HALF_ELEMS + tok * 2560 + l * 160 + seg * 8;
            uint4 v = *reinterpret_cast<const uint4*>(src);
            uint2* d = reinterpret_cast<uint2*>(&tile[r][seg * 8]);
            d[0] = make_uint2(v.x, v.y);
            d[1] = make_uint2(v.z, v.w);
        }
    }
    __syncthreads();

    const int w = t >> 5, lane = t & 31, g = lane >> 2, q = lane & 3;

    {
        const int mt = w >> 2, nt = w & 3;
        const int qr = mt * 16, kr = 32 + nt * 8;
        float c[4] = {0.f, 0.f, 0.f, 0.f};
        #pragma unroll
        for (int kc = 0; kc < 10; kc++) {
            int ko = kc * 16 + 2 * q;
            uint32_t a0 = U32(&tile[qr + g][ko]);
            uint32_t a1 = U32(&tile[qr + g + 8][ko]);
            uint32_t a2 = U32(&tile[qr + g][ko + 8]);
            uint32_t a3 = U32(&tile[qr + g + 8][ko + 8]);
            uint32_t b0 = U32(&tile[kr + g][ko]);
            uint32_t b1 = U32(&tile[kr + g][ko + 8]);
            mma16816(c, a0, a1, a2, a3, b0, b1);
        }
        *reinterpret_cast<float2*>(&sc[qr + g][nt * 8 + 2 * q]) = make_float2(c[0], c[1]);
        *reinterpret_cast<float2*>(&sc[qr + g + 8][nt * 8 + 2 * q]) = make_float2(c[2], c[3]);
    }
    __syncthreads();

    if (t < 32) {
        const float scale = 0.07905694150420949f;  // 1/sqrt(160)
        float v[32];
        float mx = -3.4e38f;
        #pragma unroll
        for (int m = 0; m < 32; m++) { v[m] = sc[t][m] * scale; mx = fmaxf(mx, v[m]); }
        float sum = 0.f;
        #pragma unroll
        for (int m = 0; m < 32; m++) { v[m] = __expf(v[m] - mx); sum += v[m]; }
        float inv = 1.f / sum;
        #pragma unroll
        for (int m = 0; m < 16; m++)
            *reinterpret_cast<__half2*>(&ps[t][2 * m]) =
                __floats2half2_rn(v[2 * m] * inv, v[2 * m + 1] * inv);
    }
    __syncthreads();

    {
        const int mt = w >> 2, nb = w & 3;
        const int mr = mt * 16;
        uint32_t a[2][4];
        #pragma unroll
        for (int kc = 0; kc < 2; kc++) {
            int ko = kc * 16 + 2 * q;
            a[kc][0] = U32(&ps[mr + g][ko]);
            a[kc][1] = U32(&ps[mr + g + 8][ko]);
            a[kc][2] = U32(&ps[mr + g][ko + 8]);
            a[kc][3] = U32(&ps[mr + g + 8][ko + 8]);
        }
        #pragma unroll
        for (int j = 0; j < 5; j++) {
            int nt = nb + 4 * j;
            int vc = nt * 8 + g;
            float o[4] = {0.f, 0.f, 0.f, 0.f};
            #pragma unroll
            for (int kc = 0; kc < 2; kc++) {
                int vrow = 64 + kc * 16;
                uint32_t b0 = H2(tile[vrow + 2 * q][vc], tile[vrow + 2 * q + 1][vc]);
                uint32_t b1 = H2(tile[vrow + 2 * q + 8][vc], tile[vrow + 2 * q + 9][vc]);
                mma16816(o, a[kc][0], a[kc][1], a[kc][2], a[kc][3], b0, b1);
            }
            float m0 = fmaxf(o[0], o[2]);
            float m1 = fmaxf(o[1], o[3]);
            #pragma unroll
            for (int s = 4; s < 32; s <<= 1) {
                m0 = fmaxf(m0, __shfl_xor_sync(0xffffffffu, m0, s));
                m1 = fmaxf(m1, __shfl_xor_sync(0xffffffffu, m1, s));
            }
            if (g == 0)
                *reinterpret_cast<float2*>(&pb[mt][nt * 8 + 2 * q]) = make_float2(m0, m1);
        }
    }
    __syncthreads();

    if (t < 160)
        g_pooled[tok * E + t] = fmaxf(pb[0][t], pb[1][t]);
}

// ---------------- host orchestration ----------------
extern "C" void kernel_launch(void* const* d_in, const int* in_sizes, int n_in,
                              void* d_out, int out_size)
{
    const float* X       = (const float*)d_in[0];
    const int*   in_idx  = (const int*)  d_in[1];
    const int*   out_idx = (const int*)  d_in[2];
    const float* iWq     = (const float*)d_in[3];
    const float* iWk     = (const float*)d_in[4];
    const float* iWv     = (const float*)d_in[5];
    const float* i_in_w  = (const float*)d_in[6];
    const float* i_in_b  = (const float*)d_in[7];
    const float* i_out_w = (const float*)d_in[8];
    const float* i_out_b = (const float*)d_in[9];
    const float* oWq     = (const float*)d_in[10];
    const float* oWk     = (const float*)d_in[11];
    const float* oWv     = (const float*)d_in[12];
    const float* o_in_w  = (const float*)d_in[13];
    const float* o_in_b  = (const float*)d_in[14];
    const float* o_out_w = (const float*)d_in[15];
    const float* o_out_b = (const float*)d_in[16];
    const float* f_in_w  = (const float*)d_in[17];
    const float* f_in_b  = (const float*)d_in[18];
    const float* f_out_w = (const float*)d_in[19];
    const float* f_out_b = (const float*)d_in[20];
    const float* lin_w   = (const float*)d_in[21];
    const float* lin_b   = (const float*)d_in[22];
    float* out = (float*)d_out;

    float* pooled;
    cudaGetSymbolAddress((void**)&pooled, g_pooled);

    const size_t smem_g   = (size_t)(128 * E + E * BSTR) * sizeof(float);   // 185,600 B
    const size_t smem_mma = (size_t)(128 * 84 + 160 * 84) * 4;              //  96,768 B
    cudaFuncSetAttribute(gemm128<1, 1>, cudaFuncAttributeMaxDynamicSharedMemorySize, (int)smem_g);
    cudaFuncSetAttribute(gemm3_mma,     cudaFuncAttributeMaxDynamicSharedMemorySize, (int)smem_mma);
    cudaFuncSetAttribute(gemm6_mma,     cudaFuncAttributeMaxDynamicSharedMemorySize, (int)smem_mma);

    // K1: fused weights + biases (2 launches)
    setup1<<<dim3(E, 13), E>>>(iWq, iWk, iWv, oWq, oWk, oWv,
                               i_in_w, o_in_w, f_in_w, i_out_w, o_out_w,
                               f_in_b, i_out_b, o_out_b);
    setup2<<<dim3(E, 13), E>>>(f_out_w, f_out_b);

    // K2: merged tensor-core projection of X -> px (fp16), one launch
    gemm6_mma<<<BN / 128, 256, smem_mma>>>(X, i_in_b, o_in_b);

    // K3: inner attentions via tensor cores (writes g_obuf fp16, half-major)
    inner_attn_mma<<<dim3(NN, BB), 320>>>(in_idx, out_idx);

    // K4: tensor-core fused final projections -> qf/kf/vf' (fp16)
    gemm3_mma<<<8192, 256, smem_mma>>>();

    // K5: final attention (mma) + folded out-projection + max pool -> pooled
    final_attn_mma<<<BN, 256>>>();

    // K6: pooled @ lin_w.T + lin_b, ELU -> output
    gemm128<1, 1><<<BN / 128, 256, smem_g>>>(pooled, lin_w, lin_b, out);

    (void)in_sizes; (void)n_in; (void)out_size;
}

// round 10
// speedup vs baseline: 8.0888x; 1.0654x over previous
#include <cuda_runtime.h>
#include <cuda_fp16.h>
#include <cstdint>
#include <cstdio>

// Problem constants
#define E   160
#define BB  8
#define NN  4096
#define BN  (BB*NN)          // 32768 tokens
#define DINN 15
#define BSTR 162             // smem B row stride for gemm128 (floats)

constexpr size_t HALF_ELEMS = (size_t)BN * 16 * E;   // elements per half

// ---------------- static device scratch (allocation-free rule) ----------------
__device__ float g_cproj[6 * E * E];       // fused inner projection matrices [k][j]
__device__ float g_mfin [6 * E * E];       // fused final projection matrices [k][j]
__device__ float g_bfin [6 * E];           // fused final biases
__device__ float g_bv   [2 * E];           // v-bias with f_out_w folded in
__device__ __half g_wh  [12 * E * E];      // fp16 weights [n][k] k-permuted: 0-3 qf/kf, 4-5 vf', 6-11 cproj
__device__ __half g_px  [6ull * BN * E];               // projected X, fp16
__device__ __half g_obuf[2ull * BN * 16 * E];          // inner attn out (half-major), fp16
__device__ __half g_fq  [2ull * BN * 16 * E];
__device__ __half g_fk  [2ull * BN * 16 * E];
__device__ __half g_fv  [2ull * BN * 16 * E];          // v' (f_out_w folded)
__device__ float g_pooled[(size_t)BN * E];

// ---------------- f32x2 helpers ----------------
__device__ __forceinline__ unsigned long long fma2(unsigned long long a,
                                                   unsigned long long b,
                                                   unsigned long long c) {
    unsigned long long d;
    asm("fma.rn.f32x2 %0, %1, %2, %3;" : "=l"(d) : "l"(a), "l"(b), "l"(c));
    return d;
}
__device__ __forceinline__ unsigned long long pack2(float x, float y) {
    unsigned long long r;
    asm("mov.b64 %0, {%1,%2};" : "=l"(r) : "f"(x), "f"(y));
    return r;
}
__device__ __forceinline__ float2 unpack2(unsigned long long v) {
    float2 f;
    asm("mov.b64 {%0,%1}, %2;" : "=f"(f.x), "=f"(f.y) : "l"(v));
    return f;
}

// ---------------- mma.sync m16n8k16 fp16->fp32 (validated frag ordering) -------
__device__ __forceinline__ void mma16816(float* c, uint32_t a0, uint32_t a1,
                                         uint32_t a2, uint32_t a3,
                                         uint32_t b0, uint32_t b1) {
    asm volatile(
        "mma.sync.aligned.m16n8k16.row.col.f32.f16.f16.f32 "
        "{%0,%1,%2,%3}, {%4,%5,%6,%7}, {%8,%9}, {%0,%1,%2,%3};\n"
        : "+f"(c[0]), "+f"(c[1]), "+f"(c[2]), "+f"(c[3])
        : "r"(a0), "r"(a1), "r"(a2), "r"(a3), "r"(b0), "r"(b1));
}

// ---------------- ldmatrix helpers ----------------
__device__ __forceinline__ uint32_t cvta_smem(const void* p) {
    return (uint32_t)__cvta_generic_to_shared(p);
}
__device__ __forceinline__ void ldsm_x4(uint32_t& r0, uint32_t& r1, uint32_t& r2,
                                        uint32_t& r3, uint32_t a) {
    asm volatile("ldmatrix.sync.aligned.m8n8.x4.shared.b16 {%0,%1,%2,%3}, [%4];"
                 : "=r"(r0), "=r"(r1), "=r"(r2), "=r"(r3) : "r"(a));
}
__device__ __forceinline__ void ldsm_x2(uint32_t& r0, uint32_t& r1, uint32_t a) {
    asm volatile("ldmatrix.sync.aligned.m8n8.x2.shared.b16 {%0,%1}, [%2];"
                 : "=r"(r0), "=r"(r1) : "r"(a));
}
__device__ __forceinline__ void ldsm_x2t(uint32_t& r0, uint32_t& r1, uint32_t a) {
    asm volatile("ldmatrix.sync.aligned.m8n8.x2.trans.shared.b16 {%0,%1}, [%2];"
                 : "=r"(r0), "=r"(r1) : "r"(a));
}

__device__ __forceinline__ uint32_t H2(__half a, __half b) {
    __half2 h = __halves2half2(a, b);
    return *reinterpret_cast<uint32_t*>(&h);
}
__device__ __forceinline__ uint32_t H2F(float a, float b) {
    __half2 h = __floats2half2_rn(a, b);
    return *reinterpret_cast<uint32_t*>(&h);
}

// k-permutation within a 16-k group so mma k-pairs are contiguous words
__device__ __forceinline__ int kperm(int l) {
    return (l < 8) ? (((l >> 1) << 2) + (l & 1))
                   : ((((l - 8) >> 1) << 2) + 2 + (l & 1));
}

// ---------------- setup1: all fused fp32 matrices + fused biases ----------------
__global__ void setup1(
    const float* __restrict__ iWq, const float* __restrict__ iWk, const float* __restrict__ iWv,
    const float* __restrict__ oWq, const float* __restrict__ oWk, const float* __restrict__ oWv,
    const float* __restrict__ i_in_w, const float* __restrict__ o_in_w,
    const float* __restrict__ f_in_w, const float* __restrict__ i_out_w,
    const float* __restrict__ o_out_w,
    const float* __restrict__ f_in_b,
    const float* __restrict__ i_out_b, const float* __restrict__ o_out_b)
{
    __shared__ float col[E];
    int m = blockIdx.y, r = blockIdx.x, j = threadIdx.x;
    if (m < 6) {
        const float* W = (m == 0) ? iWq : (m == 1) ? iWk : (m == 2) ? iWv
                       : (m == 3) ? oWq : (m == 4) ? oWk : oWv;
        const float* inw = ((m < 3) ? i_in_w : o_in_w) + (size_t)(m % 3) * E * E;
        col[j] = W[r * E + j];
        __syncthreads();
        float s = 0.f;
        #pragma unroll 8
        for (int tt = 0; tt < E; tt++) s += col[tt] * inw[j * E + tt];
        g_cproj[(size_t)m * E * E + r * E + j] = s;
    } else if (m < 12) {
        int mf = m - 6;
        int f = mf >> 1;
        const float* ow = (mf & 1) ? o_out_w : i_out_w;
        col[j] = ow[j * E + r];
        __syncthreads();
        float s = 0.f;
        #pragma unroll 8
        for (int c = 0; c < E; c++) s += col[c] * f_in_w[(f * E + j) * E + c];
        g_mfin[(size_t)mf * E * E + r * E + j] = s;
    } else {
        if (r < 6) {
            int f = r >> 1;
            const float* ob = (r & 1) ? o_out_b : i_out_b;
            float s = f_in_b[f * E + j];
            #pragma unroll 8
            for (int c = 0; c < E; c++) s += ob[c] * f_in_w[(f * E + j) * E + c];
            g_bfin[r * E + j] = s;
        }
    }
}

// ---------------- setup2: fp16 k-permuted conversion of all 12 matrices + bv ----
__global__ void setup2(const float* __restrict__ f_out_w, const float* __restrict__ f_out_b)
{
    __shared__ float s_fw[E];
    int y = blockIdx.y, n = blockIdx.x, k = threadIdx.x;
    if (y < 4) {
        g_wh[(size_t)y * E * E + n * E + (k >> 4) * 16 + kperm(k & 15)] =
            __float2half(g_mfin[(size_t)y * E * E + k * E + n]);
    } else if (y < 6) {
        s_fw[k] = f_out_w[n * E + k];
        __syncthreads();
        const float* mrow = g_mfin + (size_t)y * E * E + k * E;
        float s = 0.f;
        #pragma unroll 8
        for (int j = 0; j < E; j++) s += mrow[j] * s_fw[j];
        g_wh[(size_t)y * E * E + n * E + (k >> 4) * 16 + kperm(k & 15)] = __float2half(s);
    } else if (y < 12) {
        g_wh[(size_t)y * E * E + n * E + (k >> 4) * 16 + kperm(k & 15)] =
            __float2half(g_cproj[(size_t)(y - 6) * E * E + k * E + n]);
    } else {
        if (n < 2) {
            float s = f_out_b[k];
            const float* bf = g_bfin + (4 + n) * E;
            #pragma unroll 8
            for (int j = 0; j < E; j++) s += bf[j] * f_out_w[k * E + j];
            g_bv[n * E + k] = s;
        }
    }
}

// ---------------- 128x160 GEMM K=160, fp32, ELU out (K6) -------------
template<int TRANSB, int MODE>
__global__ __launch_bounds__(256, 1) void gemm128(
    const float* __restrict__ A, const float* __restrict__ Bm,
    const float* __restrict__ bias, float* __restrict__ Out)
{
    extern __shared__ float sm[];
    float* As = sm;
    float* Bs = sm + 128 * E;
    const int t = threadIdx.x;
    const size_t rowBase = (size_t)blockIdx.x * 128;

    const float4* Ag = reinterpret_cast<const float4*>(A + rowBase * E);
    float4* As4 = reinterpret_cast<float4*>(As);
    #pragma unroll
    for (int i = 0; i < 20; i++) As4[t + 256 * i] = Ag[t + 256 * i];

    if (TRANSB == 0) {
        #pragma unroll 4
        for (int i = 0; i < 100; i++) {
            int idx = t + 256 * i;
            int k = idx / E, j = idx - k * E;
            Bs[k * BSTR + j] = Bm[idx];
        }
    } else {
        #pragma unroll 4
        for (int i = 0; i < 100; i++) {
            int idx = t + 256 * i;
            int j = idx / E, k = idx - j * E;
            Bs[k * BSTR + j] = Bm[idx];
        }
    }
    __syncthreads();

    const int tx = t & 15, ty = t >> 4;
    unsigned long long acc[8][5];
    const unsigned long long z = pack2(0.f, 0.f);
    #pragma unroll
    for (int i = 0; i < 8; i++)
        #pragma unroll
        for (int u = 0; u < 5; u++) acc[i][u] = z;

    const float* Ath = As + ty * (8 * E);
    #pragma unroll 2
    for (int k = 0; k < E; k++) {
        unsigned long long b2[5];
        const unsigned long long* bp =
            reinterpret_cast<const unsigned long long*>(Bs + k * BSTR + tx * 10);
        #pragma unroll
        for (int u = 0; u < 5; u++) b2[u] = bp[u];
        #pragma unroll
        for (int i = 0; i < 8; i++) {
            float a = Ath[i * E + k];
            unsigned long long a2 = pack2(a, a);
            #pragma unroll
            for (int u = 0; u < 5; u++) acc[i][u] = fma2(a2, b2[u], acc[i][u]);
        }
    }

    float bcol[10];
    #pragma unroll
    for (int u = 0; u < 10; u++) bcol[u] = bias[tx * 10 + u];

    #pragma unroll
    for (int i = 0; i < 8; i++) {
        size_t ro = (rowBase + ty * 8 + i) * E + tx * 10;
        #pragma unroll
        for (int u = 0; u < 5; u++) {
            float2 v = unpack2(acc[i][u]);
            v.x += bcol[2 * u];
            v.y += bcol[2 * u + 1];
            if (MODE == 1) {
                v.x = v.x > 0.f ? v.x : expm1f(v.x);
                v.y = v.y > 0.f ? v.y : expm1f(v.y);
            }
            *reinterpret_cast<float2*>(Out + ro + 2 * u) = v;
        }
    }
}

// ---------------- K2: tensor-core merged projection of X (6 matrices) ----------
__global__ __launch_bounds__(256, 2) void gemm6_mma(
    const float* __restrict__ X,
    const float* __restrict__ i_in_b, const float* __restrict__ o_in_b)
{
    extern __shared__ uint32_t smw[];
    uint32_t* Aw = smw;                 // 128*84 words
    uint32_t* Bw = smw + 128 * 84;      // 160*84 words
    const int t = threadIdx.x;
    const size_t rowBase = (size_t)blockIdx.x * 128;

    {
        const float4* Xg = reinterpret_cast<const float4*>(X + rowBase * E);
        #pragma unroll
        for (int s = 0; s < 10; s++) {
            int idx = t + 256 * s;
            int row = idx / 20, c = idx - row * 20;
            float4 x0 = Xg[idx * 2], x1 = Xg[idx * 2 + 1];
            uint32_t* d = Aw + row * 84 + (c >> 1) * 8 + (c & 1);
            d[0] = H2F(x0.x, x0.y);
            d[2] = H2F(x0.z, x0.w);
            d[4] = H2F(x1.x, x1.y);
            d[6] = H2F(x1.z, x1.w);
        }
    }

    const int lane = t & 31, w = t >> 5;
    const int rb = (w >> 1) * 32;
    const int cb = (w & 1) * 80;
    const int g = lane >> 2, q = lane & 3;

    const uint32_t* A0 = Aw + (rb + g) * 84 + q * 2;
    const uint32_t* B0 = Bw + (cb + g) * 84 + q * 2;

    for (int p = 0; p < 6; p++) {
        __syncthreads();
        {
            const uint4* Bg = reinterpret_cast<const uint4*>(g_wh + (size_t)(6 + p) * E * E);
            #pragma unroll
            for (int s = 0; s < 13; s++) {
                int idx = t + 256 * s;
                if (idx < 3200) {
                    int n = idx / 20, c = idx - n * 20;
                    *reinterpret_cast<uint4*>(Bw + n * 84 + c * 4) = Bg[idx];
                }
            }
        }
        __syncthreads();

        float acc[2][10][4];
        #pragma unroll
        for (int h2 = 0; h2 < 2; h2++)
            #pragma unroll
            for (int j = 0; j < 10; j++)
                #pragma unroll
                for (int u = 0; u < 4; u++) acc[h2][j][u] = 0.f;

        #pragma unroll
        for (int ks = 0; ks < 10; ks++) {
            uint2 aA0 = *reinterpret_cast<const uint2*>(A0 + ks * 8);
            uint2 aB0 = *reinterpret_cast<const uint2*>(A0 + 8 * 84 + ks * 8);
            uint2 aA1 = *reinterpret_cast<const uint2*>(A0 + 16 * 84 + ks * 8);
            uint2 aB1 = *reinterpret_cast<const uint2*>(A0 + 24 * 84 + ks * 8);
            #pragma unroll
            for (int j = 0; j < 10; j++) {
                uint2 bb = *reinterpret_cast<const uint2*>(B0 + (j * 8) * 84 + ks * 8);
                mma16816(acc[0][j], aA0.x, aB0.x, aA0.y, aB0.y, bb.x, bb.y);
                mma16816(acc[1][j], aA1.x, aB1.x, aA1.y, aB1.y, bb.x, bb.y);
            }
        }

        const float* bias = (p < 3) ? (i_in_b + p * E) : (o_in_b + (p - 3) * E);
        __half* Outg = g_px + (size_t)p * BN * E + rowBase * E;
        __syncthreads();
        __half* stage = reinterpret_cast<__half*>(Bw);
        #pragma unroll
        for (int j = 0; j < 10; j++) {
            int col = cb + j * 8 + q * 2;
            float b0f = bias[col], b1f = bias[col + 1];
            #pragma unroll
            for (int h2 = 0; h2 < 2; h2++) {
                int row = rb + h2 * 16 + g;
                *reinterpret_cast<__half2*>(stage + row * 160 + col) =
                    __floats2half2_rn(acc[h2][j][0] + b0f, acc[h2][j][1] + b1f);
                *reinterpret_cast<__half2*>(stage + (row + 8) * 160 + col) =
                    __floats2half2_rn(acc[h2][j][2] + b0f, acc[h2][j][3] + b1f);
            }
        }
        __syncthreads();
        #pragma unroll
        for (int s = 0; s < 10; s++) {
            int idx = t + 256 * s;
            reinterpret_cast<uint4*>(Outg)[idx] =
                reinterpret_cast<const uint4*>(stage)[idx];
        }
    }
}

// ---------------- K4: tensor-core fused final projections ---------
__global__ __launch_bounds__(256, 2) void gemm3_mma()
{
    extern __shared__ uint32_t smw[];
    uint32_t* Aw = smw;                 // 128*84 words
    uint32_t* Bw = smw + 128 * 84;      // 160*84 words
    const int t = threadIdx.x;
    const int half = blockIdx.x >> 12;
    const size_t rowBase = (size_t)blockIdx.x * 128;

    {
        const uint4* Ag = reinterpret_cast<const uint4*>(g_obuf + rowBase * E);
        #pragma unroll
        for (int s = 0; s < 10; s++) {
            int idx = t + 256 * s;
            int row = idx / 20, c = idx - row * 20;
            uint4 v = Ag[idx];
            uint32_t* d = Aw + row * 84 + (c >> 1) * 8 + (c & 1);
            d[0] = v.x; d[2] = v.y; d[4] = v.z; d[6] = v.w;
        }
    }

    const int lane = t & 31, w = t >> 5;
    const int rb = (w >> 1) * 32;
    const int cb = (w & 1) * 80;
    const int g = lane >> 2, q = lane & 3;

    const uint32_t* A0 = Aw + (rb + g) * 84 + q * 2;
    const uint32_t* B0 = Bw + (cb + g) * 84 + q * 2;

    for (int p = 0; p < 3; p++) {
        const int mat = 2 * p + half;
        __syncthreads();
        {
            const uint4* Bg = reinterpret_cast<const uint4*>(g_wh + (size_t)mat * E * E);
            #pragma unroll
            for (int s = 0; s < 13; s++) {
                int idx = t + 256 * s;
                if (idx < 3200) {
                    int n = idx / 20, c = idx - n * 20;
                    *reinterpret_cast<uint4*>(Bw + n * 84 + c * 4) = Bg[idx];
                }
            }
        }
        __syncthreads();

        float acc[2][10][4];
        #pragma unroll
        for (int h2 = 0; h2 < 2; h2++)
            #pragma unroll
            for (int j = 0; j < 10; j++)
                #pragma unroll
                for (int u = 0; u < 4; u++) acc[h2][j][u] = 0.f;

        #pragma unroll
        for (int ks = 0; ks < 10; ks++) {
            uint2 aA0 = *reinterpret_cast<const uint2*>(A0 + ks * 8);
            uint2 aB0 = *reinterpret_cast<const uint2*>(A0 + 8 * 84 + ks * 8);
            uint2 aA1 = *reinterpret_cast<const uint2*>(A0 + 16 * 84 + ks * 8);
            uint2 aB1 = *reinterpret_cast<const uint2*>(A0 + 24 * 84 + ks * 8);
            #pragma unroll
            for (int j = 0; j < 10; j++) {
                uint2 bb = *reinterpret_cast<const uint2*>(B0 + (j * 8) * 84 + ks * 8);
                mma16816(acc[0][j], aA0.x, aB0.x, aA0.y, aB0.y, bb.x, bb.y);
                mma16816(acc[1][j], aA1.x, aB1.x, aA1.y, aB1.y, bb.x, bb.y);
            }
        }

        const float* bias = (p < 2) ? (g_bfin + (2 * p + half) * E)
                                    : (g_bv + half * E);
        __half* Outg = ((p == 0) ? g_fq : (p == 1) ? g_fk : g_fv) + rowBase * E;
        __syncthreads();
        __half* stage = reinterpret_cast<__half*>(Bw);
        #pragma unroll
        for (int j = 0; j < 10; j++) {
            int col = cb + j * 8 + q * 2;
            float b0f = bias[col], b1f = bias[col + 1];
            #pragma unroll
            for (int h2 = 0; h2 < 2; h2++) {
                int row = rb + h2 * 16 + g;
                *reinterpret_cast<__half2*>(stage + row * 160 + col) =
                    __floats2half2_rn(acc[h2][j][0] + b0f, acc[h2][j][1] + b1f);
                *reinterpret_cast<__half2*>(stage + (row + 8) * 160 + col) =
                    __floats2half2_rn(acc[h2][j][2] + b0f, acc[h2][j][3] + b1f);
            }
        }
        __syncthreads();
        #pragma unroll
        for (int s = 0; s < 10; s++) {
            int idx = t + 256 * s;
            reinterpret_cast<uint4*>(Outg)[idx] =
                reinterpret_cast<const uint4*>(stage)[idx];
        }
    }
}

// ---------------- K3: inner attention via mma + ldmatrix frag loads ----------
__global__ __launch_bounds__(320) void inner_attn_mma(const int* __restrict__ in_idx,
                                                      const int* __restrict__ out_idx)
{
    __shared__ __align__(16) __half tile[96][168];   // rows: hh*48 + mat*16 + l
    __shared__ int idxs[2][16];
    const int n = blockIdx.x, b = blockIdx.y;
    const int t = threadIdx.x;
    const size_t tok = (size_t)b * NN + n;
    const size_t base = (size_t)b * NN;

    if (t < 32) {
        int hh = t >> 4, i = t & 15;
        const int* ia = hh ? out_idx : in_idx;
        idxs[hh][i] = (i == 0) ? n : ia[tok * DINN + i - 1];
    }
    __syncthreads();

    // gather 96 rows x 320B (fp16): 1920 uint4 tasks, single STS.128 each
    #pragma unroll
    for (int it = 0; it < 6; it++) {
        int task = t + 320 * it;
        int r = task / 20, seg = task - r * 20;
        int hh = r / 48, sub = r - hh * 48;
        int mat = sub >> 4, l = sub & 15;
        const __half* src = g_px +
            ((size_t)(hh * 3 + mat) * BN + base + idxs[hh][l]) * E + seg * 8;
        *reinterpret_cast<uint4*>(&tile[r][seg * 8]) =
            *reinterpret_cast<const uint4*>(src);
    }
    __syncthreads();

    const int w = t >> 5, lane = t & 31;
    const int g = lane >> 2, q = lane & 3;
    const int hh = w / 5, h = w - hh * 5;
    const int qr = hh * 48, kr = qr + 16, vr = qr + 32;
    const int koff = h * 32;
    const int lrow = lane & 15, lcol = (lane >> 4) * 8;

    // scores S[16][16] = Q Kt over d=32 (2 k-chunks)
    float s0[4] = {0.f, 0.f, 0.f, 0.f}, s1[4] = {0.f, 0.f, 0.f, 0.f};
    #pragma unroll
    for (int kc = 0; kc < 2; kc++) {
        int ko = koff + kc * 16;
        uint32_t a0, a1, a2, a3, k0, k1, k2, k3;
        ldsm_x4(a0, a1, a2, a3, cvta_smem(&tile[qr + lrow][ko + lcol]));
        ldsm_x4(k0, k1, k2, k3, cvta_smem(&tile[kr + lrow][ko + lcol]));
        // k0=(n0-7,klo) k1=(n8-15,klo) k2=(n0-7,khi) k3=(n8-15,khi)
        mma16816(s0, a0, a1, a2, a3, k0, k2);
        mma16816(s1, a0, a1, a2, a3, k1, k3);
    }
    const float scale = 0.17677669529663687f;  // 1/sqrt(32)
    #pragma unroll
    for (int u = 0; u < 4; u++) { s0[u] *= scale; s1[u] *= scale; }

    // in-register softmax over cols (rows g and g+8), reduce across 4 q-lanes
    float mx0 = fmaxf(fmaxf(s0[0], s0[1]), fmaxf(s1[0], s1[1]));
    float mx1 = fmaxf(fmaxf(s0[2], s0[3]), fmaxf(s1[2], s1[3]));
    mx0 = fmaxf(mx0, __shfl_xor_sync(0xffffffffu, mx0, 1));
    mx0 = fmaxf(mx0, __shfl_xor_sync(0xffffffffu, mx0, 2));
    mx1 = fmaxf(mx1, __shfl_xor_sync(0xffffffffu, mx1, 1));
    mx1 = fmaxf(mx1, __shfl_xor_sync(0xffffffffu, mx1, 2));
    float e00 = __expf(s0[0] - mx0), e01 = __expf(s0[1] - mx0);
    float e02 = __expf(s1[0] - mx0), e03 = __expf(s1[1] - mx0);
    float e10 = __expf(s0[2] - mx1), e11 = __expf(s0[3] - mx1);
    float e12 = __expf(s1[2] - mx1), e13 = __expf(s1[3] - mx1);
    float sum0 = e00 + e01 + e02 + e03;
    float sum1 = e10 + e11 + e12 + e13;
    sum0 += __shfl_xor_sync(0xffffffffu, sum0, 1);
    sum0 += __shfl_xor_sync(0xffffffffu, sum0, 2);
    sum1 += __shfl_xor_sync(0xffffffffu, sum1, 1);
    sum1 += __shfl_xor_sync(0xffffffffu, sum1, 2);
    float inv0 = 1.f / sum0, inv1 = 1.f / sum1;

    uint32_t pa0 = H2F(e00 * inv0, e01 * inv0);
    uint32_t pa1 = H2F(e10 * inv1, e11 * inv1);
    uint32_t pa2 = H2F(e02 * inv0, e03 * inv0);
    uint32_t pa3 = H2F(e12 * inv1, e13 * inv1);

    // AV: O[16][32] = P @ V; V b-frags via ldmatrix.trans (row-major V)
    __half* ob = g_obuf + ((size_t)hh * BN + tok) * (16 * E) + koff;
    #pragma unroll
    for (int nt = 0; nt < 4; nt++) {
        uint32_t b0, b1;
        ldsm_x2t(b0, b1, cvta_smem(&tile[vr + lrow][koff + nt * 8]));
        float o[4] = {0.f, 0.f, 0.f, 0.f};
        mma16816(o, pa0, pa1, pa2, pa3, b0, b1);
        *reinterpret_cast<__half2*>(ob + (size_t)g * E + nt * 8 + 2 * q) =
            __floats2half2_rn(o[0], o[1]);
        *reinterpret_cast<__half2*>(ob + (size_t)(g + 8) * E + nt * 8 + 2 * q) =
            __floats2half2_rn(o[2], o[3]);
    }
}

// ---------------- K5: final attention via mma + ldmatrix + max pool ----
__global__ __launch_bounds__(256) void final_attn_mma()
{
    __shared__ __align__(16) __half tile[96][168];   // 0-31 q, 32-63 k, 64-95 v
    __shared__ float sc[32][34];
    __shared__ __align__(16) __half ps[32][40];
    __shared__ float pb[2][160];
    const size_t tok = blockIdx.x;
    const int t = threadIdx.x;

    #pragma unroll
    for (int it = 0; it < 8; it++) {
        int task = t + 256 * it;
        if (task < 1920) {
            int r = task / 20, seg = task - r * 20;
            int mat = r >> 5, rr = r & 31, hh = rr >> 4, l = rr & 15;
            const __half* src = ((mat == 0) ? g_fq : (mat == 1) ? g_fk : g_fv)
                + (size_t)hh * HALF_ELEMS + tok * 2560 + l * 160 + seg * 8;
            *reinterpret_cast<uint4*>(&tile[r][seg * 8]) =
                *reinterpret_cast<const uint4*>(src);
        }
    }
    __syncthreads();

    const int w = t >> 5, lane = t & 31, g = lane >> 2, q = lane & 3;
    const int lrow = lane & 15, lcol = (lane >> 4) * 8;
    const int lrow8 = lane & 7, lcol8 = ((lane >> 3) & 1) * 8;

    // scores: warp -> (m-tile w>>2, n-tile w&3), k=160 in 10 chunks
    {
        const int mt = w >> 2, nt = w & 3;
        const int qr = mt * 16, kr = 32 + nt * 8;
        float c[4] = {0.f, 0.f, 0.f, 0.f};
        #pragma unroll
        for (int kc = 0; kc < 10; kc++) {
            int ko = kc * 16;
            uint32_t a0, a1, a2, a3, b0, b1;
            ldsm_x4(a0, a1, a2, a3, cvta_smem(&tile[qr + lrow][ko + lcol]));
            ldsm_x2(b0, b1, cvta_smem(&tile[kr + lrow8][ko + lcol8]));
            mma16816(c, a0, a1, a2, a3, b0, b1);
        }
        *reinterpret_cast<float2*>(&sc[qr + g][nt * 8 + 2 * q]) = make_float2(c[0], c[1]);
        *reinterpret_cast<float2*>(&sc[qr + g + 8][nt * 8 + 2 * q]) = make_float2(c[2], c[3]);
    }
    __syncthreads();

    // softmax rows (32 threads), probs -> fp16 (stride 40 for ldmatrix alignment)
    if (t < 32) {
        const float scale = 0.07905694150420949f;  // 1/sqrt(160)
        float v[32];
        float mx = -3.4e38f;
        #pragma unroll
        for (int m = 0; m < 32; m++) { v[m] = sc[t][m] * scale; mx = fmaxf(mx, v[m]); }
        float sum = 0.f;
        #pragma unroll
        for (int m = 0; m < 32; m++) { v[m] = __expf(v[m] - mx); sum += v[m]; }
        float inv = 1.f / sum;
        #pragma unroll
        for (int m = 0; m < 16; m++)
            *reinterpret_cast<__half2*>(&ps[t][2 * m]) =
                __floats2half2_rn(v[2 * m] * inv, v[2 * m + 1] * inv);
    }
    __syncthreads();

    // AV: O = P(32x32) @ V(32x160); a from ps via ldmatrix, b via ldmatrix.trans
    {
        const int mt = w >> 2, nb = w & 3;
        const int mr = mt * 16;
        uint32_t a[2][4];
        #pragma unroll
        for (int kc = 0; kc < 2; kc++)
            ldsm_x4(a[kc][0], a[kc][1], a[kc][2], a[kc][3],
                    cvta_smem(&ps[mr + lrow][kc * 16 + lcol]));
        #pragma unroll
        for (int j = 0; j < 5; j++) {
            int nt = nb + 4 * j;
            float o[4] = {0.f, 0.f, 0.f, 0.f};
            #pragma unroll
            for (int kc = 0; kc < 2; kc++) {
                uint32_t b0, b1;
                ldsm_x2t(b0, b1, cvta_smem(&tile[64 + kc * 16 + lrow][nt * 8]));
                mma16816(o, a[kc][0], a[kc][1], a[kc][2], a[kc][3], b0, b1);
            }
            float m0 = fmaxf(o[0], o[2]);
            float m1 = fmaxf(o[1], o[3]);
            #pragma unroll
            for (int s = 4; s < 32; s <<= 1) {
                m0 = fmaxf(m0, __shfl_xor_sync(0xffffffffu, m0, s));
                m1 = fmaxf(m1, __shfl_xor_sync(0xffffffffu, m1, s));
            }
            if (g == 0)
                *reinterpret_cast<float2*>(&pb[mt][nt * 8 + 2 * q]) = make_float2(m0, m1);
        }
    }
    __syncthreads();

    if (t < 160)
        g_pooled[tok * E + t] = fmaxf(pb[0][t], pb[1][t]);
}

// ---------------- host orchestration ----------------
extern "C" void kernel_launch(void* const* d_in, const int* in_sizes, int n_in,
                              void* d_out, int out_size)
{
    const float* X       = (const float*)d_in[0];
    const int*   in_idx  = (const int*)  d_in[1];
    const int*   out_idx = (const int*)  d_in[2];
    const float* iWq     = (const float*)d_in[3];
    const float* iWk     = (const float*)d_in[4];
    const float* iWv     = (const float*)d_in[5];
    const float* i_in_w  = (const float*)d_in[6];
    const float* i_in_b  = (const float*)d_in[7];
    const float* i_out_w = (const float*)d_in[8];
    const float* i_out_b = (const float*)d_in[9];
    const float* oWq     = (const float*)d_in[10];
    const float* oWk     = (const float*)d_in[11];
    const float* oWv     = (const float*)d_in[12];
    const float* o_in_w  = (const float*)d_in[13];
    const float* o_in_b  = (const float*)d_in[14];
    const float* o_out_w = (const float*)d_in[15];
    const float* o_out_b = (const float*)d_in[16];
    const float* f_in_w  = (const float*)d_in[17];
    const float* f_in_b  = (const float*)d_in[18];
    const float* f_out_w = (const float*)d_in[19];
    const float* f_out_b = (const float*)d_in[20];
    const float* lin_w   = (const float*)d_in[21];
    const float* lin_b   = (const float*)d_in[22];
    float* out = (float*)d_out;

    float* pooled;
    cudaGetSymbolAddress((void**)&pooled, g_pooled);

    const size_t smem_g   = (size_t)(128 * E + E * BSTR) * sizeof(float);   // 185,600 B
    const size_t smem_mma = (size_t)(128 * 84 + 160 * 84) * 4;              //  96,768 B
    cudaFuncSetAttribute(gemm128<1, 1>, cudaFuncAttributeMaxDynamicSharedMemorySize, (int)smem_g);
    cudaFuncSetAttribute(gemm3_mma,     cudaFuncAttributeMaxDynamicSharedMemorySize, (int)smem_mma);
    cudaFuncSetAttribute(gemm6_mma,     cudaFuncAttributeMaxDynamicSharedMemorySize, (int)smem_mma);

    // K1: fused weights + biases (2 launches)
    setup1<<<dim3(E, 13), E>>>(iWq, iWk, iWv, oWq, oWk, oWv,
                               i_in_w, o_in_w, f_in_w, i_out_w, o_out_w,
                               f_in_b, i_out_b, o_out_b);
    setup2<<<dim3(E, 13), E>>>(f_out_w, f_out_b);

    // K2: merged tensor-core projection of X -> px (fp16), one launch
    gemm6_mma<<<BN / 128, 256, smem_mma>>>(X, i_in_b, o_in_b);

    // K3: inner attentions via tensor cores + ldmatrix
    inner_attn_mma<<<dim3(NN, BB), 320>>>(in_idx, out_idx);

    // K4: tensor-core fused final projections -> qf/kf/vf' (fp16)
    gemm3_mma<<<8192, 256, smem_mma>>>();

    // K5: final attention (mma + ldmatrix) + folded out-proj + max pool
    final_attn_mma<<<BN, 256>>>();

    // K6: pooled @ lin_w.T + lin_b, ELU -> output
    gemm128<1, 1><<<BN / 128, 256, smem_g>>>(pooled, lin_w, lin_b, out);

    (void)in_sizes; (void)n_in; (void)out_size;
}

// round 12
// speedup vs baseline: 8.1644x; 1.0093x over previous
#include <cuda_runtime.h>
#include <cuda_fp16.h>
#include <cstdint>
#include <cstdio>

// Problem constants
#define E   160
#define BB  8
#define NN  4096
#define BN  (BB*NN)          // 32768 tokens
#define DINN 15
#define BSTR 162             // smem B row stride for gemm128 (floats)

// ---------------- static device scratch (allocation-free rule) ----------------
__device__ float g_cproj[6 * E * E];       // fused inner projection matrices [k][j]
__device__ float g_mfin [6 * E * E];       // fused final projection matrices [k][j]
__device__ float g_bfin [6 * E];           // fused final biases
__device__ float g_bv   [2 * E];           // v-bias with f_out_w folded in
// mats 0-5 (final q/k/v' h0,h1): PANEL-major [mat][ks][n][16 perm]
// mats 6-11 (cproj): row-major [n][k perm] (consumed by gemm6_mma)
__device__ __half g_wh  [12 * E * E];
__device__ __half g_px  [6ull * BN * E];               // projected X, fp16
__device__ __half g_obuf[(size_t)BN * 32 * E];         // inner attn out, TOKEN-major fp16
__device__ float g_pooled[(size_t)BN * E];

// ---------------- f32x2 helpers ----------------
__device__ __forceinline__ unsigned long long fma2(unsigned long long a,
                                                   unsigned long long b,
                                                   unsigned long long c) {
    unsigned long long d;
    asm("fma.rn.f32x2 %0, %1, %2, %3;" : "=l"(d) : "l"(a), "l"(b), "l"(c));
    return d;
}
__device__ __forceinline__ unsigned long long pack2(float x, float y) {
    unsigned long long r;
    asm("mov.b64 %0, {%1,%2};" : "=l"(r) : "f"(x), "f"(y));
    return r;
}
__device__ __forceinline__ float2 unpack2(unsigned long long v) {
    float2 f;
    asm("mov.b64 {%0,%1}, %2;" : "=f"(f.x), "=f"(f.y) : "l"(v));
    return f;
}

// ---------------- mma.sync m16n8k16 fp16->fp32 (validated frag ordering) -------
__device__ __forceinline__ void mma16816(float* c, uint32_t a0, uint32_t a1,
                                         uint32_t a2, uint32_t a3,
                                         uint32_t b0, uint32_t b1) {
    asm volatile(
        "mma.sync.aligned.m16n8k16.row.col.f32.f16.f16.f32 "
        "{%0,%1,%2,%3}, {%4,%5,%6,%7}, {%8,%9}, {%0,%1,%2,%3};\n"
        : "+f"(c[0]), "+f"(c[1]), "+f"(c[2]), "+f"(c[3])
        : "r"(a0), "r"(a1), "r"(a2), "r"(a3), "r"(b0), "r"(b1));
}

// ---------------- ldmatrix helpers ----------------
__device__ __forceinline__ uint32_t cvta_smem(const void* p) {
    return (uint32_t)__cvta_generic_to_shared(p);
}
__device__ __forceinline__ void ldsm_x4(uint32_t& r0, uint32_t& r1, uint32_t& r2,
                                        uint32_t& r3, uint32_t a) {
    asm volatile("ldmatrix.sync.aligned.m8n8.x4.shared.b16 {%0,%1,%2,%3}, [%4];"
                 : "=r"(r0), "=r"(r1), "=r"(r2), "=r"(r3) : "r"(a));
}
__device__ __forceinline__ void ldsm_x2t(uint32_t& r0, uint32_t& r1, uint32_t a) {
    asm volatile("ldmatrix.sync.aligned.m8n8.x2.trans.shared.b16 {%0,%1}, [%2];"
                 : "=r"(r0), "=r"(r1) : "r"(a));
}

__device__ __forceinline__ uint32_t H2F(float a, float b) {
    __half2 h = __floats2half2_rn(a, b);
    return *reinterpret_cast<uint32_t*>(&h);
}

// k-permutation within a 16-k group so mma k-pairs are contiguous words
__device__ __forceinline__ int kperm(int l) {
    return (l < 8) ? (((l >> 1) << 2) + (l & 1))
                   : ((((l - 8) >> 1) << 2) + 2 + (l & 1));
}

// ---------------- setup1: all fused fp32 matrices + fused biases ----------------
__global__ void setup1(
    const float* __restrict__ iWq, const float* __restrict__ iWk, const float* __restrict__ iWv,
    const float* __restrict__ oWq, const float* __restrict__ oWk, const float* __restrict__ oWv,
    const float* __restrict__ i_in_w, const float* __restrict__ o_in_w,
    const float* __restrict__ f_in_w, const float* __restrict__ i_out_w,
    const float* __restrict__ o_out_w,
    const float* __restrict__ f_in_b,
    const float* __restrict__ i_out_b, const float* __restrict__ o_out_b)
{
    __shared__ float col[E];
    int m = blockIdx.y, r = blockIdx.x, j = threadIdx.x;
    if (m < 6) {
        const float* W = (m == 0) ? iWq : (m == 1) ? iWk : (m == 2) ? iWv
                       : (m == 3) ? oWq : (m == 4) ? oWk : oWv;
        const float* inw = ((m < 3) ? i_in_w : o_in_w) + (size_t)(m % 3) * E * E;
        col[j] = W[r * E + j];
        __syncthreads();
        float s = 0.f;
        #pragma unroll 8
        for (int tt = 0; tt < E; tt++) s += col[tt] * inw[j * E + tt];
        g_cproj[(size_t)m * E * E + r * E + j] = s;
    } else if (m < 12) {
        int mf = m - 6;
        int f = mf >> 1;
        const float* ow = (mf & 1) ? o_out_w : i_out_w;
        col[j] = ow[j * E + r];
        __syncthreads();
        float s = 0.f;
        #pragma unroll 8
        for (int c = 0; c < E; c++) s += col[c] * f_in_w[(f * E + j) * E + c];
        g_mfin[(size_t)mf * E * E + r * E + j] = s;
    } else {
        if (r < 6) {
            int f = r >> 1;
            const float* ob = (r & 1) ? o_out_b : i_out_b;
            float s = f_in_b[f * E + j];
            #pragma unroll 8
            for (int c = 0; c < E; c++) s += ob[c] * f_in_w[(f * E + j) * E + c];
            g_bfin[r * E + j] = s;
        }
    }
}

// ---------------- setup2: fp16 conversions + bv ----------------
// y 0..3 : panel-major wh[y][ks][n][perm l] = mfin[y][k][n]
// y 4..5 : same, with f_out_w fold
// y 6..11: row-major wh[y][n][perm k] = cproj[y-6][k][n]  (K2 path)
// y == 12 (n<2): bv
__global__ void setup2(const float* __restrict__ f_out_w, const float* __restrict__ f_out_b)
{
    __shared__ float s_fw[E];
    int y = blockIdx.y, n = blockIdx.x, k = threadIdx.x;
    if (y < 4) {
        g_wh[(size_t)y * E * E + (k >> 4) * 2560 + n * 16 + kperm(k & 15)] =
            __float2half(g_mfin[(size_t)y * E * E + k * E + n]);
    } else if (y < 6) {
        s_fw[k] = f_out_w[n * E + k];
        __syncthreads();
        const float* mrow = g_mfin + (size_t)y * E * E + k * E;
        float s = 0.f;
        #pragma unroll 8
        for (int j = 0; j < E; j++) s += mrow[j] * s_fw[j];
        g_wh[(size_t)y * E * E + (k >> 4) * 2560 + n * 16 + kperm(k & 15)] = __float2half(s);
    } else if (y < 12) {
        g_wh[(size_t)y * E * E + n * E + (k >> 4) * 16 + kperm(k & 15)] =
            __float2half(g_cproj[(size_t)(y - 6) * E * E + k * E + n]);
    } else {
        if (n < 2) {
            float s = f_out_b[k];
            const float* bf = g_bfin + (4 + n) * E;
            #pragma unroll 8
            for (int j = 0; j < E; j++) s += bf[j] * f_out_w[k * E + j];
            g_bv[n * E + k] = s;
        }
    }
}

// ---------------- 128x160 GEMM K=160, fp32, ELU out (K6) -------------
template<int TRANSB, int MODE>
__global__ __launch_bounds__(256, 1) void gemm128(
    const float* __restrict__ A, const float* __restrict__ Bm,
    const float* __restrict__ bias, float* __restrict__ Out)
{
    extern __shared__ float sm[];
    float* As = sm;
    float* Bs = sm + 128 * E;
    const int t = threadIdx.x;
    const size_t rowBase = (size_t)blockIdx.x * 128;

    const float4* Ag = reinterpret_cast<const float4*>(A + rowBase * E);
    float4* As4 = reinterpret_cast<float4*>(As);
    #pragma unroll
    for (int i = 0; i < 20; i++) As4[t + 256 * i] = Ag[t + 256 * i];

    if (TRANSB == 0) {
        #pragma unroll 4
        for (int i = 0; i < 100; i++) {
            int idx = t + 256 * i;
            int k = idx / E, j = idx - k * E;
            Bs[k * BSTR + j] = Bm[idx];
        }
    } else {
        #pragma unroll 4
        for (int i = 0; i < 100; i++) {
            int idx = t + 256 * i;
            int j = idx / E, k = idx - j * E;
            Bs[k * BSTR + j] = Bm[idx];
        }
    }
    __syncthreads();

    const int tx = t & 15, ty = t >> 4;
    unsigned long long acc[8][5];
    const unsigned long long z = pack2(0.f, 0.f);
    #pragma unroll
    for (int i = 0; i < 8; i++)
        #pragma unroll
        for (int u = 0; u < 5; u++) acc[i][u] = z;

    const float* Ath = As + ty * (8 * E);
    #pragma unroll 2
    for (int k = 0; k < E; k++) {
        unsigned long long b2[5];
        const unsigned long long* bp =
            reinterpret_cast<const unsigned long long*>(Bs + k * BSTR + tx * 10);
        #pragma unroll
        for (int u = 0; u < 5; u++) b2[u] = bp[u];
        #pragma unroll
        for (int i = 0; i < 8; i++) {
            float a = Ath[i * E + k];
            unsigned long long a2 = pack2(a, a);
            #pragma unroll
            for (int u = 0; u < 5; u++) acc[i][u] = fma2(a2, b2[u], acc[i][u]);
        }
    }

    float bcol[10];
    #pragma unroll
    for (int u = 0; u < 10; u++) bcol[u] = bias[tx * 10 + u];

    #pragma unroll
    for (int i = 0; i < 8; i++) {
        size_t ro = (rowBase + ty * 8 + i) * E + tx * 10;
        #pragma unroll
        for (int u = 0; u < 5; u++) {
            float2 v = unpack2(acc[i][u]);
            v.x += bcol[2 * u];
            v.y += bcol[2 * u + 1];
            if (MODE == 1) {
                v.x = v.x > 0.f ? v.x : expm1f(v.x);
                v.y = v.y > 0.f ? v.y : expm1f(v.y);
            }
            *reinterpret_cast<float2*>(Out + ro + 2 * u) = v;
        }
    }
}

// ---------------- K2: tensor-core merged projection of X (6 matrices) ----------
__global__ __launch_bounds__(256, 2) void gemm6_mma(
    const float* __restrict__ X,
    const float* __restrict__ i_in_b, const float* __restrict__ o_in_b)
{
    extern __shared__ uint32_t smw[];
    uint32_t* Aw = smw;                 // 128*84 words
    uint32_t* Bw = smw + 128 * 84;      // 160*84 words
    const int t = threadIdx.x;
    const size_t rowBase = (size_t)blockIdx.x * 128;

    {
        const float4* Xg = reinterpret_cast<const float4*>(X + rowBase * E);
        #pragma unroll
        for (int s = 0; s < 10; s++) {
            int idx = t + 256 * s;
            int row = idx / 20, c = idx - row * 20;
            float4 x0 = Xg[idx * 2], x1 = Xg[idx * 2 + 1];
            uint32_t* d = Aw + row * 84 + (c >> 1) * 8 + (c & 1);
            d[0] = H2F(x0.x, x0.y);
            d[2] = H2F(x0.z, x0.w);
            d[4] = H2F(x1.x, x1.y);
            d[6] = H2F(x1.z, x1.w);
        }
    }

    const int lane = t & 31, w = t >> 5;
    const int rb = (w >> 1) * 32;
    const int cb = (w & 1) * 80;
    const int g = lane >> 2, q = lane & 3;

    const uint32_t* A0 = Aw + (rb + g) * 84 + q * 2;
    const uint32_t* B0 = Bw + (cb + g) * 84 + q * 2;

    for (int p = 0; p < 6; p++) {
        __syncthreads();
        {
            const uint4* Bg = reinterpret_cast<const uint4*>(g_wh + (size_t)(6 + p) * E * E);
            #pragma unroll
            for (int s = 0; s < 13; s++) {
                int idx = t + 256 * s;
                if (idx < 3200) {
                    int n = idx / 20, c = idx - n * 20;
                    *reinterpret_cast<uint4*>(Bw + n * 84 + c * 4) = Bg[idx];
                }
            }
        }
        __syncthreads();

        float acc[2][10][4];
        #pragma unroll
        for (int h2 = 0; h2 < 2; h2++)
            #pragma unroll
            for (int j = 0; j < 10; j++)
                #pragma unroll
                for (int u = 0; u < 4; u++) acc[h2][j][u] = 0.f;

        #pragma unroll
        for (int ks = 0; ks < 10; ks++) {
            uint2 aA0 = *reinterpret_cast<const uint2*>(A0 + ks * 8);
            uint2 aB0 = *reinterpret_cast<const uint2*>(A0 + 8 * 84 + ks * 8);
            uint2 aA1 = *reinterpret_cast<const uint2*>(A0 + 16 * 84 + ks * 8);
            uint2 aB1 = *reinterpret_cast<const uint2*>(A0 + 24 * 84 + ks * 8);
            #pragma unroll
            for (int j = 0; j < 10; j++) {
                uint2 bb = *reinterpret_cast<const uint2*>(B0 + (j * 8) * 84 + ks * 8);
                mma16816(acc[0][j], aA0.x, aB0.x, aA0.y, aB0.y, bb.x, bb.y);
                mma16816(acc[1][j], aA1.x, aB1.x, aA1.y, aB1.y, bb.x, bb.y);
            }
        }

        const float* bias = (p < 3) ? (i_in_b + p * E) : (o_in_b + (p - 3) * E);
        __half* Outg = g_px + (size_t)p * BN * E + rowBase * E;
        __syncthreads();
        __half* stage = reinterpret_cast<__half*>(Bw);
        #pragma unroll
        for (int j = 0; j < 10; j++) {
            int col = cb + j * 8 + q * 2;
            float b0f = bias[col], b1f = bias[col + 1];
            #pragma unroll
            for (int h2 = 0; h2 < 2; h2++) {
                int row = rb + h2 * 16 + g;
                *reinterpret_cast<__half2*>(stage + row * 160 + col) =
                    __floats2half2_rn(acc[h2][j][0] + b0f, acc[h2][j][1] + b1f);
                *reinterpret_cast<__half2*>(stage + (row + 8) * 160 + col) =
                    __floats2half2_rn(acc[h2][j][2] + b0f, acc[h2][j][3] + b1f);
            }
        }
        __syncthreads();
        #pragma unroll
        for (int s = 0; s < 10; s++) {
            int idx = t + 256 * s;
            reinterpret_cast<uint4*>(Outg)[idx] =
                reinterpret_cast<const uint4*>(stage)[idx];
        }
    }
}

// ---------------- K3: inner attention via mma + ldmatrix (token-major obuf) ----
__global__ __launch_bounds__(320) void inner_attn_mma(const int* __restrict__ in_idx,
                                                      const int* __restrict__ out_idx)
{
    __shared__ __align__(16) __half tile[96][168];   // rows: hh*48 + mat*16 + l
    __shared__ int idxs[2][16];
    const int n = blockIdx.x, b = blockIdx.y;
    const int t = threadIdx.x;
    const size_t tok = (size_t)b * NN + n;
    const size_t base = (size_t)b * NN;

    if (t < 32) {
        int hh = t >> 4, i = t & 15;
        const int* ia = hh ? out_idx : in_idx;
        idxs[hh][i] = (i == 0) ? n : ia[tok * DINN + i - 1];
    }
    __syncthreads();

    #pragma unroll
    for (int it = 0; it < 6; it++) {
        int task = t + 320 * it;
        int r = task / 20, seg = task - r * 20;
        int hh = r / 48, sub = r - hh * 48;
        int mat = sub >> 4, l = sub & 15;
        const __half* src = g_px +
            ((size_t)(hh * 3 + mat) * BN + base + idxs[hh][l]) * E + seg * 8;
        *reinterpret_cast<uint4*>(&tile[r][seg * 8]) =
            *reinterpret_cast<const uint4*>(src);
    }
    __syncthreads();

    const int w = t >> 5, lane = t & 31;
    const int g = lane >> 2, q = lane & 3;
    const int hh = w / 5, h = w - hh * 5;
    const int qr = hh * 48, kr = qr + 16, vr = qr + 32;
    const int koff = h * 32;
    const int lrow = lane & 15, lcol = (lane >> 4) * 8;

    float s0[4] = {0.f, 0.f, 0.f, 0.f}, s1[4] = {0.f, 0.f, 0.f, 0.f};
    #pragma unroll
    for (int kc = 0; kc < 2; kc++) {
        int ko = koff + kc * 16;
        uint32_t a0, a1, a2, a3, k0, k1, k2, k3;
        ldsm_x4(a0, a1, a2, a3, cvta_smem(&tile[qr + lrow][ko + lcol]));
        ldsm_x4(k0, k1, k2, k3, cvta_smem(&tile[kr + lrow][ko + lcol]));
        mma16816(s0, a0, a1, a2, a3, k0, k2);
        mma16816(s1, a0, a1, a2, a3, k1, k3);
    }
    const float scale = 0.17677669529663687f;  // 1/sqrt(32)
    #pragma unroll
    for (int u = 0; u < 4; u++) { s0[u] *= scale; s1[u] *= scale; }

    float mx0 = fmaxf(fmaxf(s0[0], s0[1]), fmaxf(s1[0], s1[1]));
    float mx1 = fmaxf(fmaxf(s0[2], s0[3]), fmaxf(s1[2], s1[3]));
    mx0 = fmaxf(mx0, __shfl_xor_sync(0xffffffffu, mx0, 1));
    mx0 = fmaxf(mx0, __shfl_xor_sync(0xffffffffu, mx0, 2));
    mx1 = fmaxf(mx1, __shfl_xor_sync(0xffffffffu, mx1, 1));
    mx1 = fmaxf(mx1, __shfl_xor_sync(0xffffffffu, mx1, 2));
    float e00 = __expf(s0[0] - mx0), e01 = __expf(s0[1] - mx0);
    float e02 = __expf(s1[0] - mx0), e03 = __expf(s1[1] - mx0);
    float e10 = __expf(s0[2] - mx1), e11 = __expf(s0[3] - mx1);
    float e12 = __expf(s1[2] - mx1), e13 = __expf(s1[3] - mx1);
    float sum0 = e00 + e01 + e02 + e03;
    float sum1 = e10 + e11 + e12 + e13;
    sum0 += __shfl_xor_sync(0xffffffffu, sum0, 1);
    sum0 += __shfl_xor_sync(0xffffffffu, sum0, 2);
    sum1 += __shfl_xor_sync(0xffffffffu, sum1, 1);
    sum1 += __shfl_xor_sync(0xffffffffu, sum1, 2);
    float inv0 = 1.f / sum0, inv1 = 1.f / sum1;

    uint32_t pa0 = H2F(e00 * inv0, e01 * inv0);
    uint32_t pa1 = H2F(e10 * inv1, e11 * inv1);
    uint32_t pa2 = H2F(e02 * inv0, e03 * inv0);
    uint32_t pa3 = H2F(e12 * inv1, e13 * inv1);

    // token-major obuf: token rows [32*tok, +32), half hh at +16*hh
    __half* ob = g_obuf + ((size_t)tok * 32 + hh * 16) * E + koff;
    #pragma unroll
    for (int nt = 0; nt < 4; nt++) {
        uint32_t b0, b1;
        ldsm_x2t(b0, b1, cvta_smem(&tile[vr + lrow][koff + nt * 8]));
        float o[4] = {0.f, 0.f, 0.f, 0.f};
        mma16816(o, pa0, pa1, pa2, pa3, b0, b1);
        *reinterpret_cast<__half2*>(ob + (size_t)g * E + nt * 8 + 2 * q) =
            __floats2half2_rn(o[0], o[1]);
        *reinterpret_cast<__half2*>(ob + (size_t)(g + 8) * E + nt * 8 + 2 * q) =
            __floats2half2_rn(o[2], o[3]);
    }
}

// ---------------- K45 fused: final projections + attention + max pool ----------
// CTA = 2 tokens = 64 obuf rows. Q/K/V' computed into smem (never to DRAM),
// then 32x32 attention + folded out-proj + pool.
// smem layout (bytes):
//   [0, 21504)        A (64 rows x 84 words, k-permuted)  -- reused for sc/ps/pb
//   [21504, 43008)    Qs  (64 x 168 halves)
//   [43008, 64512)    Ks
//   [64512, 86016)    Vs
//   [86016, 106496)   B panels: 2 buf x 2 half x 160 n x 8 words
#define FA_SMEM 106496
__global__ __launch_bounds__(256, 2) void fused_attn()
{
    extern __shared__ __align__(16) char smc[];
    uint32_t* Aw   = reinterpret_cast<uint32_t*>(smc);
    __half (*Qs)[168] = reinterpret_cast<__half(*)[168]>(smc + 21504);
    __half (*Ks)[168] = reinterpret_cast<__half(*)[168]>(smc + 43008);
    __half (*Vs)[168] = reinterpret_cast<__half(*)[168]>(smc + 64512);
    uint32_t* Bpw  = reinterpret_cast<uint32_t*>(smc + 86016);
    uint4*    BpU4 = reinterpret_cast<uint4*>(smc + 86016);

    const int t = threadIdx.x;
    const size_t rowBase = (size_t)blockIdx.x * 64;

    // ---- load A tile (64 rows fp16, k-permuted store) ----
    {
        const uint4* Ag = reinterpret_cast<const uint4*>(g_obuf + rowBase * E);
        #pragma unroll
        for (int s = 0; s < 5; s++) {
            int idx = t + 256 * s;
            int row = idx / 20, c = idx - row * 20;
            uint4 v = Ag[idx];
            uint32_t* d = Aw + row * 84 + (c >> 1) * 8 + (c & 1);
            d[0] = v.x; d[2] = v.y; d[4] = v.z; d[6] = v.w;
        }
    }

    const int lane = t & 31, w = t >> 5;
    const int g = lane >> 2, q = lane & 3;
    const int half = w >> 2;             // GEMM: which half's weight matrix
    const int cb = (w & 3) * 40;         // GEMM: 40-col group
    const uint32_t* A0 = Aw + (half * 16 + g) * 84 + q * 2;

    int buf = 0;
    __syncthreads();   // A tile ready (also Bpan free)

    for (int p = 0; p < 3; p++) {
        // preload panel 0 of this pass into current buf
        {
            #pragma unroll
            for (int s = 0; s < 3; s++) {
                int idx = t + 256 * s;
                if (idx < 640) {
                    int hs = idx >= 320 ? 1 : 0;
                    int i2 = idx - hs * 320;
                    BpU4[buf * 640 + idx] = reinterpret_cast<const uint4*>(
                        g_wh + (size_t)(2 * p + hs) * E * E)[i2];
                }
            }
        }
        __syncthreads();

        float acc[2][5][4];
        #pragma unroll
        for (int h2 = 0; h2 < 2; h2++)
            #pragma unroll
            for (int j = 0; j < 5; j++)
                #pragma unroll
                for (int u = 0; u < 4; u++) acc[h2][j][u] = 0.f;

        for (int ks = 0; ks < 10; ks++) {
            uint4 pf[3];
            if (ks < 9) {
                #pragma unroll
                for (int s = 0; s < 3; s++) {
                    int idx = t + 256 * s;
                    if (idx < 640) {
                        int hs = idx >= 320 ? 1 : 0;
                        int i2 = idx - hs * 320;
                        pf[s] = reinterpret_cast<const uint4*>(
                            g_wh + (size_t)(2 * p + hs) * E * E + (ks + 1) * 2560)[i2];
                    }
                }
            }
            // compute on panel ks (buf)
            {
                uint2 aA0 = *reinterpret_cast<const uint2*>(A0 + ks * 8);
                uint2 aB0 = *reinterpret_cast<const uint2*>(A0 + 8 * 84 + ks * 8);
                uint2 aA1 = *reinterpret_cast<const uint2*>(A0 + 32 * 84 + ks * 8);
                uint2 aB1 = *reinterpret_cast<const uint2*>(A0 + 40 * 84 + ks * 8);
                const uint32_t* Bp = Bpw + buf * 2560 + half * 1280 + (cb + g) * 8 + q * 2;
                #pragma unroll
                for (int j = 0; j < 5; j++) {
                    uint2 bb = *reinterpret_cast<const uint2*>(Bp + j * 64);
                    mma16816(acc[0][j], aA0.x, aB0.x, aA0.y, aB0.y, bb.x, bb.y);
                    mma16816(acc[1][j], aA1.x, aB1.x, aA1.y, aB1.y, bb.x, bb.y);
                }
            }
            if (ks < 9) {
                #pragma unroll
                for (int s = 0; s < 3; s++) {
                    int idx = t + 256 * s;
                    if (idx < 640) BpU4[(buf ^ 1) * 640 + idx] = pf[s];
                }
            }
            __syncthreads();
            if (ks < 9) buf ^= 1;
        }

        // epilogue: bias + fp16 into Qs/Ks/Vs
        {
            const float* bias = (p < 2) ? (g_bfin + (2 * p + half) * E)
                                        : (g_bv + half * E);
            __half (*dst)[168] = (p == 0) ? Qs : (p == 1) ? Ks : Vs;
            const int r0 = half * 16 + g;
            #pragma unroll
            for (int j = 0; j < 5; j++) {
                int col = cb + j * 8 + 2 * q;
                float b0f = bias[col], b1f = bias[col + 1];
                *reinterpret_cast<__half2*>(&dst[r0][col]) =
                    __floats2half2_rn(acc[0][j][0] + b0f, acc[0][j][1] + b1f);
                *reinterpret_cast<__half2*>(&dst[r0 + 8][col]) =
                    __floats2half2_rn(acc[0][j][2] + b0f, acc[0][j][3] + b1f);
                *reinterpret_cast<__half2*>(&dst[32 + r0][col]) =
                    __floats2half2_rn(acc[1][j][0] + b0f, acc[1][j][1] + b1f);
                *reinterpret_cast<__half2*>(&dst[32 + r0 + 8][col]) =
                    __floats2half2_rn(acc[1][j][2] + b0f, acc[1][j][3] + b1f);
            }
        }
        __syncthreads();
    }

    // ---- attention on the 2 tokens (Q/K/V in smem) ----
    float*  sc = reinterpret_cast<float*>(smc);            // [2][32][34]
    __half* ps = reinterpret_cast<__half*>(smc + 8704);    // [2][32][40]
    float*  pb = reinterpret_cast<float*>(smc + 13824);    // [2][2][160]

    const int lrow = lane & 15, lcol = (lane >> 4) * 8;

    // scores: warp -> (token w>>2, mt=(w>>1)&1, nt2=w&1), m16n16, k=160
    {
        const int tk = w >> 2, mt = (w >> 1) & 1, nt2 = w & 1;
        const __half* Qb = &Qs[32 * tk + 16 * mt + lrow][0];
        const __half* Kb = &Ks[32 * tk + 16 * nt2 + lrow][0];
        float s0[4] = {0.f, 0.f, 0.f, 0.f}, s1[4] = {0.f, 0.f, 0.f, 0.f};
        #pragma unroll
        for (int kc = 0; kc < 10; kc++) {
            uint32_t a0, a1, a2, a3, k0, k1, k2, k3;
            ldsm_x4(a0, a1, a2, a3, cvta_smem(Qb + kc * 16 + lcol));
            ldsm_x4(k0, k1, k2, k3, cvta_smem(Kb + kc * 16 + lcol));
            mma16816(s0, a0, a1, a2, a3, k0, k2);
            mma16816(s1, a0, a1, a2, a3, k1, k3);
        }
        const float scale = 0.07905694150420949f;  // 1/sqrt(160)
        float* scr = sc + tk * (32 * 34);
        int rr = 16 * mt + g, cc = 16 * nt2 + 2 * q;
        *reinterpret_cast<float2*>(&scr[rr * 34 + cc]) =
            make_float2(s0[0] * scale, s0[1] * scale);
        *reinterpret_cast<float2*>(&scr[(rr + 8) * 34 + cc]) =
            make_float2(s0[2] * scale, s0[3] * scale);
        *reinterpret_cast<float2*>(&scr[rr * 34 + cc + 8]) =
            make_float2(s1[0] * scale, s1[1] * scale);
        *reinterpret_cast<float2*>(&scr[(rr + 8) * 34 + cc + 8]) =
            make_float2(s1[2] * scale, s1[3] * scale);
    }
    __syncthreads();

    // softmax: 64 threads, one row each
    if (t < 64) {
        const int tk = t >> 5, r = t & 31;
        float* row = sc + tk * (32 * 34) + r * 34;
        float v[32];
        float mx = -3.4e38f;
        #pragma unroll
        for (int m = 0; m < 32; m++) { v[m] = row[m]; mx = fmaxf(mx, v[m]); }
        float sum = 0.f;
        #pragma unroll
        for (int m = 0; m < 32; m++) { v[m] = __expf(v[m] - mx); sum += v[m]; }
        float inv = 1.f / sum;
        __half* pr = ps + tk * (32 * 40) + r * 40;
        #pragma unroll
        for (int m = 0; m < 16; m++)
            *reinterpret_cast<__half2*>(pr + 2 * m) =
                __floats2half2_rn(v[2 * m] * inv, v[2 * m + 1] * inv);
    }
    __syncthreads();

    // AV + max pool: warp -> (token w>>2, mt, nb), m16n80 (10 n-tiles per warp)
    {
        const int tk = w >> 2, sub = w & 3;
        const int mt = sub >> 1, nb = sub & 1;
        uint32_t a[2][4];
        #pragma unroll
        for (int kc = 0; kc < 2; kc++)
            ldsm_x4(a[kc][0], a[kc][1], a[kc][2], a[kc][3],
                    cvta_smem(ps + tk * (32 * 40) + (16 * mt + lrow) * 40 + kc * 16 + lcol));
        #pragma unroll
        for (int nt = 0; nt < 10; nt++) {
            float o[4] = {0.f, 0.f, 0.f, 0.f};
            #pragma unroll
            for (int kc = 0; kc < 2; kc++) {
                uint32_t b0, b1;
                ldsm_x2t(b0, b1, cvta_smem(&Vs[32 * tk + kc * 16 + lrow][nb * 80 + nt * 8]));
                mma16816(o, a[kc][0], a[kc][1], a[kc][2], a[kc][3], b0, b1);
            }
            float m0 = fmaxf(o[0], o[2]);
            float m1 = fmaxf(o[1], o[3]);
            #pragma unroll
            for (int s = 4; s < 32; s <<= 1) {
                m0 = fmaxf(m0, __shfl_xor_sync(0xffffffffu, m0, s));
                m1 = fmaxf(m1, __shfl_xor_sync(0xffffffffu, m1, s));
            }
            if (g == 0)
                *reinterpret_cast<float2*>(&pb[(tk * 2 + mt) * 160 + nb * 80 + nt * 8 + 2 * q]) =
                    make_float2(m0, m1);
        }
    }
    __syncthreads();

    // final pool across the two 16-row halves -> g_pooled
    for (int j = t; j < 320; j += 256) {
        int tk = j / 160, c = j - tk * 160;
        g_pooled[((size_t)blockIdx.x * 2 + tk) * E + c] =
            fmaxf(pb[tk * 320 + c], pb[tk * 320 + 160 + c]);
    }
}

// ---------------- host orchestration ----------------
extern "C" void kernel_launch(void* const* d_in, const int* in_sizes, int n_in,
                              void* d_out, int out_size)
{
    const float* X       = (const float*)d_in[0];
    const int*   in_idx  = (const int*)  d_in[1];
    const int*   out_idx = (const int*)  d_in[2];
    const float* iWq     = (const float*)d_in[3];
    const float* iWk     = (const float*)d_in[4];
    const float* iWv     = (const float*)d_in[5];
    const float* i_in_w  = (const float*)d_in[6];
    const float* i_in_b  = (const float*)d_in[7];
    const float* i_out_w = (const float*)d_in[8];
    const float* i_out_b = (const float*)d_in[9];
    const float* oWq     = (const float*)d_in[10];
    const float* oWk     = (const float*)d_in[11];
    const float* oWv     = (const float*)d_in[12];
    const float* o_in_w  = (const float*)d_in[13];
    const float* o_in_b  = (const float*)d_in[14];
    const float* o_out_w = (const float*)d_in[15];
    const float* o_out_b = (const float*)d_in[16];
    const float* f_in_w  = (const float*)d_in[17];
    const float* f_in_b  = (const float*)d_in[18];
    const float* f_out_w = (const float*)d_in[19];
    const float* f_out_b = (const float*)d_in[20];
    const float* lin_w   = (const float*)d_in[21];
    const float* lin_b   = (const float*)d_in[22];
    float* out = (float*)d_out;

    float* pooled;
    cudaGetSymbolAddress((void**)&pooled, g_pooled);

    const size_t smem_g   = (size_t)(128 * E + E * BSTR) * sizeof(float);   // 185,600 B
    const size_t smem_mma = (size_t)(128 * 84 + 160 * 84) * 4;              //  96,768 B
    cudaFuncSetAttribute(gemm128<1, 1>, cudaFuncAttributeMaxDynamicSharedMemorySize, (int)smem_g);
    cudaFuncSetAttribute(gemm6_mma,     cudaFuncAttributeMaxDynamicSharedMemorySize, (int)smem_mma);
    cudaFuncSetAttribute(fused_attn,    cudaFuncAttributeMaxDynamicSharedMemorySize, FA_SMEM);

    // K1: fused weights + biases (2 launches)
    setup1<<<dim3(E, 13), E>>>(iWq, iWk, iWv, oWq, oWk, oWv,
                               i_in_w, o_in_w, f_in_w, i_out_w, o_out_w,
                               f_in_b, i_out_b, o_out_b);
    setup2<<<dim3(E, 13), E>>>(f_out_w, f_out_b);

    // K2: merged tensor-core projection of X -> px (fp16), one launch
    gemm6_mma<<<BN / 128, 256, smem_mma>>>(X, i_in_b, o_in_b);

    // K3: inner attentions via tensor cores -> obuf (token-major fp16)
    inner_attn_mma<<<dim3(NN, BB), 320>>>(in_idx, out_idx);

    // K45: fused final projections + attention + max pool -> pooled
    fused_attn<<<BN / 2, 256, FA_SMEM>>>();

    // K6: pooled @ lin_w.T + lin_b, ELU -> output
    gemm128<1, 1><<<BN / 128, 256, smem_g>>>(pooled, lin_w, lin_b, out);

    (void)in_sizes; (void)n_in; (void)out_size;
}

// round 13
// speedup vs baseline: 10.8495x; 1.3289x over previous
#include <cuda_runtime.h>
#include <cuda_fp16.h>
#include <cstdint>
#include <cstdio>

// Problem constants
#define E   160
#define BB  8
#define NN  4096
#define BN  (BB*NN)          // 32768 tokens
#define DINN 15
#define BSTR 162             // smem B row stride for gemm128 (floats)

// ---------------- static device scratch (allocation-free rule) ----------------
__device__ float g_cproj[6 * E * E];       // fused inner projection matrices [k][j]
__device__ float g_mfin [6 * E * E];       // fused final projection matrices [k][j]
__device__ float g_bfin [6 * E];           // fused final biases
__device__ float g_bv   [2 * E];           // v-bias with f_out_w folded in
// mats 0-5 (final q/k/v' h0,h1): PANEL-major [mat][ks][n][16 perm]
// mats 6-11 (cproj): row-major [n][k perm] (consumed by gemm6_mma)
__device__ __half g_wh  [12 * E * E];
__device__ __half g_px  [6ull * BN * E];               // projected X, fp16
__device__ __half g_obuf[(size_t)BN * 32 * E];         // inner attn out, TOKEN-major fp16
__device__ float g_pooled[(size_t)BN * E];

// ---------------- f32x2 helpers ----------------
__device__ __forceinline__ unsigned long long fma2(unsigned long long a,
                                                   unsigned long long b,
                                                   unsigned long long c) {
    unsigned long long d;
    asm("fma.rn.f32x2 %0, %1, %2, %3;" : "=l"(d) : "l"(a), "l"(b), "l"(c));
    return d;
}
__device__ __forceinline__ unsigned long long pack2(float x, float y) {
    unsigned long long r;
    asm("mov.b64 %0, {%1,%2};" : "=l"(r) : "f"(x), "f"(y));
    return r;
}
__device__ __forceinline__ float2 unpack2(unsigned long long v) {
    float2 f;
    asm("mov.b64 {%0,%1}, %2;" : "=f"(f.x), "=f"(f.y) : "l"(v));
    return f;
}

// ---------------- mma.sync m16n8k16 fp16->fp32 (validated frag ordering) -------
__device__ __forceinline__ void mma16816(float* c, uint32_t a0, uint32_t a1,
                                         uint32_t a2, uint32_t a3,
                                         uint32_t b0, uint32_t b1) {
    asm volatile(
        "mma.sync.aligned.m16n8k16.row.col.f32.f16.f16.f32 "
        "{%0,%1,%2,%3}, {%4,%5,%6,%7}, {%8,%9}, {%0,%1,%2,%3};\n"
        : "+f"(c[0]), "+f"(c[1]), "+f"(c[2]), "+f"(c[3])
        : "r"(a0), "r"(a1), "r"(a2), "r"(a3), "r"(b0), "r"(b1));
}

// ---------------- ldmatrix helpers ----------------
__device__ __forceinline__ uint32_t cvta_smem(const void* p) {
    return (uint32_t)__cvta_generic_to_shared(p);
}
__device__ __forceinline__ void ldsm_x4(uint32_t& r0, uint32_t& r1, uint32_t& r2,
                                        uint32_t& r3, uint32_t a) {
    asm volatile("ldmatrix.sync.aligned.m8n8.x4.shared.b16 {%0,%1,%2,%3}, [%4];"
                 : "=r"(r0), "=r"(r1), "=r"(r2), "=r"(r3) : "r"(a));
}
__device__ __forceinline__ void ldsm_x2t(uint32_t& r0, uint32_t& r1, uint32_t a) {
    asm volatile("ldmatrix.sync.aligned.m8n8.x2.trans.shared.b16 {%0,%1}, [%2];"
                 : "=r"(r0), "=r"(r1) : "r"(a));
}

__device__ __forceinline__ uint32_t H2F(float a, float b) {
    __half2 h = __floats2half2_rn(a, b);
    return *reinterpret_cast<uint32_t*>(&h);
}

// k-permutation within a 16-k group so mma k-pairs are contiguous words
__device__ __forceinline__ int kperm(int l) {
    return (l < 8) ? (((l >> 1) << 2) + (l & 1))
                   : ((((l - 8) >> 1) << 2) + 2 + (l & 1));
}

// ---------------- setup1: all fused fp32 matrices + fused biases ----------------
__global__ void setup1(
    const float* __restrict__ iWq, const float* __restrict__ iWk, const float* __restrict__ iWv,
    const float* __restrict__ oWq, const float* __restrict__ oWk, const float* __restrict__ oWv,
    const float* __restrict__ i_in_w, const float* __restrict__ o_in_w,
    const float* __restrict__ f_in_w, const float* __restrict__ i_out_w,
    const float* __restrict__ o_out_w,
    const float* __restrict__ f_in_b,
    const float* __restrict__ i_out_b, const float* __restrict__ o_out_b)
{
    __shared__ float col[E];
    int m = blockIdx.y, r = blockIdx.x, j = threadIdx.x;
    if (m < 6) {
        const float* W = (m == 0) ? iWq : (m == 1) ? iWk : (m == 2) ? iWv
                       : (m == 3) ? oWq : (m == 4) ? oWk : oWv;
        const float* inw = ((m < 3) ? i_in_w : o_in_w) + (size_t)(m % 3) * E * E;
        col[j] = W[r * E + j];
        __syncthreads();
        float s = 0.f;
        #pragma unroll 8
        for (int tt = 0; tt < E; tt++) s += col[tt] * inw[j * E + tt];
        g_cproj[(size_t)m * E * E + r * E + j] = s;
    } else if (m < 12) {
        int mf = m - 6;
        int f = mf >> 1;
        const float* ow = (mf & 1) ? o_out_w : i_out_w;
        col[j] = ow[j * E + r];
        __syncthreads();
        float s = 0.f;
        #pragma unroll 8
        for (int c = 0; c < E; c++) s += col[c] * f_in_w[(f * E + j) * E + c];
        g_mfin[(size_t)mf * E * E + r * E + j] = s;
    } else {
        if (r < 6) {
            int f = r >> 1;
            const float* ob = (r & 1) ? o_out_b : i_out_b;
            float s = f_in_b[f * E + j];
            #pragma unroll 8
            for (int c = 0; c < E; c++) s += ob[c] * f_in_w[(f * E + j) * E + c];
            g_bfin[r * E + j] = s;
        }
    }
}

// ---------------- setup2: fp16 conversions + bv ----------------
// y 0..3 : panel-major wh[y][ks][n][perm l] = mfin[y][k][n]
// y 4..5 : same, with f_out_w fold
// y 6..11: row-major wh[y][n][perm k] = cproj[y-6][k][n]  (K2 path)
// y == 12 (n<2): bv
__global__ void setup2(const float* __restrict__ f_out_w, const float* __restrict__ f_out_b)
{
    __shared__ float s_fw[E];
    int y = blockIdx.y, n = blockIdx.x, k = threadIdx.x;
    if (y < 4) {
        g_wh[(size_t)y * E * E + (k >> 4) * 2560 + n * 16 + kperm(k & 15)] =
            __float2half(g_mfin[(size_t)y * E * E + k * E + n]);
    } else if (y < 6) {
        s_fw[k] = f_out_w[n * E + k];
        __syncthreads();
        const float* mrow = g_mfin + (size_t)y * E * E + k * E;
        float s = 0.f;
        #pragma unroll 8
        for (int j = 0; j < E; j++) s += mrow[j] * s_fw[j];
        g_wh[(size_t)y * E * E + (k >> 4) * 2560 + n * 16 + kperm(k & 15)] = __float2half(s);
    } else if (y < 12) {
        g_wh[(size_t)y * E * E + n * E + (k >> 4) * 16 + kperm(k & 15)] =
            __float2half(g_cproj[(size_t)(y - 6) * E * E + k * E + n]);
    } else {
        if (n < 2) {
            float s = f_out_b[k];
            const float* bf = g_bfin + (4 + n) * E;
            #pragma unroll 8
            for (int j = 0; j < E; j++) s += bf[j] * f_out_w[k * E + j];
            g_bv[n * E + k] = s;
        }
    }
}

// ---------------- 128x160 GEMM K=160, fp32, ELU out (K6) -------------
template<int TRANSB, int MODE>
__global__ __launch_bounds__(256, 1) void gemm128(
    const float* __restrict__ A, const float* __restrict__ Bm,
    const float* __restrict__ bias, float* __restrict__ Out)
{
    extern __shared__ float sm[];
    float* As = sm;
    float* Bs = sm + 128 * E;
    const int t = threadIdx.x;
    const size_t rowBase = (size_t)blockIdx.x * 128;

    const float4* Ag = reinterpret_cast<const float4*>(A + rowBase * E);
    float4* As4 = reinterpret_cast<float4*>(As);
    #pragma unroll
    for (int i = 0; i < 20; i++) As4[t + 256 * i] = Ag[t + 256 * i];

    if (TRANSB == 0) {
        #pragma unroll 4
        for (int i = 0; i < 100; i++) {
            int idx = t + 256 * i;
            int k = idx / E, j = idx - k * E;
            Bs[k * BSTR + j] = Bm[idx];
        }
    } else {
        #pragma unroll 4
        for (int i = 0; i < 100; i++) {
            int idx = t + 256 * i;
            int j = idx / E, k = idx - j * E;
            Bs[k * BSTR + j] = Bm[idx];
        }
    }
    __syncthreads();

    const int tx = t & 15, ty = t >> 4;
    unsigned long long acc[8][5];
    const unsigned long long z = pack2(0.f, 0.f);
    #pragma unroll
    for (int i = 0; i < 8; i++)
        #pragma unroll
        for (int u = 0; u < 5; u++) acc[i][u] = z;

    const float* Ath = As + ty * (8 * E);
    #pragma unroll 2
    for (int k = 0; k < E; k++) {
        unsigned long long b2[5];
        const unsigned long long* bp =
            reinterpret_cast<const unsigned long long*>(Bs + k * BSTR + tx * 10);
        #pragma unroll
        for (int u = 0; u < 5; u++) b2[u] = bp[u];
        #pragma unroll
        for (int i = 0; i < 8; i++) {
            float a = Ath[i * E + k];
            unsigned long long a2 = pack2(a, a);
            #pragma unroll
            for (int u = 0; u < 5; u++) acc[i][u] = fma2(a2, b2[u], acc[i][u]);
        }
    }

    float bcol[10];
    #pragma unroll
    for (int u = 0; u < 10; u++) bcol[u] = bias[tx * 10 + u];

    #pragma unroll
    for (int i = 0; i < 8; i++) {
        size_t ro = (rowBase + ty * 8 + i) * E + tx * 10;
        #pragma unroll
        for (int u = 0; u < 5; u++) {
            float2 v = unpack2(acc[i][u]);
            v.x += bcol[2 * u];
            v.y += bcol[2 * u + 1];
            if (MODE == 1) {
                v.x = v.x > 0.f ? v.x : expm1f(v.x);
                v.y = v.y > 0.f ? v.y : expm1f(v.y);
            }
            *reinterpret_cast<float2*>(Out + ro + 2 * u) = v;
        }
    }
}

// ---------------- K2: tensor-core merged projection of X (6 matrices) ----------
__global__ __launch_bounds__(256, 2) void gemm6_mma(
    const float* __restrict__ X,
    const float* __restrict__ i_in_b, const float* __restrict__ o_in_b)
{
    extern __shared__ uint32_t smw[];
    uint32_t* Aw = smw;                 // 128*84 words
    uint32_t* Bw = smw + 128 * 84;      // 160*84 words
    const int t = threadIdx.x;
    const size_t rowBase = (size_t)blockIdx.x * 128;

    {
        const float4* Xg = reinterpret_cast<const float4*>(X + rowBase * E);
        #pragma unroll
        for (int s = 0; s < 10; s++) {
            int idx = t + 256 * s;
            int row = idx / 20, c = idx - row * 20;
            float4 x0 = Xg[idx * 2], x1 = Xg[idx * 2 + 1];
            uint32_t* d = Aw + row * 84 + (c >> 1) * 8 + (c & 1);
            d[0] = H2F(x0.x, x0.y);
            d[2] = H2F(x0.z, x0.w);
            d[4] = H2F(x1.x, x1.y);
            d[6] = H2F(x1.z, x1.w);
        }
    }

    const int lane = t & 31, w = t >> 5;
    const int rb = (w >> 1) * 32;
    const int cb = (w & 1) * 80;
    const int g = lane >> 2, q = lane & 3;

    const uint32_t* A0 = Aw + (rb + g) * 84 + q * 2;
    const uint32_t* B0 = Bw + (cb + g) * 84 + q * 2;

    for (int p = 0; p < 6; p++) {
        __syncthreads();
        {
            const uint4* Bg = reinterpret_cast<const uint4*>(g_wh + (size_t)(6 + p) * E * E);
            #pragma unroll
            for (int s = 0; s < 13; s++) {
                int idx = t + 256 * s;
                if (idx < 3200) {
                    int n = idx / 20, c = idx - n * 20;
                    *reinterpret_cast<uint4*>(Bw + n * 84 + c * 4) = Bg[idx];
                }
            }
        }
        __syncthreads();

        float acc[2][10][4];
        #pragma unroll
        for (int h2 = 0; h2 < 2; h2++)
            #pragma unroll
            for (int j = 0; j < 10; j++)
                #pragma unroll
                for (int u = 0; u < 4; u++) acc[h2][j][u] = 0.f;

        #pragma unroll
        for (int ks = 0; ks < 10; ks++) {
            uint2 aA0 = *reinterpret_cast<const uint2*>(A0 + ks * 8);
            uint2 aB0 = *reinterpret_cast<const uint2*>(A0 + 8 * 84 + ks * 8);
            uint2 aA1 = *reinterpret_cast<const uint2*>(A0 + 16 * 84 + ks * 8);
            uint2 aB1 = *reinterpret_cast<const uint2*>(A0 + 24 * 84 + ks * 8);
            #pragma unroll
            for (int j = 0; j < 10; j++) {
                uint2 bb = *reinterpret_cast<const uint2*>(B0 + (j * 8) * 84 + ks * 8);
                mma16816(acc[0][j], aA0.x, aB0.x, aA0.y, aB0.y, bb.x, bb.y);
                mma16816(acc[1][j], aA1.x, aB1.x, aA1.y, aB1.y, bb.x, bb.y);
            }
        }

        const float* bias = (p < 3) ? (i_in_b + p * E) : (o_in_b + (p - 3) * E);
        __half* Outg = g_px + (size_t)p * BN * E + rowBase * E;
        __syncthreads();
        __half* stage = reinterpret_cast<__half*>(Bw);
        #pragma unroll
        for (int j = 0; j < 10; j++) {
            int col = cb + j * 8 + q * 2;
            float b0f = bias[col], b1f = bias[col + 1];
            #pragma unroll
            for (int h2 = 0; h2 < 2; h2++) {
                int row = rb + h2 * 16 + g;
                *reinterpret_cast<__half2*>(stage + row * 160 + col) =
                    __floats2half2_rn(acc[h2][j][0] + b0f, acc[h2][j][1] + b1f);
                *reinterpret_cast<__half2*>(stage + (row + 8) * 160 + col) =
                    __floats2half2_rn(acc[h2][j][2] + b0f, acc[h2][j][3] + b1f);
            }
        }
        __syncthreads();
        #pragma unroll
        for (int s = 0; s < 10; s++) {
            int idx = t + 256 * s;
            reinterpret_cast<uint4*>(Outg)[idx] =
                reinterpret_cast<const uint4*>(stage)[idx];
        }
    }
}

// ---------------- K3: inner attention via mma + ldmatrix (token-major obuf) ----
__global__ __launch_bounds__(320) void inner_attn_mma(const int* __restrict__ in_idx,
                                                      const int* __restrict__ out_idx)
{
    __shared__ __align__(16) __half tile[96][168];   // rows: hh*48 + mat*16 + l
    __shared__ int idxs[2][16];
    const int n = blockIdx.x, b = blockIdx.y;
    const int t = threadIdx.x;
    const size_t tok = (size_t)b * NN + n;
    const size_t base = (size_t)b * NN;

    if (t < 32) {
        int hh = t >> 4, i = t & 15;
        const int* ia = hh ? out_idx : in_idx;
        idxs[hh][i] = (i == 0) ? n : ia[tok * DINN + i - 1];
    }
    __syncthreads();

    #pragma unroll
    for (int it = 0; it < 6; it++) {
        int task = t + 320 * it;
        int r = task / 20, seg = task - r * 20;
        int hh = r / 48, sub = r - hh * 48;
        int mat = sub >> 4, l = sub & 15;
        const __half* src = g_px +
            ((size_t)(hh * 3 + mat) * BN + base + idxs[hh][l]) * E + seg * 8;
        *reinterpret_cast<uint4*>(&tile[r][seg * 8]) =
            *reinterpret_cast<const uint4*>(src);
    }
    __syncthreads();

    const int w = t >> 5, lane = t & 31;
    const int g = lane >> 2, q = lane & 3;
    const int hh = w / 5, h = w - hh * 5;
    const int qr = hh * 48, kr = qr + 16, vr = qr + 32;
    const int koff = h * 32;
    const int lrow = lane & 15, lcol = (lane >> 4) * 8;

    float s0[4] = {0.f, 0.f, 0.f, 0.f}, s1[4] = {0.f, 0.f, 0.f, 0.f};
    #pragma unroll
    for (int kc = 0; kc < 2; kc++) {
        int ko = koff + kc * 16;
        uint32_t a0, a1, a2, a3, k0, k1, k2, k3;
        ldsm_x4(a0, a1, a2, a3, cvta_smem(&tile[qr + lrow][ko + lcol]));
        ldsm_x4(k0, k1, k2, k3, cvta_smem(&tile[kr + lrow][ko + lcol]));
        mma16816(s0, a0, a1, a2, a3, k0, k2);
        mma16816(s1, a0, a1, a2, a3, k1, k3);
    }
    const float scale = 0.17677669529663687f;  // 1/sqrt(32)
    #pragma unroll
    for (int u = 0; u < 4; u++) { s0[u] *= scale; s1[u] *= scale; }

    float mx0 = fmaxf(fmaxf(s0[0], s0[1]), fmaxf(s1[0], s1[1]));
    float mx1 = fmaxf(fmaxf(s0[2], s0[3]), fmaxf(s1[2], s1[3]));
    mx0 = fmaxf(mx0, __shfl_xor_sync(0xffffffffu, mx0, 1));
    mx0 = fmaxf(mx0, __shfl_xor_sync(0xffffffffu, mx0, 2));
    mx1 = fmaxf(mx1, __shfl_xor_sync(0xffffffffu, mx1, 1));
    mx1 = fmaxf(mx1, __shfl_xor_sync(0xffffffffu, mx1, 2));
    float e00 = __expf(s0[0] - mx0), e01 = __expf(s0[1] - mx0);
    float e02 = __expf(s1[0] - mx0), e03 = __expf(s1[1] - mx0);
    float e10 = __expf(s0[2] - mx1), e11 = __expf(s0[3] - mx1);
    float e12 = __expf(s1[2] - mx1), e13 = __expf(s1[3] - mx1);
    float sum0 = e00 + e01 + e02 + e03;
    float sum1 = e10 + e11 + e12 + e13;
    sum0 += __shfl_xor_sync(0xffffffffu, sum0, 1);
    sum0 += __shfl_xor_sync(0xffffffffu, sum0, 2);
    sum1 += __shfl_xor_sync(0xffffffffu, sum1, 1);
    sum1 += __shfl_xor_sync(0xffffffffu, sum1, 2);
    float inv0 = 1.f / sum0, inv1 = 1.f / sum1;

    uint32_t pa0 = H2F(e00 * inv0, e01 * inv0);
    uint32_t pa1 = H2F(e10 * inv1, e11 * inv1);
    uint32_t pa2 = H2F(e02 * inv0, e03 * inv0);
    uint32_t pa3 = H2F(e12 * inv1, e13 * inv1);

    // token-major obuf: token rows [32*tok, +32), half hh at +16*hh
    __half* ob = g_obuf + ((size_t)tok * 32 + hh * 16) * E + koff;
    #pragma unroll
    for (int nt = 0; nt < 4; nt++) {
        uint32_t b0, b1;
        ldsm_x2t(b0, b1, cvta_smem(&tile[vr + lrow][koff + nt * 8]));
        float o[4] = {0.f, 0.f, 0.f, 0.f};
        mma16816(o, pa0, pa1, pa2, pa3, b0, b1);
        *reinterpret_cast<__half2*>(ob + (size_t)g * E + nt * 8 + 2 * q) =
            __floats2half2_rn(o[0], o[1]);
        *reinterpret_cast<__half2*>(ob + (size_t)(g + 8) * E + nt * 8 + 2 * q) =
            __floats2half2_rn(o[2], o[3]);
    }
}

// ---------------- K45 fused v2: barrier-free GEMM (B global->register) ---------
// CTA = 2 tokens = 64 obuf rows. B fragments stream straight from L2-resident
// panel-major g_wh into registers (double-buffered) -> no B smem, no GEMM
// barriers. Q/K/V' land in smem; attention identical to validated R12 tail.
// smem layout (bytes):
//   [0, 21504)        A (64 rows x 84 words, k-permuted)  -- reused for sc/ps/pb
//   [21504, 43008)    Qs  (64 x 168 halves)
//   [43008, 64512)    Ks
//   [64512, 86016)    Vs
#define FA_SMEM 86016
__global__ __launch_bounds__(256, 2) void fused_attn()
{
    extern __shared__ __align__(16) char smc[];
    uint32_t* Aw   = reinterpret_cast<uint32_t*>(smc);
    __half (*Qs)[168] = reinterpret_cast<__half(*)[168]>(smc + 21504);
    __half (*Ks)[168] = reinterpret_cast<__half(*)[168]>(smc + 43008);
    __half (*Vs)[168] = reinterpret_cast<__half(*)[168]>(smc + 64512);

    const int t = threadIdx.x;
    const size_t rowBase = (size_t)blockIdx.x * 64;

    // ---- load A tile (64 rows fp16, k-permuted store) ----
    {
        const uint4* Ag = reinterpret_cast<const uint4*>(g_obuf + rowBase * E);
        #pragma unroll
        for (int s = 0; s < 5; s++) {
            int idx = t + 256 * s;
            int row = idx / 20, c = idx - row * 20;
            uint4 v = Ag[idx];
            uint32_t* d = Aw + row * 84 + (c >> 1) * 8 + (c & 1);
            d[0] = v.x; d[2] = v.y; d[4] = v.z; d[6] = v.w;
        }
    }

    const int lane = t & 31, w = t >> 5;
    const int g = lane >> 2, q = lane & 3;
    const int half = w >> 2;             // GEMM: which half's weight matrix
    const int cb = (w & 3) * 40;         // GEMM: 40-col group
    const uint32_t* A0 = Aw + (half * 16 + g) * 84 + q * 2;
    // lane's half-element offset within a k-panel (coalesced across warp)
    const int boff = (cb + g) * 16 + q * 4;

    __syncthreads();   // A tile ready

    #pragma unroll 1
    for (int p = 0; p < 3; p++) {
        const __half* Wb = g_wh + (size_t)(2 * p + half) * E * E;

        // prefetch panel ks=0 into register buffer 0
        uint2 bb[2][5];
        #pragma unroll
        for (int j = 0; j < 5; j++)
            bb[0][j] = *reinterpret_cast<const uint2*>(Wb + boff + j * 128);

        float acc[2][5][4];
        #pragma unroll
        for (int h2 = 0; h2 < 2; h2++)
            #pragma unroll
            for (int j = 0; j < 5; j++)
                #pragma unroll
                for (int u = 0; u < 4; u++) acc[h2][j][u] = 0.f;

        #pragma unroll
        for (int ks = 0; ks < 10; ks++) {
            const int cur = ks & 1;
            if (ks < 9) {
                const __half* Wn = Wb + (ks + 1) * 2560 + boff;
                #pragma unroll
                for (int j = 0; j < 5; j++)
                    bb[cur ^ 1][j] = *reinterpret_cast<const uint2*>(Wn + j * 128);
            }
            uint2 aA0 = *reinterpret_cast<const uint2*>(A0 + ks * 8);
            uint2 aB0 = *reinterpret_cast<const uint2*>(A0 + 8 * 84 + ks * 8);
            uint2 aA1 = *reinterpret_cast<const uint2*>(A0 + 32 * 84 + ks * 8);
            uint2 aB1 = *reinterpret_cast<const uint2*>(A0 + 40 * 84 + ks * 8);
            #pragma unroll
            for (int j = 0; j < 5; j++) {
                mma16816(acc[0][j], aA0.x, aB0.x, aA0.y, aB0.y, bb[cur][j].x, bb[cur][j].y);
                mma16816(acc[1][j], aA1.x, aB1.x, aA1.y, aB1.y, bb[cur][j].x, bb[cur][j].y);
            }
        }

        // epilogue: bias + fp16 into Qs/Ks/Vs (disjoint per-warp regions; no sync)
        {
            const float* bias = (p < 2) ? (g_bfin + (2 * p + half) * E)
                                        : (g_bv + half * E);
            __half (*dst)[168] = (p == 0) ? Qs : (p == 1) ? Ks : Vs;
            const int r0 = half * 16 + g;
            #pragma unroll
            for (int j = 0; j < 5; j++) {
                int col = cb + j * 8 + 2 * q;
                float b0f = bias[col], b1f = bias[col + 1];
                *reinterpret_cast<__half2*>(&dst[r0][col]) =
                    __floats2half2_rn(acc[0][j][0] + b0f, acc[0][j][1] + b1f);
                *reinterpret_cast<__half2*>(&dst[r0 + 8][col]) =
                    __floats2half2_rn(acc[0][j][2] + b0f, acc[0][j][3] + b1f);
                *reinterpret_cast<__half2*>(&dst[32 + r0][col]) =
                    __floats2half2_rn(acc[1][j][0] + b0f, acc[1][j][1] + b1f);
                *reinterpret_cast<__half2*>(&dst[32 + r0 + 8][col]) =
                    __floats2half2_rn(acc[1][j][2] + b0f, acc[1][j][3] + b1f);
            }
        }
    }
    __syncthreads();   // Q/K/V complete, A region free

    // ---- attention on the 2 tokens (Q/K/V in smem) ----
    float*  sc = reinterpret_cast<float*>(smc);            // [2][32][34]
    __half* ps = reinterpret_cast<__half*>(smc + 8704);    // [2][32][40]
    float*  pb = reinterpret_cast<float*>(smc + 13824);    // [2][2][160]

    const int lrow = lane & 15, lcol = (lane >> 4) * 8;

    // scores: warp -> (token w>>2, mt=(w>>1)&1, nt2=w&1), m16n16, k=160
    {
        const int tk = w >> 2, mt = (w >> 1) & 1, nt2 = w & 1;
        const __half* Qb = &Qs[32 * tk + 16 * mt + lrow][0];
        const __half* Kb = &Ks[32 * tk + 16 * nt2 + lrow][0];
        float s0[4] = {0.f, 0.f, 0.f, 0.f}, s1[4] = {0.f, 0.f, 0.f, 0.f};
        #pragma unroll
        for (int kc = 0; kc < 10; kc++) {
            uint32_t a0, a1, a2, a3, k0, k1, k2, k3;
            ldsm_x4(a0, a1, a2, a3, cvta_smem(Qb + kc * 16 + lcol));
            ldsm_x4(k0, k1, k2, k3, cvta_smem(Kb + kc * 16 + lcol));
            mma16816(s0, a0, a1, a2, a3, k0, k2);
            mma16816(s1, a0, a1, a2, a3, k1, k3);
        }
        const float scale = 0.07905694150420949f;  // 1/sqrt(160)
        float* scr = sc + tk * (32 * 34);
        int rr = 16 * mt + g, cc = 16 * nt2 + 2 * q;
        *reinterpret_cast<float2*>(&scr[rr * 34 + cc]) =
            make_float2(s0[0] * scale, s0[1] * scale);
        *reinterpret_cast<float2*>(&scr[(rr + 8) * 34 + cc]) =
            make_float2(s0[2] * scale, s0[3] * scale);
        *reinterpret_cast<float2*>(&scr[rr * 34 + cc + 8]) =
            make_float2(s1[0] * scale, s1[1] * scale);
        *reinterpret_cast<float2*>(&scr[(rr + 8) * 34 + cc + 8]) =
            make_float2(s1[2] * scale, s1[3] * scale);
    }
    __syncthreads();

    // softmax: 64 threads, one row each
    if (t < 64) {
        const int tk = t >> 5, r = t & 31;
        float* row = sc + tk * (32 * 34) + r * 34;
        float v[32];
        float mx = -3.4e38f;
        #pragma unroll
        for (int m = 0; m < 32; m++) { v[m] = row[m]; mx = fmaxf(mx, v[m]); }
        float sum = 0.f;
        #pragma unroll
        for (int m = 0; m < 32; m++) { v[m] = __expf(v[m] - mx); sum += v[m]; }
        float inv = 1.f / sum;
        __half* pr = ps + tk * (32 * 40) + r * 40;
        #pragma unroll
        for (int m = 0; m < 16; m++)
            *reinterpret_cast<__half2*>(pr + 2 * m) =
                __floats2half2_rn(v[2 * m] * inv, v[2 * m + 1] * inv);
    }
    __syncthreads();

    // AV + max pool: warp -> (token w>>2, mt, nb), m16n80 (10 n-tiles per warp)
    {
        const int tk = w >> 2, sub = w & 3;
        const int mt = sub >> 1, nb = sub & 1;
        uint32_t a[2][4];
        #pragma unroll
        for (int kc = 0; kc < 2; kc++)
            ldsm_x4(a[kc][0], a[kc][1], a[kc][2], a[kc][3],
                    cvta_smem(ps + tk * (32 * 40) + (16 * mt + lrow) * 40 + kc * 16 + lcol));
        #pragma unroll
        for (int nt = 0; nt < 10; nt++) {
            float o[4] = {0.f, 0.f, 0.f, 0.f};
            #pragma unroll
            for (int kc = 0; kc < 2; kc++) {
                uint32_t b0, b1;
                ldsm_x2t(b0, b1, cvta_smem(&Vs[32 * tk + kc * 16 + lrow][nb * 80 + nt * 8]));
                mma16816(o, a[kc][0], a[kc][1], a[kc][2], a[kc][3], b0, b1);
            }
            float m0 = fmaxf(o[0], o[2]);
            float m1 = fmaxf(o[1], o[3]);
            #pragma unroll
            for (int s = 4; s < 32; s <<= 1) {
                m0 = fmaxf(m0, __shfl_xor_sync(0xffffffffu, m0, s));
                m1 = fmaxf(m1, __shfl_xor_sync(0xffffffffu, m1, s));
            }
            if (g == 0)
                *reinterpret_cast<float2*>(&pb[(tk * 2 + mt) * 160 + nb * 80 + nt * 8 + 2 * q]) =
                    make_float2(m0, m1);
        }
    }
    __syncthreads();

    // final pool across the two 16-row halves -> g_pooled
    for (int j = t; j < 320; j += 256) {
        int tk = j / 160, c = j - tk * 160;
        g_pooled[((size_t)blockIdx.x * 2 + tk) * E + c] =
            fmaxf(pb[tk * 320 + c], pb[tk * 320 + 160 + c]);
    }
}

// ---------------- host orchestration ----------------
extern "C" void kernel_launch(void* const* d_in, const int* in_sizes, int n_in,
                              void* d_out, int out_size)
{
    const float* X       = (const float*)d_in[0];
    const int*   in_idx  = (const int*)  d_in[1];
    const int*   out_idx = (const int*)  d_in[2];
    const float* iWq     = (const float*)d_in[3];
    const float* iWk     = (const float*)d_in[4];
    const float* iWv     = (const float*)d_in[5];
    const float* i_in_w  = (const float*)d_in[6];
    const float* i_in_b  = (const float*)d_in[7];
    const float* i_out_w = (const float*)d_in[8];
    const float* i_out_b = (const float*)d_in[9];
    const float* oWq     = (const float*)d_in[10];
    const float* oWk     = (const float*)d_in[11];
    const float* oWv     = (const float*)d_in[12];
    const float* o_in_w  = (const float*)d_in[13];
    const float* o_in_b  = (const float*)d_in[14];
    const float* o_out_w = (const float*)d_in[15];
    const float* o_out_b = (const float*)d_in[16];
    const float* f_in_w  = (const float*)d_in[17];
    const float* f_in_b  = (const float*)d_in[18];
    const float* f_out_w = (const float*)d_in[19];
    const float* f_out_b = (const float*)d_in[20];
    const float* lin_w   = (const float*)d_in[21];
    const float* lin_b   = (const float*)d_in[22];
    float* out = (float*)d_out;

    float* pooled;
    cudaGetSymbolAddress((void**)&pooled, g_pooled);

    const size_t smem_g   = (size_t)(128 * E + E * BSTR) * sizeof(float);   // 185,600 B
    const size_t smem_mma = (size_t)(128 * 84 + 160 * 84) * 4;              //  96,768 B
    cudaFuncSetAttribute(gemm128<1, 1>, cudaFuncAttributeMaxDynamicSharedMemorySize, (int)smem_g);
    cudaFuncSetAttribute(gemm6_mma,     cudaFuncAttributeMaxDynamicSharedMemorySize, (int)smem_mma);
    cudaFuncSetAttribute(fused_attn,    cudaFuncAttributeMaxDynamicSharedMemorySize, FA_SMEM);

    // K1: fused weights + biases (2 launches)
    setup1<<<dim3(E, 13), E>>>(iWq, iWk, iWv, oWq, oWk, oWv,
                               i_in_w, o_in_w, f_in_w, i_out_w, o_out_w,
                               f_in_b, i_out_b, o_out_b);
    setup2<<<dim3(E, 13), E>>>(f_out_w, f_out_b);

    // K2: merged tensor-core projection of X -> px (fp16), one launch
    gemm6_mma<<<BN / 128, 256, smem_mma>>>(X, i_in_b, o_in_b);

    // K3: inner attentions via tensor cores -> obuf (token-major fp16)
    inner_attn_mma<<<dim3(NN, BB), 320>>>(in_idx, out_idx);

    // K45: fused final projections (barrier-free) + attention + max pool
    fused_attn<<<BN / 2, 256, FA_SMEM>>>();

    // K6: pooled @ lin_w.T + lin_b, ELU -> output
    gemm128<1, 1><<<BN / 128, 256, smem_g>>>(pooled, lin_w, lin_b, out);

    (void)in_sizes; (void)n_in; (void)out_size;
}